// round 9
// baseline (speedup 1.0000x reference)
#include <cuda_runtime.h>
#include <cuda_bf16.h>
#include <cuda_fp16.h>
#include <cstdint>

#define S     2048
#define HID   2048
#define NH    32
#define NKV   8
#define HD    64
#define KVDIM (NKV*HD)   // 512
#define CTX   (S-10)     // 2038: rows >= CTX use narrow rope

typedef unsigned long long ull;
typedef __nv_bfloat16 bf16;

__device__ __forceinline__ uint32_t smem_u32(const void* p) {
    uint32_t a;
    asm("{ .reg .u64 t; cvta.to.shared.u64 t, %1; cvt.u32.u64 %0, t; }" : "=r"(a) : "l"(p));
    return a;
}

// ---------------- mma.sync primitives (compute_103-safe) ----------------
__device__ __forceinline__ void cp16(uint32_t s, const void* g) {
    asm volatile("cp.async.cg.shared.global [%0], [%1], 16;" :: "r"(s), "l"(g));
}
#define CP_COMMIT() asm volatile("cp.async.commit_group;" ::: "memory")
#define CP_WAIT1()  asm volatile("cp.async.wait_group 1;" ::: "memory")

__device__ __forceinline__ void ldsm_x4(uint32_t addr, uint32_t& r0, uint32_t& r1,
                                        uint32_t& r2, uint32_t& r3) {
    asm volatile("ldmatrix.sync.aligned.m8n8.x4.shared.b16 {%0,%1,%2,%3}, [%4];"
                 : "=r"(r0), "=r"(r1), "=r"(r2), "=r"(r3) : "r"(addr));
}
__device__ __forceinline__ void ldsm_x4t(uint32_t addr, uint32_t& r0, uint32_t& r1,
                                         uint32_t& r2, uint32_t& r3) {
    asm volatile("ldmatrix.sync.aligned.m8n8.x4.trans.shared.b16 {%0,%1,%2,%3}, [%4];"
                 : "=r"(r0), "=r"(r1), "=r"(r2), "=r"(r3) : "r"(addr));
}
__device__ __forceinline__ void mma16816(float* c, const uint32_t* a, const uint32_t* b) {
    asm volatile(
        "mma.sync.aligned.m16n8k16.row.col.f32.bf16.bf16.f32 "
        "{%0,%1,%2,%3}, {%4,%5,%6,%7}, {%8,%9}, {%0,%1,%2,%3};"
        : "+f"(c[0]), "+f"(c[1]), "+f"(c[2]), "+f"(c[3])
        : "r"(a[0]), "r"(a[1]), "r"(a[2]), "r"(a[3]), "r"(b[0]), "r"(b[1]));
}
__device__ __forceinline__ void mma16816h(float* c, const uint32_t* a, const uint32_t* b) {
    asm volatile(
        "mma.sync.aligned.m16n8k16.row.col.f32.f16.f16.f32 "
        "{%0,%1,%2,%3}, {%4,%5,%6,%7}, {%8,%9}, {%0,%1,%2,%3};"
        : "+f"(c[0]), "+f"(c[1]), "+f"(c[2]), "+f"(c[3])
        : "r"(a[0]), "r"(a[1]), "r"(a[2]), "r"(a[3]), "r"(b[0]), "r"(b[1]));
}
__device__ __forceinline__ uint32_t pack_bf16x2(float lo, float hi) {
    uint32_t r; asm("cvt.rn.bf16x2.f32 %0, %1, %2;" : "=r"(r) : "f"(hi), "f"(lo));
    return r;
}
__device__ __forceinline__ uint32_t pack_f16x2(float lo, float hi) {
    uint32_t r; asm("cvt.rn.f16x2.f32 %0, %1, %2;" : "=r"(r) : "f"(hi), "f"(lo));
    return r;
}

// ---------------- scratch (static device globals; no allocs) ----------------
__device__ float g_Q   [S*HID];
__device__ float g_K   [S*KVDIM];
__device__ float g_V   [S*KVDIM];
__device__ float g_attn[S*HID];
__device__ bf16 g_hH[S*HID],     g_hL[S*HID];
__device__ bf16 g_WqH[HID*HID],  g_WqL[HID*HID];
__device__ bf16 g_WkH[KVDIM*HID],g_WkL[KVDIM*HID];
__device__ bf16 g_WvH[KVDIM*HID],g_WvL[KVDIM*HID];
__device__ bf16 g_WoH[HID*HID],  g_WoL[HID*HID];
__device__ bf16 g_aH[S*HID],     g_aL[S*HID];
__device__ bf16 g_Qh[S*HID],    g_Ql[S*HID];
__device__ bf16 g_bKh[S*KVDIM], g_bKl[S*KVDIM];
__device__ bf16 g_nKh[S*KVDIM], g_nKl[S*KVDIM];
__device__ __half g_Vh[S*KVDIM], g_Vl[S*KVDIM];   // fp16 split of V

// ---------------- fp32 -> bf16 hi/lo split ----------------
__device__ __forceinline__ void split_body(const float* __restrict__ x,
                                           bf16* __restrict__ hi, bf16* __restrict__ lo,
                                           int i)
{
    float4 v = ((const float4*)x)[i];
    bf16 h0 = __float2bfloat16(v.x);
    bf16 h1 = __float2bfloat16(v.y);
    bf16 h2 = __float2bfloat16(v.z);
    bf16 h3 = __float2bfloat16(v.w);
    __nv_bfloat162 H0 = __nv_bfloat162(h0, h1), H1 = __nv_bfloat162(h2, h3);
    __nv_bfloat162 L0 = __nv_bfloat162(__float2bfloat16(v.x - __bfloat162float(h0)),
                                       __float2bfloat16(v.y - __bfloat162float(h1)));
    __nv_bfloat162 L1 = __nv_bfloat162(__float2bfloat16(v.z - __bfloat162float(h2)),
                                       __float2bfloat16(v.w - __bfloat162float(h3)));
    ((__nv_bfloat162*)hi)[i*2+0] = H0; ((__nv_bfloat162*)hi)[i*2+1] = H1;
    ((__nv_bfloat162*)lo)[i*2+0] = L0; ((__nv_bfloat162*)lo)[i*2+1] = L1;
}

// 4 float4 per thread (MLP=4)
__global__ __launch_bounds__(256)
void split4_kernel(const float* __restrict__ x, bf16* __restrict__ hi,
                   bf16* __restrict__ lo, int n4)
{
    int base = (blockIdx.x * 256 + threadIdx.x) * 4;
#pragma unroll
    for (int k = 0; k < 4; k++) {
        int i = base + k;
        if (i < n4) split_body(x, hi, lo, i);
    }
}

// merged split of all 5 inputs, 4 float4/thread.
// regions (float4 units): hidden 1048576 | Wq 1048576 | Wk 262144 | Wv 262144 | Wo 1048576
__global__ __launch_bounds__(256)
void split_all_kernel(const float* __restrict__ hid, const float* __restrict__ Wq,
                      const float* __restrict__ Wk,  const float* __restrict__ Wv,
                      const float* __restrict__ Wo,
                      bf16* __restrict__ hH, bf16* __restrict__ hL,
                      bf16* __restrict__ qH, bf16* __restrict__ qL,
                      bf16* __restrict__ kH, bf16* __restrict__ kL,
                      bf16* __restrict__ vH, bf16* __restrict__ vL,
                      bf16* __restrict__ oH, bf16* __restrict__ oL)
{
    int g0 = (blockIdx.x * 256 + threadIdx.x) * 4;   // region boundaries all %4==0
    const int R0 = 1048576, R1 = R0 + 1048576, R2 = R1 + 262144, R3 = R2 + 262144;
    const int TOT = R3 + 1048576;
    if (g0 >= TOT) return;
    const float* src; bf16 *dh, *dl; int rb;
    if (g0 < R0)      { src = hid; dh = hH; dl = hL; rb = 0;  }
    else if (g0 < R1) { src = Wq;  dh = qH; dl = qL; rb = R0; }
    else if (g0 < R2) { src = Wk;  dh = kH; dl = kL; rb = R1; }
    else if (g0 < R3) { src = Wv;  dh = vH; dl = vL; rb = R2; }
    else              { src = Wo;  dh = oH; dl = oL; rb = R3; }
#pragma unroll
    for (int k = 0; k < 4; k++) split_body(src, dh, dl, g0 - rb + k);
}

// ---------------- mma.sync split-bf16 GEMM core (unchanged) ------------
#define STG      16384
#define SM_STAGE (4*STG)          // 64 KB
#define SM_TOTAL (2*SM_STAGE)     // 128 KB

__device__ __forceinline__ void g_load_stage(
    uint32_t sbuf,
    const bf16* __restrict__ Ah, const bf16* __restrict__ Al,
    const bf16* __restrict__ Bh, const bf16* __restrict__ Bl,
    int mBase, int nBase, int Kdim, int k0, int tid)
{
#pragma unroll
    for (int i = 0; i < 4; i++) {
        int u = i * 256 + tid;
        int r = u >> 3, c = u & 7;
        uint32_t so = (uint32_t)(r * 128 + ((c ^ (r & 7)) << 4));
        size_t eoffA = (size_t)(mBase + r) * Kdim + k0 + c * 8;
        size_t eoffB = (size_t)(nBase + r) * Kdim + k0 + c * 8;
        cp16(sbuf +          so, Ah + eoffA);
        cp16(sbuf +   STG  + so, Al + eoffA);
        cp16(sbuf + 2*STG  + so, Bh + eoffB);
        cp16(sbuf + 3*STG  + so, Bl + eoffB);
    }
}

__device__ __forceinline__ void gemm_body(
    const bf16* __restrict__ Ah, const bf16* __restrict__ Al,
    const bf16* __restrict__ Bh, const bf16* __restrict__ Bl,
    float* __restrict__ C, int Ntot, int Kdim, int mBase, int nBase, uint32_t sb)
{
    const int tid  = threadIdx.x;
    const int lane = tid & 31;
    const int wid  = tid >> 5;
    const int wm   = wid & 1;
    const int wn   = wid >> 1;

    float acc[4][4][4];
#pragma unroll
    for (int i = 0; i < 4; i++)
#pragma unroll
        for (int j = 0; j < 4; j++)
#pragma unroll
            for (int k = 0; k < 4; k++) acc[i][j][k] = 0.0f;

    const int NC = Kdim >> 6;

    g_load_stage(sb,            Ah, Al, Bh, Bl, mBase, nBase, Kdim, 0,  tid);
    CP_COMMIT();
    g_load_stage(sb + SM_STAGE, Ah, Al, Bh, Bl, mBase, nBase, Kdim, 64, tid);
    CP_COMMIT();

    const int aRow = wm * 64;
    const int bRow = wn * 32;

    for (int c = 0; c < NC; c++) {
        CP_WAIT1();
        __syncthreads();
        const uint32_t sbuf = sb + (c & 1) * SM_STAGE;
        const uint32_t sAh = sbuf, sAl = sbuf + STG, sBh = sbuf + 2*STG, sBl = sbuf + 3*STG;

#pragma unroll
        for (int ks = 0; ks < 4; ks++) {
            uint32_t aH[4][4], aL[4][4], bH[4][2], bL[4][2];
            {
                int rA = aRow + (lane & 15);
                int ccA = ks * 2 + (lane >> 4);
#pragma unroll
                for (int mf = 0; mf < 4; mf++) {
                    int r = rA + mf * 16;
                    uint32_t so = (uint32_t)(r * 128 + ((ccA ^ (r & 7)) << 4));
                    ldsm_x4(sAh + so, aH[mf][0], aH[mf][1], aH[mf][2], aH[mf][3]);
                    ldsm_x4(sAl + so, aL[mf][0], aL[mf][1], aL[mf][2], aL[mf][3]);
                }
            }
            {
                int rB0 = bRow + (lane & 7) + ((lane >> 4) << 3);
                int ccB = ks * 2 + ((lane >> 3) & 1);
#pragma unroll
                for (int nf2 = 0; nf2 < 2; nf2++) {
                    int r = rB0 + nf2 * 16;
                    uint32_t so = (uint32_t)(r * 128 + ((ccB ^ (r & 7)) << 4));
                    ldsm_x4(sBh + so, bH[nf2*2][0], bH[nf2*2][1], bH[nf2*2+1][0], bH[nf2*2+1][1]);
                    ldsm_x4(sBl + so, bL[nf2*2][0], bL[nf2*2][1], bL[nf2*2+1][0], bL[nf2*2+1][1]);
                }
            }
#pragma unroll
            for (int mf = 0; mf < 4; mf++)
#pragma unroll
                for (int nf = 0; nf < 4; nf++) {
                    mma16816(acc[mf][nf], aH[mf], bH[nf]);
                    mma16816(acc[mf][nf], aL[mf], bH[nf]);
                    mma16816(acc[mf][nf], aH[mf], bL[nf]);
                }
        }
        __syncthreads();
        if (c + 2 < NC)
            g_load_stage(sb + (c & 1) * SM_STAGE, Ah, Al, Bh, Bl,
                         mBase, nBase, Kdim, (c + 2) * 64, tid);
        CP_COMMIT();
    }

#pragma unroll
    for (int mf = 0; mf < 4; mf++) {
        int row0 = mBase + wm * 64 + mf * 16 + (lane >> 2);
#pragma unroll
        for (int nf = 0; nf < 4; nf++) {
            int col = nBase + wn * 32 + nf * 8 + (lane & 3) * 2;
            *(float2*)&C[(size_t)row0 * Ntot + col]       = make_float2(acc[mf][nf][0], acc[mf][nf][1]);
            *(float2*)&C[(size_t)(row0 + 8) * Ntot + col] = make_float2(acc[mf][nf][2], acc[mf][nf][3]);
        }
    }
}

__global__ __launch_bounds__(256)
void qkv_gemm(const bf16* __restrict__ Ah, const bf16* __restrict__ Al,
              const bf16* __restrict__ WqH, const bf16* __restrict__ WqL,
              const bf16* __restrict__ WkH, const bf16* __restrict__ WkL,
              const bf16* __restrict__ WvH, const bf16* __restrict__ WvL,
              float* __restrict__ Cq, float* __restrict__ Ck, float* __restrict__ Cv)
{
    extern __shared__ char dyns[];
    uint32_t sb = smem_u32(dyns);
    int bx = blockIdx.x, mBase = blockIdx.y * 128;
    if (bx < 16)      gemm_body(Ah, Al, WqH, WqL, Cq, HID,   HID, mBase, bx*128,      sb);
    else if (bx < 20) gemm_body(Ah, Al, WkH, WkL, Ck, KVDIM, HID, mBase, (bx-16)*128, sb);
    else              gemm_body(Ah, Al, WvH, WvL, Cv, KVDIM, HID, mBase, (bx-20)*128, sb);
}

__global__ __launch_bounds__(256)
void wo_gemm(const bf16* __restrict__ Ah, const bf16* __restrict__ Al,
             const bf16* __restrict__ Bh, const bf16* __restrict__ Bl,
             float* __restrict__ C)
{
    extern __shared__ char dyns[];
    uint32_t sb = smem_u32(dyns);
    gemm_body(Ah, Al, Bh, Bl, C, HID, HID, blockIdx.y*128, blockIdx.x*128, sb);
}

// ---------------- RoPE + split ------------------------------------------
__device__ __forceinline__ void split_w(bf16* hp, bf16* lp, float x) {
    bf16 h = __float2bfloat16(x);
    *hp = h;
    *lp = __float2bfloat16(x - __bfloat162float(h));
}
__device__ __forceinline__ void split_h(__half* hp, __half* lp, float x) {
    __half h = __float2half_rn(x);
    *hp = h;
    *lp = __float2half_rn(x - __half2float(h));
}

__global__ void rope_split_kernel(const float* __restrict__ Q, const float* __restrict__ K,
                                  const float* __restrict__ V,
                                  bf16* __restrict__ qh, bf16* __restrict__ ql,
                                  bf16* __restrict__ kbh, bf16* __restrict__ kbl,
                                  bf16* __restrict__ knh, bf16* __restrict__ knl,
                                  __half* __restrict__ vh, __half* __restrict__ vl)
{
    const int s = blockIdx.x;
    const int tid = threadIdx.x; // 256
    const bool narrowRow = (s >= CTX);
    const float QS = 1.4426950408889634f * 0.125f;   // log2(e)/sqrt(64)

    __shared__ float cb[32], sb[32], cn[32], sn[32];
    if (tid < 32) {
        double inv = pow(10000.0, -(double)tid / 32.0);
        double ab = (double)s * inv;
        double an = ((double)s * 0.25) * inv;
        cb[tid] = (float)cos(ab); sb[tid] = (float)sin(ab);
        cn[tid] = (float)cos(an); sn[tid] = (float)sin(an);
    }
    __syncthreads();

    for (int p = tid; p < NH * 32; p += 256) {
        int h = p >> 5, d = p & 31;
        size_t base = (size_t)s * HID + h * HD;
        float x1 = Q[base + d];
        float x2 = Q[base + d + 32];
        float c  = narrowRow ? cn[d] : cb[d];
        float si = narrowRow ? sn[d] : sb[d];
        split_w(qh + base + d,      ql + base + d,      (x1 * c - x2 * si) * QS);
        split_w(qh + base + d + 32, ql + base + d + 32, (x2 * c + x1 * si) * QS);
    }
    for (int p = tid; p < NKV * 32; p += 256) {
        int h = p >> 5, d = p & 31;
        size_t base = (size_t)s * KVDIM + h * HD;
        float x1 = K[base + d];
        float x2 = K[base + d + 32];
        split_w(kbh + base + d,      kbl + base + d,      x1 * cb[d] - x2 * sb[d]);
        split_w(kbh + base + d + 32, kbl + base + d + 32, x2 * cb[d] + x1 * sb[d]);
        split_w(knh + base + d,      knl + base + d,      x1 * cn[d] - x2 * sn[d]);
        split_w(knh + base + d + 32, knl + base + d + 32, x2 * cn[d] + x1 * sn[d]);
    }
    for (int e = tid; e < KVDIM; e += 256) {
        size_t base = (size_t)s * KVDIM + e;
        split_h(vh + base, vl + base, V[base]);
    }
}

// ---------------- Tensor-core flash attention + merged fixup ----------------
// blockIdx.x < 32: flash tile (qt = 31-bx, heavy first), Boost K; epilogue
//   stores predicated on row < CTX.
// blockIdx.x >= 32: fixup CTA for row CTX + (bx-32), head = blockIdx.y
//   (exact fp32 softmax with narrow K, coalesced loads).

__device__ __forceinline__ void fa_load_stage(
    uint32_t sb, int kt, int kvh, int tid,
    const bf16* __restrict__ Kbh, const bf16* __restrict__ Kbl,
    const __half* __restrict__ Vh, const __half* __restrict__ Vl)
{
#pragma unroll
    for (int i = 0; i < 4; i++) {
        int u = i * 128 + tid;      // 0..511
        int r = u >> 3, c = u & 7;
        uint32_t so = (uint32_t)(r * 128 + ((c ^ (r & 7)) << 4));
        size_t go = (size_t)(kt * 64 + r) * KVDIM + kvh * 64 + c * 8;
        cp16(sb +         so, Kbh + go);
        cp16(sb + 8192  + so, Kbl + go);
        cp16(sb + 16384 + so, Vh + go);
        cp16(sb + 24576 + so, Vl + go);
    }
}

__device__ __forceinline__ void fa_compute_S(
    float s[8][4], uint32_t sKh, uint32_t sKl,
    const uint32_t qfh[4][4], const uint32_t qfl[4][4], int lane)
{
#pragma unroll
    for (int kk = 0; kk < 4; kk++) {
        uint32_t kh[8][2], kl[8][2];
        int rB0 = (lane & 7) + ((lane >> 4) << 3);
        int ccB = kk * 2 + ((lane >> 3) & 1);
#pragma unroll
        for (int nb = 0; nb < 4; nb++) {
            int r = nb * 16 + rB0;
            uint32_t so = (uint32_t)(r * 128 + ((ccB ^ (r & 7)) << 4));
            ldsm_x4(sKh + so, kh[nb*2][0], kh[nb*2][1], kh[nb*2+1][0], kh[nb*2+1][1]);
            ldsm_x4(sKl + so, kl[nb*2][0], kl[nb*2][1], kl[nb*2+1][0], kl[nb*2+1][1]);
        }
#pragma unroll
        for (int nf = 0; nf < 8; nf++) {
            mma16816(s[nf], qfh[kk], kh[nf]);
            mma16816(s[nf], qfl[kk], kh[nf]);
            mma16816(s[nf], qfh[kk], kl[nf]);
        }
    }
}

#define FA_STAGE 32768
#define FA_SMEM  (16384 + 2*FA_STAGE)   // 81920
#define NQT      (S/64)                  // 32

__global__ __launch_bounds__(128, 2)
void flash_mma(const bf16* __restrict__ Qh, const bf16* __restrict__ Ql,
               const bf16* __restrict__ Kbh, const bf16* __restrict__ Kbl,
               const bf16* __restrict__ nKh, const bf16* __restrict__ nKl,
               const __half* __restrict__ Vh,  const __half* __restrict__ Vl,
               float* __restrict__ attnOut)
{
    extern __shared__ char dyn[];
    const int tid = threadIdx.x, lane = tid & 31, w = tid >> 5;
    const int h = blockIdx.y, kvh = h >> 2;

    if (blockIdx.x >= NQT) {
        // ================= fixup path: one CTA per (row, head) ==============
        float* sc  = (float*)dyn;            // 2048 scores (8 KB)
        float* qsm = (float*)(dyn + 8192);   // 64
        float* red = qsm + 64;               // 4
        float* oacc = red + 8;               // 2 x 64

        const int row = CTX + ((int)blockIdx.x - NQT);
        const int nkeys = row + 1;

        if (tid < 64) {
            size_t off = (size_t)row * HID + h * 64 + tid;
            qsm[tid] = __bfloat162float(Qh[off]) + __bfloat162float(Ql[off]);
        }
        __syncthreads();

        // phase 1: scores (warp per key, lanes over dims)
        const float q0 = qsm[lane * 2], q1 = qsm[lane * 2 + 1];
        for (int j = w; j < nkeys; j += 4) {
            size_t off = (size_t)j * KVDIM + kvh * 64;
            __nv_bfloat162 a = ((const __nv_bfloat162*)(nKh + off))[lane];
            __nv_bfloat162 b = ((const __nv_bfloat162*)(nKl + off))[lane];
            float kx = __bfloat162float(a.x) + __bfloat162float(b.x);
            float ky = __bfloat162float(a.y) + __bfloat162float(b.y);
            float s = q0 * kx + q1 * ky;
#pragma unroll
            for (int d = 16; d; d >>= 1) s += __shfl_xor_sync(0xffffffffu, s, d);
            if (lane == 0) sc[j] = s;
        }
        __syncthreads();

        // max reduce
        float mym = -1e30f;
        for (int j = tid; j < nkeys; j += 128) mym = fmaxf(mym, sc[j]);
#pragma unroll
        for (int d = 16; d; d >>= 1) mym = fmaxf(mym, __shfl_xor_sync(0xffffffffu, mym, d));
        if (lane == 0) red[w] = mym;
        __syncthreads();
        float M = fmaxf(fmaxf(red[0], red[1]), fmaxf(red[2], red[3]));
        __syncthreads();

        // p = exp2(s - M), sum
        float ls = 0.0f;
        for (int j = tid; j < nkeys; j += 128) {
            float p = exp2f(sc[j] - M);
            sc[j] = p;
            ls += p;
        }
#pragma unroll
        for (int d = 16; d; d >>= 1) ls += __shfl_xor_sync(0xffffffffu, ls, d);
        if (lane == 0) red[w] = ls;
        __syncthreads();
        float L = red[0] + red[1] + red[2] + red[3];

        // phase 2: O = sum p_j V_j (thread = dim x key-chunk, coalesced)
        const int d = tid & 63, ch = tid >> 6;   // 2 chunks
        float acc = 0.0f;
        for (int j = ch; j < nkeys; j += 2) {
            size_t off = (size_t)j * KVDIM + kvh * 64 + d;
            acc += sc[j] * (__half2float(Vh[off]) + __half2float(Vl[off]));
        }
        oacc[ch * 64 + d] = acc;
        __syncthreads();

        if (tid < 64) {
            float o = (oacc[tid] + oacc[64 + tid]) / L;
            attnOut[(size_t)row * HID + h * 64 + tid] = o;
        }
        return;
    }

    // ===================== flash path =====================
    const uint32_t sQ = smem_u32(dyn);           // Qh 8K | Ql 8K | stage0 | stage1
    const int qt = (NQT - 1) - (int)blockIdx.x;   // heavy first

    {
        const bf16* gQh = Qh + (size_t)(qt * 64) * HID + h * 64;
        const bf16* gQl = Ql + (size_t)(qt * 64) * HID + h * 64;
#pragma unroll
        for (int i = 0; i < 4; i++) {
            int u = i * 128 + tid;
            int r = u >> 3, c = u & 7;
            uint32_t so = (uint32_t)(r * 128 + ((c ^ (r & 7)) << 4));
            cp16(sQ +        so, gQh + (size_t)r * HID + c * 8);
            cp16(sQ + 8192 + so, gQl + (size_t)r * HID + c * 8);
        }
    }
    fa_load_stage(sQ + 16384, 0, kvh, tid, Kbh, Kbl, Vh, Vl);
    CP_COMMIT();
    if (qt >= 1)
        fa_load_stage(sQ + 16384 + FA_STAGE, 1, kvh, tid, Kbh, Kbl, Vh, Vl);
    CP_COMMIT();

    CP_WAIT1();
    __syncthreads();

    uint32_t qfh[4][4], qfl[4][4];
    {
        int rA = w * 16 + (lane & 15);
#pragma unroll
        for (int kk = 0; kk < 4; kk++) {
            int cc = kk * 2 + (lane >> 4);
            uint32_t so = (uint32_t)(rA * 128 + ((cc ^ (rA & 7)) << 4));
            ldsm_x4(sQ + so,        qfh[kk][0], qfh[kk][1], qfh[kk][2], qfh[kk][3]);
            ldsm_x4(sQ + 8192 + so, qfl[kk][0], qfl[kk][1], qfl[kk][2], qfl[kk][3]);
        }
    }

    float o[8][4];
#pragma unroll
    for (int nf = 0; nf < 8; nf++)
#pragma unroll
        for (int j = 0; j < 4; j++) o[nf][j] = 0.0f;
    float m0 = -1e30f, m1 = -1e30f, l0 = 0.0f, l1 = 0.0f;

    const int rg0 = qt * 64 + w * 16 + (lane >> 2);
    const int rg1 = rg0 + 8;

    for (int kt = 0; kt <= qt; kt++) {
        if (kt) { CP_WAIT1(); __syncthreads(); }
        const uint32_t sb = sQ + 16384 + (kt & 1) * FA_STAGE;

        float s[8][4];
#pragma unroll
        for (int nf = 0; nf < 8; nf++)
#pragma unroll
            for (int j = 0; j < 4; j++) s[nf][j] = 0.0f;
        fa_compute_S(s, sb, sb + 8192, qfh, qfl, lane);

        if (kt == qt) {
#pragma unroll
            for (int nf = 0; nf < 8; nf++) {
                int c0 = kt * 64 + nf * 8 + (lane & 3) * 2;
                if (c0     > rg0) s[nf][0] = -1e30f;
                if (c0 + 1 > rg0) s[nf][1] = -1e30f;
                if (c0     > rg1) s[nf][2] = -1e30f;
                if (c0 + 1 > rg1) s[nf][3] = -1e30f;
            }
        }

        float mr0 = -1e30f, mr1 = -1e30f;
#pragma unroll
        for (int nf = 0; nf < 8; nf++) {
            mr0 = fmaxf(mr0, fmaxf(s[nf][0], s[nf][1]));
            mr1 = fmaxf(mr1, fmaxf(s[nf][2], s[nf][3]));
        }
        mr0 = fmaxf(mr0, __shfl_xor_sync(0xffffffffu, mr0, 1));
        mr0 = fmaxf(mr0, __shfl_xor_sync(0xffffffffu, mr0, 2));
        mr1 = fmaxf(mr1, __shfl_xor_sync(0xffffffffu, mr1, 1));
        mr1 = fmaxf(mr1, __shfl_xor_sync(0xffffffffu, mr1, 2));

        float mn0 = fmaxf(m0, mr0), mn1 = fmaxf(m1, mr1);
        float sc0 = exp2f(m0 - mn0), sc1 = exp2f(m1 - mn1);
        m0 = mn0; m1 = mn1;
        l0 *= sc0; l1 *= sc1;
#pragma unroll
        for (int nf = 0; nf < 8; nf++) {
            o[nf][0] *= sc0; o[nf][1] *= sc0;
            o[nf][2] *= sc1; o[nf][3] *= sc1;
        }

        // P in fp16 (2-pass PV)
        uint32_t pF[4][4];
        float sum0 = 0.0f, sum1 = 0.0f;
#pragma unroll
        for (int nf = 0; nf < 8; nf++) {
            float p0 = exp2f(s[nf][0] - m0), p1 = exp2f(s[nf][1] - m0);
            float p2 = exp2f(s[nf][2] - m1), p3 = exp2f(s[nf][3] - m1);
            sum0 += p0 + p1; sum1 += p2 + p3;
            int kk = nf >> 1;
            int off = (nf & 1) * 2;
            pF[kk][off + 0] = pack_f16x2(p0, p1);
            pF[kk][off + 1] = pack_f16x2(p2, p3);
        }
        sum0 += __shfl_xor_sync(0xffffffffu, sum0, 1);
        sum0 += __shfl_xor_sync(0xffffffffu, sum0, 2);
        sum1 += __shfl_xor_sync(0xffffffffu, sum1, 1);
        sum1 += __shfl_xor_sync(0xffffffffu, sum1, 2);
        l0 += sum0; l1 += sum1;

        // O += P V  (fp16, 2 passes: P·Vh + P·Vl)
        const uint32_t sVh = sb + 16384, sVl = sb + 24576;
#pragma unroll
        for (int kk = 0; kk < 4; kk++) {
            uint32_t vh[8][2], vl[8][2];
            int key0 = kk * 16 + (lane & 7) + ((lane >> 3) & 1) * 8;
#pragma unroll
            for (int nb = 0; nb < 4; nb++) {
                int chunk = nb * 2 + (lane >> 4);
                uint32_t so = (uint32_t)(key0 * 128 + ((chunk ^ (key0 & 7)) << 4));
                ldsm_x4t(sVh + so, vh[nb*2][0], vh[nb*2][1], vh[nb*2+1][0], vh[nb*2+1][1]);
                ldsm_x4t(sVl + so, vl[nb*2][0], vl[nb*2][1], vl[nb*2+1][0], vl[nb*2+1][1]);
            }
#pragma unroll
            for (int nf = 0; nf < 8; nf++) {
                mma16816h(o[nf], pF[kk], vh[nf]);
                mma16816h(o[nf], pF[kk], vl[nf]);
            }
        }

        __syncthreads();
        if (kt + 2 <= qt)
            fa_load_stage(sQ + 16384 + (kt & 1) * FA_STAGE, kt + 2, kvh, tid,
                          Kbh, Kbl, Vh, Vl);
        CP_COMMIT();
    }

    // epilogue: fp32 write, predicated (rows >= CTX owned by fixup CTAs)
    float inv0 = 1.0f / l0, inv1 = 1.0f / l1;
#pragma unroll
    for (int nf = 0; nf < 8; nf++) {
        int col = h * 64 + nf * 8 + (lane & 3) * 2;
        if (rg0 < CTX)
            *(float2*)&attnOut[(size_t)rg0 * HID + col] = make_float2(o[nf][0]*inv0, o[nf][1]*inv0);
        if (rg1 < CTX)
            *(float2*)&attnOut[(size_t)rg1 * HID + col] = make_float2(o[nf][2]*inv1, o[nf][3]*inv1);
    }
}

// ---------------- launch ----------------
extern "C" void kernel_launch(void* const* d_in, const int* in_sizes, int n_in,
                              void* d_out, int out_size)
{
    const float* hidden = (const float*)d_in[0];
    const float* Wq = (const float*)d_in[3];
    const float* Wk = (const float*)d_in[4];
    const float* Wv = (const float*)d_in[5];
    const float* Wo = (const float*)d_in[6];
    float* out = (float*)d_out;

    float *qB, *kB, *vB, *atB;
    cudaGetSymbolAddress((void**)&qB,  g_Q);
    cudaGetSymbolAddress((void**)&kB,  g_K);
    cudaGetSymbolAddress((void**)&vB,  g_V);
    cudaGetSymbolAddress((void**)&atB, g_attn);

    bf16 *hH,*hL,*WqH,*WqL,*WkH,*WkL,*WvH,*WvL,*WoH,*WoL,*aH,*aL;
    cudaGetSymbolAddress((void**)&hH,  g_hH);  cudaGetSymbolAddress((void**)&hL,  g_hL);
    cudaGetSymbolAddress((void**)&WqH, g_WqH); cudaGetSymbolAddress((void**)&WqL, g_WqL);
    cudaGetSymbolAddress((void**)&WkH, g_WkH); cudaGetSymbolAddress((void**)&WkL, g_WkL);
    cudaGetSymbolAddress((void**)&WvH, g_WvH); cudaGetSymbolAddress((void**)&WvL, g_WvL);
    cudaGetSymbolAddress((void**)&WoH, g_WoH); cudaGetSymbolAddress((void**)&WoL, g_WoL);
    cudaGetSymbolAddress((void**)&aH,  g_aH);  cudaGetSymbolAddress((void**)&aL,  g_aL);

    bf16 *Qh,*Ql,*bKh,*bKl,*nKh,*nKl;
    __half *Vh,*Vl;
    cudaGetSymbolAddress((void**)&Qh,  g_Qh);  cudaGetSymbolAddress((void**)&Ql,  g_Ql);
    cudaGetSymbolAddress((void**)&bKh, g_bKh); cudaGetSymbolAddress((void**)&bKl, g_bKl);
    cudaGetSymbolAddress((void**)&nKh, g_nKh); cudaGetSymbolAddress((void**)&nKl, g_nKl);
    cudaGetSymbolAddress((void**)&Vh,  g_Vh);  cudaGetSymbolAddress((void**)&Vl,  g_Vl);

    cudaFuncSetAttribute(qkv_gemm, cudaFuncAttributeMaxDynamicSharedMemorySize, SM_TOTAL);
    cudaFuncSetAttribute(wo_gemm,  cudaFuncAttributeMaxDynamicSharedMemorySize, SM_TOTAL);
    cudaFuncSetAttribute(flash_mma, cudaFuncAttributeMaxDynamicSharedMemorySize, FA_SMEM);

    const int TOT4 = 1048576*3 + 262144*2;   // 3.67M float4
    split_all_kernel<<<(TOT4/4 + 255)/256, 256>>>(hidden, Wq, Wk, Wv, Wo,
                                                  hH, hL, WqH, WqL, WkH, WkL,
                                                  WvH, WvL, WoH, WoL);

    qkv_gemm<<<dim3(24, 16), 256, SM_TOTAL>>>(hH, hL, WqH, WqL, WkH, WkL, WvH, WvL,
                                              qB, kB, vB);

    rope_split_kernel<<<S, 256>>>(qB, kB, vB, Qh, Ql, bKh, bKl, nKh, nKl, Vh, Vl);

    // 32 flash q-tiles (heavy first) + 10 fixup CTAs per head, one launch
    flash_mma<<<dim3(NQT + 10, NH), 128, FA_SMEM>>>(Qh, Ql, bKh, bKl, nKh, nKl,
                                                    Vh, Vl, atB);

    split4_kernel<<<(S*HID/4/4 + 255)/256, 256>>>(atB, aH, aL, S*HID/4);
    wo_gemm<<<dim3(16, 16), 256, SM_TOTAL>>>(aH, aL, WoH, WoL, out);
}

// round 10
// speedup vs baseline: 1.2057x; 1.2057x over previous
#include <cuda_runtime.h>
#include <cuda_bf16.h>
#include <cuda_fp16.h>
#include <cstdint>

#define S     2048
#define HID   2048
#define NH    32
#define NKV   8
#define HD    64
#define KVDIM (NKV*HD)   // 512
#define CTX   (S-10)     // 2038: rows >= CTX use narrow rope

typedef unsigned long long ull;
typedef __nv_bfloat16 bf16;

__device__ __forceinline__ uint32_t smem_u32(const void* p) {
    uint32_t a;
    asm("{ .reg .u64 t; cvta.to.shared.u64 t, %1; cvt.u32.u64 %0, t; }" : "=r"(a) : "l"(p));
    return a;
}

// ---------------- mma.sync primitives (compute_103-safe) ----------------
__device__ __forceinline__ void cp16(uint32_t s, const void* g) {
    asm volatile("cp.async.cg.shared.global [%0], [%1], 16;" :: "r"(s), "l"(g));
}
#define CP_COMMIT() asm volatile("cp.async.commit_group;" ::: "memory")
#define CP_WAIT1()  asm volatile("cp.async.wait_group 1;" ::: "memory")

__device__ __forceinline__ void ldsm_x4(uint32_t addr, uint32_t& r0, uint32_t& r1,
                                        uint32_t& r2, uint32_t& r3) {
    asm volatile("ldmatrix.sync.aligned.m8n8.x4.shared.b16 {%0,%1,%2,%3}, [%4];"
                 : "=r"(r0), "=r"(r1), "=r"(r2), "=r"(r3) : "r"(addr));
}
__device__ __forceinline__ void ldsm_x4t(uint32_t addr, uint32_t& r0, uint32_t& r1,
                                         uint32_t& r2, uint32_t& r3) {
    asm volatile("ldmatrix.sync.aligned.m8n8.x4.trans.shared.b16 {%0,%1,%2,%3}, [%4];"
                 : "=r"(r0), "=r"(r1), "=r"(r2), "=r"(r3) : "r"(addr));
}
__device__ __forceinline__ void mma16816(float* c, const uint32_t* a, const uint32_t* b) {
    asm volatile(
        "mma.sync.aligned.m16n8k16.row.col.f32.bf16.bf16.f32 "
        "{%0,%1,%2,%3}, {%4,%5,%6,%7}, {%8,%9}, {%0,%1,%2,%3};"
        : "+f"(c[0]), "+f"(c[1]), "+f"(c[2]), "+f"(c[3])
        : "r"(a[0]), "r"(a[1]), "r"(a[2]), "r"(a[3]), "r"(b[0]), "r"(b[1]));
}
__device__ __forceinline__ void mma16816h(float* c, const uint32_t* a, const uint32_t* b) {
    asm volatile(
        "mma.sync.aligned.m16n8k16.row.col.f32.f16.f16.f32 "
        "{%0,%1,%2,%3}, {%4,%5,%6,%7}, {%8,%9}, {%0,%1,%2,%3};"
        : "+f"(c[0]), "+f"(c[1]), "+f"(c[2]), "+f"(c[3])
        : "r"(a[0]), "r"(a[1]), "r"(a[2]), "r"(a[3]), "r"(b[0]), "r"(b[1]));
}
__device__ __forceinline__ uint32_t pack_bf16x2(float lo, float hi) {
    uint32_t r; asm("cvt.rn.bf16x2.f32 %0, %1, %2;" : "=r"(r) : "f"(hi), "f"(lo));
    return r;
}

// ---------------- scratch (static device globals; no allocs) ----------------
__device__ float g_Q   [S*HID];
__device__ float g_K   [S*KVDIM];
__device__ float g_V   [S*KVDIM];
__device__ float g_attn[S*HID];
__device__ bf16 g_hH[S*HID],     g_hL[S*HID];
__device__ bf16 g_WqH[HID*HID],  g_WqL[HID*HID];
__device__ bf16 g_WkH[KVDIM*HID],g_WkL[KVDIM*HID];
__device__ bf16 g_WvH[KVDIM*HID],g_WvL[KVDIM*HID];
__device__ __half g_WoF[HID*HID];                  // Wo in fp16 (hi only)
__device__ __half g_aHf[S*HID],  g_aLf[S*HID];     // attn out fp16 hi/lo
__device__ bf16 g_Qh[S*HID],    g_Ql[S*HID];
__device__ bf16 g_bKh[S*KVDIM], g_bKl[S*KVDIM];
__device__ bf16 g_nKh[S*KVDIM], g_nKl[S*KVDIM];
__device__ bf16 g_Vh[S*KVDIM],  g_Vl[S*KVDIM];

// ---------------- fp32 -> bf16 hi/lo split ----------------
__device__ __forceinline__ void split_body(const float* __restrict__ x,
                                           bf16* __restrict__ hi, bf16* __restrict__ lo,
                                           int i)
{
    float4 v = ((const float4*)x)[i];
    bf16 h0 = __float2bfloat16(v.x);
    bf16 h1 = __float2bfloat16(v.y);
    bf16 h2 = __float2bfloat16(v.z);
    bf16 h3 = __float2bfloat16(v.w);
    __nv_bfloat162 H0 = __nv_bfloat162(h0, h1), H1 = __nv_bfloat162(h2, h3);
    __nv_bfloat162 L0 = __nv_bfloat162(__float2bfloat16(v.x - __bfloat162float(h0)),
                                       __float2bfloat16(v.y - __bfloat162float(h1)));
    __nv_bfloat162 L1 = __nv_bfloat162(__float2bfloat16(v.z - __bfloat162float(h2)),
                                       __float2bfloat16(v.w - __bfloat162float(h3)));
    ((__nv_bfloat162*)hi)[i*2+0] = H0; ((__nv_bfloat162*)hi)[i*2+1] = H1;
    ((__nv_bfloat162*)lo)[i*2+0] = L0; ((__nv_bfloat162*)lo)[i*2+1] = L1;
}

// merged split of hidden/Wq/Wk/Wv (bf16 hi/lo), 4 float4 per thread
__global__ __launch_bounds__(256)
void split_all_kernel(const float* __restrict__ hid, const float* __restrict__ Wq,
                      const float* __restrict__ Wk,  const float* __restrict__ Wv,
                      bf16* __restrict__ hH, bf16* __restrict__ hL,
                      bf16* __restrict__ qH, bf16* __restrict__ qL,
                      bf16* __restrict__ kH, bf16* __restrict__ kL,
                      bf16* __restrict__ vH, bf16* __restrict__ vL)
{
    int g0 = (blockIdx.x * 256 + threadIdx.x) * 4;   // region bounds all %4==0
    const int R0 = 1048576, R1 = R0 + 1048576, R2 = R1 + 262144;
    const int TOT = R2 + 262144;
    if (g0 >= TOT) return;
    const float* src; bf16 *dh, *dl; int rb;
    if (g0 < R0)      { src = hid; dh = hH; dl = hL; rb = 0;  }
    else if (g0 < R1) { src = Wq;  dh = qH; dl = qL; rb = R0; }
    else if (g0 < R2) { src = Wk;  dh = kH; dl = kL; rb = R1; }
    else              { src = Wv;  dh = vH; dl = vL; rb = R2; }
#pragma unroll
    for (int k = 0; k < 4; k++) split_body(src, dh, dl, g0 - rb + k);
}

// Wo -> fp16 (hi only), 4 float4 per thread
__global__ __launch_bounds__(256)
void wo_half_kernel(const float* __restrict__ x, __half* __restrict__ y)
{
    int base = (blockIdx.x * 256 + threadIdx.x) * 4;
#pragma unroll
    for (int k = 0; k < 4; k++) {
        int i = base + k;
        float4 v = ((const float4*)x)[i];
        __half2 a = __half2(__float2half_rn(v.x), __float2half_rn(v.y));
        __half2 b = __half2(__float2half_rn(v.z), __float2half_rn(v.w));
        ((__half2*)y)[i*2+0] = a;
        ((__half2*)y)[i*2+1] = b;
    }
}

// attn fp32 -> fp16 hi/lo split, 4 float4 per thread
__global__ __launch_bounds__(256)
void split4h_kernel(const float* __restrict__ x, __half* __restrict__ hi,
                    __half* __restrict__ lo)
{
    int base = (blockIdx.x * 256 + threadIdx.x) * 4;
#pragma unroll
    for (int k = 0; k < 4; k++) {
        int i = base + k;
        float4 v = ((const float4*)x)[i];
        __half h0 = __float2half_rn(v.x), h1 = __float2half_rn(v.y);
        __half h2 = __float2half_rn(v.z), h3 = __float2half_rn(v.w);
        ((__half2*)hi)[i*2+0] = __half2(h0, h1);
        ((__half2*)hi)[i*2+1] = __half2(h2, h3);
        ((__half2*)lo)[i*2+0] = __half2(__float2half_rn(v.x - __half2float(h0)),
                                        __float2half_rn(v.y - __half2float(h1)));
        ((__half2*)lo)[i*2+1] = __half2(__float2half_rn(v.z - __half2float(h2)),
                                        __float2half_rn(v.w - __half2float(h3)));
    }
}

// ---------------- mma.sync split-bf16 GEMM core (3-pass, unchanged) ----
#define STG      16384
#define SM_STAGE (4*STG)          // 64 KB
#define SM_TOTAL (2*SM_STAGE)     // 128 KB

__device__ __forceinline__ void g_load_stage(
    uint32_t sbuf,
    const bf16* __restrict__ Ah, const bf16* __restrict__ Al,
    const bf16* __restrict__ Bh, const bf16* __restrict__ Bl,
    int mBase, int nBase, int Kdim, int k0, int tid)
{
#pragma unroll
    for (int i = 0; i < 4; i++) {
        int u = i * 256 + tid;
        int r = u >> 3, c = u & 7;
        uint32_t so = (uint32_t)(r * 128 + ((c ^ (r & 7)) << 4));
        size_t eoffA = (size_t)(mBase + r) * Kdim + k0 + c * 8;
        size_t eoffB = (size_t)(nBase + r) * Kdim + k0 + c * 8;
        cp16(sbuf +          so, Ah + eoffA);
        cp16(sbuf +   STG  + so, Al + eoffA);
        cp16(sbuf + 2*STG  + so, Bh + eoffB);
        cp16(sbuf + 3*STG  + so, Bl + eoffB);
    }
}

__device__ __forceinline__ void gemm_body(
    const bf16* __restrict__ Ah, const bf16* __restrict__ Al,
    const bf16* __restrict__ Bh, const bf16* __restrict__ Bl,
    float* __restrict__ C, int Ntot, int Kdim, int mBase, int nBase, uint32_t sb)
{
    const int tid  = threadIdx.x;
    const int lane = tid & 31;
    const int wid  = tid >> 5;
    const int wm   = wid & 1;
    const int wn   = wid >> 1;

    float acc[4][4][4];
#pragma unroll
    for (int i = 0; i < 4; i++)
#pragma unroll
        for (int j = 0; j < 4; j++)
#pragma unroll
            for (int k = 0; k < 4; k++) acc[i][j][k] = 0.0f;

    const int NC = Kdim >> 6;

    g_load_stage(sb,            Ah, Al, Bh, Bl, mBase, nBase, Kdim, 0,  tid);
    CP_COMMIT();
    g_load_stage(sb + SM_STAGE, Ah, Al, Bh, Bl, mBase, nBase, Kdim, 64, tid);
    CP_COMMIT();

    const int aRow = wm * 64;
    const int bRow = wn * 32;

    for (int c = 0; c < NC; c++) {
        CP_WAIT1();
        __syncthreads();
        const uint32_t sbuf = sb + (c & 1) * SM_STAGE;
        const uint32_t sAh = sbuf, sAl = sbuf + STG, sBh = sbuf + 2*STG, sBl = sbuf + 3*STG;

#pragma unroll
        for (int ks = 0; ks < 4; ks++) {
            uint32_t aH[4][4], aL[4][4], bH[4][2], bL[4][2];
            {
                int rA = aRow + (lane & 15);
                int ccA = ks * 2 + (lane >> 4);
#pragma unroll
                for (int mf = 0; mf < 4; mf++) {
                    int r = rA + mf * 16;
                    uint32_t so = (uint32_t)(r * 128 + ((ccA ^ (r & 7)) << 4));
                    ldsm_x4(sAh + so, aH[mf][0], aH[mf][1], aH[mf][2], aH[mf][3]);
                    ldsm_x4(sAl + so, aL[mf][0], aL[mf][1], aL[mf][2], aL[mf][3]);
                }
            }
            {
                int rB0 = bRow + (lane & 7) + ((lane >> 4) << 3);
                int ccB = ks * 2 + ((lane >> 3) & 1);
#pragma unroll
                for (int nf2 = 0; nf2 < 2; nf2++) {
                    int r = rB0 + nf2 * 16;
                    uint32_t so = (uint32_t)(r * 128 + ((ccB ^ (r & 7)) << 4));
                    ldsm_x4(sBh + so, bH[nf2*2][0], bH[nf2*2][1], bH[nf2*2+1][0], bH[nf2*2+1][1]);
                    ldsm_x4(sBl + so, bL[nf2*2][0], bL[nf2*2][1], bL[nf2*2+1][0], bL[nf2*2+1][1]);
                }
            }
#pragma unroll
            for (int mf = 0; mf < 4; mf++)
#pragma unroll
                for (int nf = 0; nf < 4; nf++) {
                    mma16816(acc[mf][nf], aH[mf], bH[nf]);
                    mma16816(acc[mf][nf], aL[mf], bH[nf]);
                    mma16816(acc[mf][nf], aH[mf], bL[nf]);
                }
        }
        __syncthreads();
        if (c + 2 < NC)
            g_load_stage(sb + (c & 1) * SM_STAGE, Ah, Al, Bh, Bl,
                         mBase, nBase, Kdim, (c + 2) * 64, tid);
        CP_COMMIT();
    }

#pragma unroll
    for (int mf = 0; mf < 4; mf++) {
        int row0 = mBase + wm * 64 + mf * 16 + (lane >> 2);
#pragma unroll
        for (int nf = 0; nf < 4; nf++) {
            int col = nBase + wn * 32 + nf * 8 + (lane & 3) * 2;
            *(float2*)&C[(size_t)row0 * Ntot + col]       = make_float2(acc[mf][nf][0], acc[mf][nf][1]);
            *(float2*)&C[(size_t)(row0 + 8) * Ntot + col] = make_float2(acc[mf][nf][2], acc[mf][nf][3]);
        }
    }
}

// fused QKV projection: bx 0..15 -> Q, 16..19 -> K, 20..23 -> V
__global__ __launch_bounds__(256)
void qkv_gemm(const bf16* __restrict__ Ah, const bf16* __restrict__ Al,
              const bf16* __restrict__ WqH, const bf16* __restrict__ WqL,
              const bf16* __restrict__ WkH, const bf16* __restrict__ WkL,
              const bf16* __restrict__ WvH, const bf16* __restrict__ WvL,
              float* __restrict__ Cq, float* __restrict__ Ck, float* __restrict__ Cv)
{
    extern __shared__ char dyns[];
    uint32_t sb = smem_u32(dyns);
    int bx = blockIdx.x, mBase = blockIdx.y * 128;
    if (bx < 16)      gemm_body(Ah, Al, WqH, WqL, Cq, HID,   HID, mBase, bx*128,      sb);
    else if (bx < 20) gemm_body(Ah, Al, WkH, WkL, Ck, KVDIM, HID, mBase, (bx-16)*128, sb);
    else              gemm_body(Ah, Al, WvH, WvL, Cv, KVDIM, HID, mBase, (bx-20)*128, sb);
}

// ---------------- 2-pass fp16 GEMM for Wo: C = (Ah+Al) @ Bh^T ----------
#define STG2      16384
#define SM_STAGE2 (3*STG2)        // 48 KB
#define SM_TOTAL2 (2*SM_STAGE2)   // 96 KB -> 2 CTAs/SM

__device__ __forceinline__ void g_load_stage2(
    uint32_t sbuf,
    const __half* __restrict__ Ah, const __half* __restrict__ Al,
    const __half* __restrict__ Bh,
    int mBase, int nBase, int Kdim, int k0, int tid)
{
#pragma unroll
    for (int i = 0; i < 4; i++) {
        int u = i * 256 + tid;
        int r = u >> 3, c = u & 7;
        uint32_t so = (uint32_t)(r * 128 + ((c ^ (r & 7)) << 4));
        size_t eoffA = (size_t)(mBase + r) * Kdim + k0 + c * 8;
        size_t eoffB = (size_t)(nBase + r) * Kdim + k0 + c * 8;
        cp16(sbuf +          so, Ah + eoffA);
        cp16(sbuf +   STG2 + so, Al + eoffA);
        cp16(sbuf + 2*STG2 + so, Bh + eoffB);
    }
}

__global__ __launch_bounds__(256, 2)
void wo_gemm2(const __half* __restrict__ Ah, const __half* __restrict__ Al,
              const __half* __restrict__ Bh, float* __restrict__ C)
{
    extern __shared__ char dyns[];
    const uint32_t sb = smem_u32(dyns);
    const int tid  = threadIdx.x;
    const int lane = tid & 31;
    const int wid  = tid >> 5;
    const int wm   = wid & 1;
    const int wn   = wid >> 1;
    const int mBase = blockIdx.y * 128, nBase = blockIdx.x * 128;

    float acc[4][4][4];
#pragma unroll
    for (int i = 0; i < 4; i++)
#pragma unroll
        for (int j = 0; j < 4; j++)
#pragma unroll
            for (int k = 0; k < 4; k++) acc[i][j][k] = 0.0f;

    const int NC = HID >> 6;   // 32

    g_load_stage2(sb,             Ah, Al, Bh, mBase, nBase, HID, 0,  tid);
    CP_COMMIT();
    g_load_stage2(sb + SM_STAGE2, Ah, Al, Bh, mBase, nBase, HID, 64, tid);
    CP_COMMIT();

    const int aRow = wm * 64;
    const int bRow = wn * 32;

    for (int c = 0; c < NC; c++) {
        CP_WAIT1();
        __syncthreads();
        const uint32_t sbuf = sb + (c & 1) * SM_STAGE2;
        const uint32_t sAh = sbuf, sAl = sbuf + STG2, sBh = sbuf + 2*STG2;

#pragma unroll
        for (int ks = 0; ks < 4; ks++) {
            uint32_t aH[4][4], aL[4][4], bH[4][2];
            {
                int rA = aRow + (lane & 15);
                int ccA = ks * 2 + (lane >> 4);
#pragma unroll
                for (int mf = 0; mf < 4; mf++) {
                    int r = rA + mf * 16;
                    uint32_t so = (uint32_t)(r * 128 + ((ccA ^ (r & 7)) << 4));
                    ldsm_x4(sAh + so, aH[mf][0], aH[mf][1], aH[mf][2], aH[mf][3]);
                    ldsm_x4(sAl + so, aL[mf][0], aL[mf][1], aL[mf][2], aL[mf][3]);
                }
            }
            {
                int rB0 = bRow + (lane & 7) + ((lane >> 4) << 3);
                int ccB = ks * 2 + ((lane >> 3) & 1);
#pragma unroll
                for (int nf2 = 0; nf2 < 2; nf2++) {
                    int r = rB0 + nf2 * 16;
                    uint32_t so = (uint32_t)(r * 128 + ((ccB ^ (r & 7)) << 4));
                    ldsm_x4(sBh + so, bH[nf2*2][0], bH[nf2*2][1], bH[nf2*2+1][0], bH[nf2*2+1][1]);
                }
            }
#pragma unroll
            for (int mf = 0; mf < 4; mf++)
#pragma unroll
                for (int nf = 0; nf < 4; nf++) {
                    mma16816h(acc[mf][nf], aH[mf], bH[nf]);
                    mma16816h(acc[mf][nf], aL[mf], bH[nf]);
                }
        }
        __syncthreads();
        if (c + 2 < NC)
            g_load_stage2(sb + (c & 1) * SM_STAGE2, Ah, Al, Bh,
                          mBase, nBase, HID, (c + 2) * 64, tid);
        CP_COMMIT();
    }

#pragma unroll
    for (int mf = 0; mf < 4; mf++) {
        int row0 = mBase + wm * 64 + mf * 16 + (lane >> 2);
#pragma unroll
        for (int nf = 0; nf < 4; nf++) {
            int col = nBase + wn * 32 + nf * 8 + (lane & 3) * 2;
            *(float2*)&C[(size_t)row0 * HID + col]       = make_float2(acc[mf][nf][0], acc[mf][nf][1]);
            *(float2*)&C[(size_t)(row0 + 8) * HID + col] = make_float2(acc[mf][nf][2], acc[mf][nf][3]);
        }
    }
}

// ---------------- RoPE + split (R5-exact) --------------------------------
__device__ __forceinline__ void split_w(bf16* hp, bf16* lp, float x) {
    bf16 h = __float2bfloat16(x);
    *hp = h;
    *lp = __float2bfloat16(x - __bfloat162float(h));
}

__global__ void rope_split_kernel(const float* __restrict__ Q, const float* __restrict__ K,
                                  const float* __restrict__ V,
                                  bf16* __restrict__ qh, bf16* __restrict__ ql,
                                  bf16* __restrict__ kbh, bf16* __restrict__ kbl,
                                  bf16* __restrict__ knh, bf16* __restrict__ knl,
                                  bf16* __restrict__ vh, bf16* __restrict__ vl)
{
    const int s = blockIdx.x;
    const int tid = threadIdx.x; // 256
    const bool narrowRow = (s >= CTX);
    const float QS = 1.4426950408889634f * 0.125f;   // log2(e)/sqrt(64)

    __shared__ float cb[32], sb[32], cn[32], sn[32];
    if (tid < 32) {
        double inv = pow(10000.0, -(double)tid / 32.0);
        double ab = (double)s * inv;
        double an = ((double)s * 0.25) * inv;
        cb[tid] = (float)cos(ab); sb[tid] = (float)sin(ab);
        cn[tid] = (float)cos(an); sn[tid] = (float)sin(an);
    }
    __syncthreads();

    for (int p = tid; p < NH * 32; p += 256) {
        int h = p >> 5, d = p & 31;
        size_t base = (size_t)s * HID + h * HD;
        float x1 = Q[base + d];
        float x2 = Q[base + d + 32];
        float c  = narrowRow ? cn[d] : cb[d];
        float si = narrowRow ? sn[d] : sb[d];
        split_w(qh + base + d,      ql + base + d,      (x1 * c - x2 * si) * QS);
        split_w(qh + base + d + 32, ql + base + d + 32, (x2 * c + x1 * si) * QS);
    }
    for (int p = tid; p < NKV * 32; p += 256) {
        int h = p >> 5, d = p & 31;
        size_t base = (size_t)s * KVDIM + h * HD;
        float x1 = K[base + d];
        float x2 = K[base + d + 32];
        split_w(kbh + base + d,      kbl + base + d,      x1 * cb[d] - x2 * sb[d]);
        split_w(kbh + base + d + 32, kbl + base + d + 32, x2 * cb[d] + x1 * sb[d]);
        split_w(knh + base + d,      knl + base + d,      x1 * cn[d] - x2 * sn[d]);
        split_w(knh + base + d + 32, knl + base + d + 32, x2 * cn[d] + x1 * sn[d]);
    }
    for (int e = tid; e < KVDIM; e += 256) {
        size_t base = (size_t)s * KVDIM + e;
        split_w(vh + base, vl + base, V[base]);
    }
}

// ---------------- Tensor-core flash attention (R5-exact) -------------------
template<bool DUAL>
__device__ __forceinline__ void fa_load_stage(
    uint32_t sb, int kt, int kvh, int tid,
    const bf16* __restrict__ Kbh, const bf16* __restrict__ Kbl,
    const bf16* __restrict__ Knh, const bf16* __restrict__ Knl,
    const bf16* __restrict__ Vh, const bf16* __restrict__ Vl)
{
#pragma unroll
    for (int i = 0; i < 4; i++) {
        int u = i * 128 + tid;      // 0..511
        int r = u >> 3, c = u & 7;
        uint32_t so = (uint32_t)(r * 128 + ((c ^ (r & 7)) << 4));
        size_t go = (size_t)(kt * 64 + r) * KVDIM + kvh * 64 + c * 8;
        cp16(sb +         so, Kbh + go);
        cp16(sb + 8192  + so, Kbl + go);
        cp16(sb + 16384 + so, Vh + go);
        cp16(sb + 24576 + so, Vl + go);
        if (DUAL) {
            cp16(sb + 32768 + so, Knh + go);
            cp16(sb + 40960 + so, Knl + go);
        }
    }
}

__device__ __forceinline__ void fa_compute_S(
    float s[8][4], uint32_t sKh, uint32_t sKl,
    const uint32_t qfh[4][4], const uint32_t qfl[4][4], int lane)
{
#pragma unroll
    for (int kk = 0; kk < 4; kk++) {
        uint32_t kh[8][2], kl[8][2];
        int rB0 = (lane & 7) + ((lane >> 4) << 3);
        int ccB = kk * 2 + ((lane >> 3) & 1);
#pragma unroll
        for (int nb = 0; nb < 4; nb++) {
            int r = nb * 16 + rB0;
            uint32_t so = (uint32_t)(r * 128 + ((ccB ^ (r & 7)) << 4));
            ldsm_x4(sKh + so, kh[nb*2][0], kh[nb*2][1], kh[nb*2+1][0], kh[nb*2+1][1]);
            ldsm_x4(sKl + so, kl[nb*2][0], kl[nb*2][1], kl[nb*2+1][0], kl[nb*2+1][1]);
        }
#pragma unroll
        for (int nf = 0; nf < 8; nf++) {
            mma16816(s[nf], qfh[kk], kh[nf]);
            mma16816(s[nf], qfl[kk], kh[nf]);
            mma16816(s[nf], qfh[kk], kl[nf]);
        }
    }
}

template<bool DUAL>
__global__ __launch_bounds__(128, DUAL ? 1 : 2)
void flash_mma(const bf16* __restrict__ Qh, const bf16* __restrict__ Ql,
               const bf16* __restrict__ Kbh, const bf16* __restrict__ Kbl,
               const bf16* __restrict__ Knh, const bf16* __restrict__ Knl,
               const bf16* __restrict__ Vh,  const bf16* __restrict__ Vl,
               float* __restrict__ attnOut)
{
    constexpr int STAGE = DUAL ? 49152 : 32768;
    extern __shared__ char dyn[];
    const uint32_t sQ = smem_u32(dyn);           // Qh 8K | Ql 8K | stage0 | stage1

    const int tid = threadIdx.x, lane = tid & 31, w = tid >> 5;
    const int qt = DUAL ? (S/64 - 1) : (S/64 - 2 - (int)blockIdx.x);   // heavy first
    const int h = blockIdx.y, kvh = h >> 2;

    {
        const bf16* gQh = Qh + (size_t)(qt * 64) * HID + h * 64;
        const bf16* gQl = Ql + (size_t)(qt * 64) * HID + h * 64;
#pragma unroll
        for (int i = 0; i < 4; i++) {
            int u = i * 128 + tid;
            int r = u >> 3, c = u & 7;
            uint32_t so = (uint32_t)(r * 128 + ((c ^ (r & 7)) << 4));
            cp16(sQ +        so, gQh + (size_t)r * HID + c * 8);
            cp16(sQ + 8192 + so, gQl + (size_t)r * HID + c * 8);
        }
    }
    fa_load_stage<DUAL>(sQ + 16384, 0, kvh, tid, Kbh, Kbl, Knh, Knl, Vh, Vl);
    CP_COMMIT();
    if (qt >= 1)
        fa_load_stage<DUAL>(sQ + 16384 + STAGE, 1, kvh, tid, Kbh, Kbl, Knh, Knl, Vh, Vl);
    CP_COMMIT();

    CP_WAIT1();
    __syncthreads();

    uint32_t qfh[4][4], qfl[4][4];
    {
        int rA = w * 16 + (lane & 15);
#pragma unroll
        for (int kk = 0; kk < 4; kk++) {
            int cc = kk * 2 + (lane >> 4);
            uint32_t so = (uint32_t)(rA * 128 + ((cc ^ (rA & 7)) << 4));
            ldsm_x4(sQ + so,        qfh[kk][0], qfh[kk][1], qfh[kk][2], qfh[kk][3]);
            ldsm_x4(sQ + 8192 + so, qfl[kk][0], qfl[kk][1], qfl[kk][2], qfl[kk][3]);
        }
    }

    float o[8][4];
#pragma unroll
    for (int nf = 0; nf < 8; nf++)
#pragma unroll
        for (int j = 0; j < 4; j++) o[nf][j] = 0.0f;
    float m0 = -1e30f, m1 = -1e30f, l0 = 0.0f, l1 = 0.0f;

    const int rg0 = qt * 64 + w * 16 + (lane >> 2);
    const int rg1 = rg0 + 8;

    for (int kt = 0; kt <= qt; kt++) {
        if (kt) { CP_WAIT1(); __syncthreads(); }
        const uint32_t sb = sQ + 16384 + (kt & 1) * STAGE;

        float s[8][4];
#pragma unroll
        for (int nf = 0; nf < 8; nf++)
#pragma unroll
            for (int j = 0; j < 4; j++) s[nf][j] = 0.0f;
        fa_compute_S(s, sb, sb + 8192, qfh, qfl, lane);

        if (DUAL) {
            float sn[8][4];
#pragma unroll
            for (int nf = 0; nf < 8; nf++)
#pragma unroll
                for (int j = 0; j < 4; j++) sn[nf][j] = 0.0f;
            fa_compute_S(sn, sb + 32768, sb + 40960, qfh, qfl, lane);
            if (rg0 >= CTX) {
#pragma unroll
                for (int nf = 0; nf < 8; nf++) { s[nf][0] = sn[nf][0]; s[nf][1] = sn[nf][1]; }
            }
            if (rg1 >= CTX) {
#pragma unroll
                for (int nf = 0; nf < 8; nf++) { s[nf][2] = sn[nf][2]; s[nf][3] = sn[nf][3]; }
            }
        }

        if (kt == qt) {
#pragma unroll
            for (int nf = 0; nf < 8; nf++) {
                int c0 = kt * 64 + nf * 8 + (lane & 3) * 2;
                if (c0     > rg0) s[nf][0] = -1e30f;
                if (c0 + 1 > rg0) s[nf][1] = -1e30f;
                if (c0     > rg1) s[nf][2] = -1e30f;
                if (c0 + 1 > rg1) s[nf][3] = -1e30f;
            }
        }

        float mr0 = -1e30f, mr1 = -1e30f;
#pragma unroll
        for (int nf = 0; nf < 8; nf++) {
            mr0 = fmaxf(mr0, fmaxf(s[nf][0], s[nf][1]));
            mr1 = fmaxf(mr1, fmaxf(s[nf][2], s[nf][3]));
        }
        mr0 = fmaxf(mr0, __shfl_xor_sync(0xffffffffu, mr0, 1));
        mr0 = fmaxf(mr0, __shfl_xor_sync(0xffffffffu, mr0, 2));
        mr1 = fmaxf(mr1, __shfl_xor_sync(0xffffffffu, mr1, 1));
        mr1 = fmaxf(mr1, __shfl_xor_sync(0xffffffffu, mr1, 2));

        float mn0 = fmaxf(m0, mr0), mn1 = fmaxf(m1, mr1);
        float sc0 = exp2f(m0 - mn0), sc1 = exp2f(m1 - mn1);
        m0 = mn0; m1 = mn1;
        l0 *= sc0; l1 *= sc1;
#pragma unroll
        for (int nf = 0; nf < 8; nf++) {
            o[nf][0] *= sc0; o[nf][1] *= sc0;
            o[nf][2] *= sc1; o[nf][3] *= sc1;
        }

        uint32_t pH[4][4], pL[4][4];
        float sum0 = 0.0f, sum1 = 0.0f;
#pragma unroll
        for (int nf = 0; nf < 8; nf++) {
            float p0 = exp2f(s[nf][0] - m0), p1 = exp2f(s[nf][1] - m0);
            float p2 = exp2f(s[nf][2] - m1), p3 = exp2f(s[nf][3] - m1);
            sum0 += p0 + p1; sum1 += p2 + p3;
            float r0 = __bfloat162float(__float2bfloat16(p0));
            float r1 = __bfloat162float(__float2bfloat16(p1));
            float r2 = __bfloat162float(__float2bfloat16(p2));
            float r3 = __bfloat162float(__float2bfloat16(p3));
            int kk = nf >> 1;
            int off = (nf & 1) * 2;
            pH[kk][off + 0] = pack_bf16x2(p0, p1);
            pH[kk][off + 1] = pack_bf16x2(p2, p3);
            pL[kk][off + 0] = pack_bf16x2(p0 - r0, p1 - r1);
            pL[kk][off + 1] = pack_bf16x2(p2 - r2, p3 - r3);
        }
        sum0 += __shfl_xor_sync(0xffffffffu, sum0, 1);
        sum0 += __shfl_xor_sync(0xffffffffu, sum0, 2);
        sum1 += __shfl_xor_sync(0xffffffffu, sum1, 1);
        sum1 += __shfl_xor_sync(0xffffffffu, sum1, 2);
        l0 += sum0; l1 += sum1;

        const uint32_t sVh = sb + 16384, sVl = sb + 24576;
#pragma unroll
        for (int kk = 0; kk < 4; kk++) {
            uint32_t vh[8][2], vl[8][2];
            int key0 = kk * 16 + (lane & 7) + ((lane >> 3) & 1) * 8;
#pragma unroll
            for (int nb = 0; nb < 4; nb++) {
                int chunk = nb * 2 + (lane >> 4);
                uint32_t so = (uint32_t)(key0 * 128 + ((chunk ^ (key0 & 7)) << 4));
                ldsm_x4t(sVh + so, vh[nb*2][0], vh[nb*2][1], vh[nb*2+1][0], vh[nb*2+1][1]);
                ldsm_x4t(sVl + so, vl[nb*2][0], vl[nb*2][1], vl[nb*2+1][0], vl[nb*2+1][1]);
            }
#pragma unroll
            for (int nf = 0; nf < 8; nf++) {
                mma16816(o[nf], pH[kk], vh[nf]);
                mma16816(o[nf], pL[kk], vh[nf]);
                mma16816(o[nf], pH[kk], vl[nf]);
            }
        }

        __syncthreads();
        if (kt + 2 <= qt)
            fa_load_stage<DUAL>(sQ + 16384 + (kt & 1) * STAGE, kt + 2, kvh, tid,
                                Kbh, Kbl, Knh, Knl, Vh, Vl);
        CP_COMMIT();
    }

    float inv0 = 1.0f / l0, inv1 = 1.0f / l1;
#pragma unroll
    for (int nf = 0; nf < 8; nf++) {
        int col = h * 64 + nf * 8 + (lane & 3) * 2;
        *(float2*)&attnOut[(size_t)rg0 * HID + col] = make_float2(o[nf][0]*inv0, o[nf][1]*inv0);
        *(float2*)&attnOut[(size_t)rg1 * HID + col] = make_float2(o[nf][2]*inv1, o[nf][3]*inv1);
    }
}

// ---------------- launch ----------------
extern "C" void kernel_launch(void* const* d_in, const int* in_sizes, int n_in,
                              void* d_out, int out_size)
{
    const float* hidden = (const float*)d_in[0];
    const float* Wq = (const float*)d_in[3];
    const float* Wk = (const float*)d_in[4];
    const float* Wv = (const float*)d_in[5];
    const float* Wo = (const float*)d_in[6];
    float* out = (float*)d_out;

    float *qB, *kB, *vB, *atB;
    cudaGetSymbolAddress((void**)&qB,  g_Q);
    cudaGetSymbolAddress((void**)&kB,  g_K);
    cudaGetSymbolAddress((void**)&vB,  g_V);
    cudaGetSymbolAddress((void**)&atB, g_attn);

    bf16 *hH,*hL,*WqH,*WqL,*WkH,*WkL,*WvH,*WvL;
    cudaGetSymbolAddress((void**)&hH,  g_hH);  cudaGetSymbolAddress((void**)&hL,  g_hL);
    cudaGetSymbolAddress((void**)&WqH, g_WqH); cudaGetSymbolAddress((void**)&WqL, g_WqL);
    cudaGetSymbolAddress((void**)&WkH, g_WkH); cudaGetSymbolAddress((void**)&WkL, g_WkL);
    cudaGetSymbolAddress((void**)&WvH, g_WvH); cudaGetSymbolAddress((void**)&WvL, g_WvL);

    __half *WoF, *aHf, *aLf;
    cudaGetSymbolAddress((void**)&WoF, g_WoF);
    cudaGetSymbolAddress((void**)&aHf, g_aHf);
    cudaGetSymbolAddress((void**)&aLf, g_aLf);

    bf16 *Qh,*Ql,*bKh,*bKl,*nKh,*nKl,*Vh,*Vl;
    cudaGetSymbolAddress((void**)&Qh,  g_Qh);  cudaGetSymbolAddress((void**)&Ql,  g_Ql);
    cudaGetSymbolAddress((void**)&bKh, g_bKh); cudaGetSymbolAddress((void**)&bKl, g_bKl);
    cudaGetSymbolAddress((void**)&nKh, g_nKh); cudaGetSymbolAddress((void**)&nKl, g_nKl);
    cudaGetSymbolAddress((void**)&Vh,  g_Vh);  cudaGetSymbolAddress((void**)&Vl,  g_Vl);

    cudaFuncSetAttribute(qkv_gemm, cudaFuncAttributeMaxDynamicSharedMemorySize, SM_TOTAL);
    cudaFuncSetAttribute(wo_gemm2, cudaFuncAttributeMaxDynamicSharedMemorySize, SM_TOTAL2);
    const int FA_SMEM_N = 16384 + 2*32768;   // 81920
    const int FA_SMEM_D = 16384 + 2*49152;   // 114688
    cudaFuncSetAttribute(flash_mma<false>, cudaFuncAttributeMaxDynamicSharedMemorySize, FA_SMEM_N);
    cudaFuncSetAttribute(flash_mma<true>,  cudaFuncAttributeMaxDynamicSharedMemorySize, FA_SMEM_D);

    // input splits: hidden/Wq/Wk/Wv -> bf16 h/l (one launch); Wo -> fp16
    const int TOT4 = 1048576*2 + 262144*2;   // float4 units
    split_all_kernel<<<(TOT4/4 + 255)/256, 256>>>(hidden, Wq, Wk, Wv,
                                                  hH, hL, WqH, WqL, WkH, WkL, WvH, WvL);
    wo_half_kernel<<<(1048576/4 + 255)/256, 256>>>(Wo, WoF);

    qkv_gemm<<<dim3(24, 16), 256, SM_TOTAL>>>(hH, hL, WqH, WqL, WkH, WkL, WvH, WvL,
                                              qB, kB, vB);

    rope_split_kernel<<<S, 256>>>(qB, kB, vB, Qh, Ql, bKh, bKl, nKh, nKl, Vh, Vl);

    // boundary tile (rows 1984..2047, contains CTX) — dual-variant kernel
    flash_mma<true><<<dim3(1, NH), 128, FA_SMEM_D>>>(Qh, Ql, bKh, bKl, nKh, nKl, Vh, Vl, atB);
    // remaining tiles, heavy first
    flash_mma<false><<<dim3(S/64 - 1, NH), 128, FA_SMEM_N>>>(Qh, Ql, bKh, bKl, nKh, nKl, Vh, Vl, atB);

    // attn -> fp16 hi/lo, then 2-pass fp16 Wo GEMM into d_out
    split4h_kernel<<<(1048576/4 + 255)/256, 256>>>(atB, aHf, aLf);
    wo_gemm2<<<dim3(16, 16), 256, SM_TOTAL2>>>(aHf, aLf, WoF, out);
}

// round 11
// speedup vs baseline: 1.2677x; 1.0514x over previous
#include <cuda_runtime.h>
#include <cuda_bf16.h>
#include <cuda_fp16.h>
#include <cstdint>

#define S     2048
#define HID   2048
#define NH    32
#define NKV   8
#define HD    64
#define KVDIM (NKV*HD)   // 512
#define CTX   (S-10)     // 2038: rows >= CTX use narrow rope

typedef unsigned long long ull;
typedef __nv_bfloat16 bf16;

__device__ __forceinline__ uint32_t smem_u32(const void* p) {
    uint32_t a;
    asm("{ .reg .u64 t; cvta.to.shared.u64 t, %1; cvt.u32.u64 %0, t; }" : "=r"(a) : "l"(p));
    return a;
}

// ---------------- mma.sync primitives (compute_103-safe) ----------------
__device__ __forceinline__ void cp16(uint32_t s, const void* g) {
    asm volatile("cp.async.cg.shared.global [%0], [%1], 16;" :: "r"(s), "l"(g));
}
#define CP_COMMIT() asm volatile("cp.async.commit_group;" ::: "memory")
#define CP_WAIT1()  asm volatile("cp.async.wait_group 1;" ::: "memory")

__device__ __forceinline__ void ldsm_x4(uint32_t addr, uint32_t& r0, uint32_t& r1,
                                        uint32_t& r2, uint32_t& r3) {
    asm volatile("ldmatrix.sync.aligned.m8n8.x4.shared.b16 {%0,%1,%2,%3}, [%4];"
                 : "=r"(r0), "=r"(r1), "=r"(r2), "=r"(r3) : "r"(addr));
}
__device__ __forceinline__ void ldsm_x4t(uint32_t addr, uint32_t& r0, uint32_t& r1,
                                         uint32_t& r2, uint32_t& r3) {
    asm volatile("ldmatrix.sync.aligned.m8n8.x4.trans.shared.b16 {%0,%1,%2,%3}, [%4];"
                 : "=r"(r0), "=r"(r1), "=r"(r2), "=r"(r3) : "r"(addr));
}
__device__ __forceinline__ void mma16816(float* c, const uint32_t* a, const uint32_t* b) {
    asm volatile(
        "mma.sync.aligned.m16n8k16.row.col.f32.bf16.bf16.f32 "
        "{%0,%1,%2,%3}, {%4,%5,%6,%7}, {%8,%9}, {%0,%1,%2,%3};"
        : "+f"(c[0]), "+f"(c[1]), "+f"(c[2]), "+f"(c[3])
        : "r"(a[0]), "r"(a[1]), "r"(a[2]), "r"(a[3]), "r"(b[0]), "r"(b[1]));
}
__device__ __forceinline__ void mma16816h(float* c, const uint32_t* a, const uint32_t* b) {
    asm volatile(
        "mma.sync.aligned.m16n8k16.row.col.f32.f16.f16.f32 "
        "{%0,%1,%2,%3}, {%4,%5,%6,%7}, {%8,%9}, {%0,%1,%2,%3};"
        : "+f"(c[0]), "+f"(c[1]), "+f"(c[2]), "+f"(c[3])
        : "r"(a[0]), "r"(a[1]), "r"(a[2]), "r"(a[3]), "r"(b[0]), "r"(b[1]));
}
__device__ __forceinline__ uint32_t pack_bf16x2(float lo, float hi) {
    uint32_t r; asm("cvt.rn.bf16x2.f32 %0, %1, %2;" : "=r"(r) : "f"(hi), "f"(lo));
    return r;
}
__device__ __forceinline__ uint32_t pack_f16x2(float lo, float hi) {
    uint32_t r; asm("cvt.rn.f16x2.f32 %0, %1, %2;" : "=r"(r) : "f"(hi), "f"(lo));
    return r;
}

// ---------------- scratch (static device globals; no allocs) ----------------
__device__ float g_Q   [S*HID];
__device__ float g_K   [S*KVDIM];
__device__ float g_V   [S*KVDIM];
__device__ float g_attn[S*HID];
__device__ bf16 g_hH[S*HID],     g_hL[S*HID];
__device__ bf16 g_WqH[HID*HID],  g_WqL[HID*HID];
__device__ bf16 g_WkH[KVDIM*HID],g_WkL[KVDIM*HID];
__device__ bf16 g_WvH[KVDIM*HID],g_WvL[KVDIM*HID];
__device__ __half g_WoF[HID*HID];                  // Wo in fp16 (hi only)
__device__ __half g_aHf[S*HID],  g_aLf[S*HID];     // attn out fp16 hi/lo
__device__ bf16 g_Qh[S*HID],    g_Ql[S*HID];
__device__ bf16 g_bKh[S*KVDIM], g_bKl[S*KVDIM];
__device__ bf16 g_nKh[S*KVDIM], g_nKl[S*KVDIM];
__device__ __half g_Vh[S*KVDIM], g_Vl[S*KVDIM];    // fp16 split of V

// ---------------- fp32 -> bf16 hi/lo split ----------------
__device__ __forceinline__ void split_body(const float* __restrict__ x,
                                           bf16* __restrict__ hi, bf16* __restrict__ lo,
                                           int i)
{
    float4 v = ((const float4*)x)[i];
    bf16 h0 = __float2bfloat16(v.x);
    bf16 h1 = __float2bfloat16(v.y);
    bf16 h2 = __float2bfloat16(v.z);
    bf16 h3 = __float2bfloat16(v.w);
    __nv_bfloat162 H0 = __nv_bfloat162(h0, h1), H1 = __nv_bfloat162(h2, h3);
    __nv_bfloat162 L0 = __nv_bfloat162(__float2bfloat16(v.x - __bfloat162float(h0)),
                                       __float2bfloat16(v.y - __bfloat162float(h1)));
    __nv_bfloat162 L1 = __nv_bfloat162(__float2bfloat16(v.z - __bfloat162float(h2)),
                                       __float2bfloat16(v.w - __bfloat162float(h3)));
    ((__nv_bfloat162*)hi)[i*2+0] = H0; ((__nv_bfloat162*)hi)[i*2+1] = H1;
    ((__nv_bfloat162*)lo)[i*2+0] = L0; ((__nv_bfloat162*)lo)[i*2+1] = L1;
}

// merged split of hidden/Wq/Wk/Wv (bf16 hi/lo), 4 float4 per thread
__global__ __launch_bounds__(256)
void split_all_kernel(const float* __restrict__ hid, const float* __restrict__ Wq,
                      const float* __restrict__ Wk,  const float* __restrict__ Wv,
                      bf16* __restrict__ hH, bf16* __restrict__ hL,
                      bf16* __restrict__ qH, bf16* __restrict__ qL,
                      bf16* __restrict__ kH, bf16* __restrict__ kL,
                      bf16* __restrict__ vH, bf16* __restrict__ vL)
{
    int g0 = (blockIdx.x * 256 + threadIdx.x) * 4;   // region bounds all %4==0
    const int R0 = 1048576, R1 = R0 + 1048576, R2 = R1 + 262144;
    const int TOT = R2 + 262144;
    if (g0 >= TOT) return;
    const float* src; bf16 *dh, *dl; int rb;
    if (g0 < R0)      { src = hid; dh = hH; dl = hL; rb = 0;  }
    else if (g0 < R1) { src = Wq;  dh = qH; dl = qL; rb = R0; }
    else if (g0 < R2) { src = Wk;  dh = kH; dl = kL; rb = R1; }
    else              { src = Wv;  dh = vH; dl = vL; rb = R2; }
#pragma unroll
    for (int k = 0; k < 4; k++) split_body(src, dh, dl, g0 - rb + k);
}

// Wo -> fp16 (hi only), 4 float4 per thread
__global__ __launch_bounds__(256)
void wo_half_kernel(const float* __restrict__ x, __half* __restrict__ y)
{
    int base = (blockIdx.x * 256 + threadIdx.x) * 4;
#pragma unroll
    for (int k = 0; k < 4; k++) {
        int i = base + k;
        float4 v = ((const float4*)x)[i];
        __half2 a = __half2(__float2half_rn(v.x), __float2half_rn(v.y));
        __half2 b = __half2(__float2half_rn(v.z), __float2half_rn(v.w));
        ((__half2*)y)[i*2+0] = a;
        ((__half2*)y)[i*2+1] = b;
    }
}

// attn fp32 -> fp16 hi/lo split, 4 float4 per thread
__global__ __launch_bounds__(256)
void split4h_kernel(const float* __restrict__ x, __half* __restrict__ hi,
                    __half* __restrict__ lo)
{
    int base = (blockIdx.x * 256 + threadIdx.x) * 4;
#pragma unroll
    for (int k = 0; k < 4; k++) {
        int i = base + k;
        float4 v = ((const float4*)x)[i];
        __half h0 = __float2half_rn(v.x), h1 = __float2half_rn(v.y);
        __half h2 = __float2half_rn(v.z), h3 = __float2half_rn(v.w);
        ((__half2*)hi)[i*2+0] = __half2(h0, h1);
        ((__half2*)hi)[i*2+1] = __half2(h2, h3);
        ((__half2*)lo)[i*2+0] = __half2(__float2half_rn(v.x - __half2float(h0)),
                                        __float2half_rn(v.y - __half2float(h1)));
        ((__half2*)lo)[i*2+1] = __half2(__float2half_rn(v.z - __half2float(h2)),
                                        __float2half_rn(v.w - __half2float(h3)));
    }
}

// ---------------- mma.sync split-bf16 GEMM core (3-pass, unchanged) ----
#define STG      16384
#define SM_STAGE (4*STG)          // 64 KB
#define SM_TOTAL (2*SM_STAGE)     // 128 KB

__device__ __forceinline__ void g_load_stage(
    uint32_t sbuf,
    const bf16* __restrict__ Ah, const bf16* __restrict__ Al,
    const bf16* __restrict__ Bh, const bf16* __restrict__ Bl,
    int mBase, int nBase, int Kdim, int k0, int tid)
{
#pragma unroll
    for (int i = 0; i < 4; i++) {
        int u = i * 256 + tid;
        int r = u >> 3, c = u & 7;
        uint32_t so = (uint32_t)(r * 128 + ((c ^ (r & 7)) << 4));
        size_t eoffA = (size_t)(mBase + r) * Kdim + k0 + c * 8;
        size_t eoffB = (size_t)(nBase + r) * Kdim + k0 + c * 8;
        cp16(sbuf +          so, Ah + eoffA);
        cp16(sbuf +   STG  + so, Al + eoffA);
        cp16(sbuf + 2*STG  + so, Bh + eoffB);
        cp16(sbuf + 3*STG  + so, Bl + eoffB);
    }
}

__device__ __forceinline__ void gemm_body(
    const bf16* __restrict__ Ah, const bf16* __restrict__ Al,
    const bf16* __restrict__ Bh, const bf16* __restrict__ Bl,
    float* __restrict__ C, int Ntot, int Kdim, int mBase, int nBase, uint32_t sb)
{
    const int tid  = threadIdx.x;
    const int lane = tid & 31;
    const int wid  = tid >> 5;
    const int wm   = wid & 1;
    const int wn   = wid >> 1;

    float acc[4][4][4];
#pragma unroll
    for (int i = 0; i < 4; i++)
#pragma unroll
        for (int j = 0; j < 4; j++)
#pragma unroll
            for (int k = 0; k < 4; k++) acc[i][j][k] = 0.0f;

    const int NC = Kdim >> 6;

    g_load_stage(sb,            Ah, Al, Bh, Bl, mBase, nBase, Kdim, 0,  tid);
    CP_COMMIT();
    g_load_stage(sb + SM_STAGE, Ah, Al, Bh, Bl, mBase, nBase, Kdim, 64, tid);
    CP_COMMIT();

    const int aRow = wm * 64;
    const int bRow = wn * 32;

    for (int c = 0; c < NC; c++) {
        CP_WAIT1();
        __syncthreads();
        const uint32_t sbuf = sb + (c & 1) * SM_STAGE;
        const uint32_t sAh = sbuf, sAl = sbuf + STG, sBh = sbuf + 2*STG, sBl = sbuf + 3*STG;

#pragma unroll
        for (int ks = 0; ks < 4; ks++) {
            uint32_t aH[4][4], aL[4][4], bH[4][2], bL[4][2];
            {
                int rA = aRow + (lane & 15);
                int ccA = ks * 2 + (lane >> 4);
#pragma unroll
                for (int mf = 0; mf < 4; mf++) {
                    int r = rA + mf * 16;
                    uint32_t so = (uint32_t)(r * 128 + ((ccA ^ (r & 7)) << 4));
                    ldsm_x4(sAh + so, aH[mf][0], aH[mf][1], aH[mf][2], aH[mf][3]);
                    ldsm_x4(sAl + so, aL[mf][0], aL[mf][1], aL[mf][2], aL[mf][3]);
                }
            }
            {
                int rB0 = bRow + (lane & 7) + ((lane >> 4) << 3);
                int ccB = ks * 2 + ((lane >> 3) & 1);
#pragma unroll
                for (int nf2 = 0; nf2 < 2; nf2++) {
                    int r = rB0 + nf2 * 16;
                    uint32_t so = (uint32_t)(r * 128 + ((ccB ^ (r & 7)) << 4));
                    ldsm_x4(sBh + so, bH[nf2*2][0], bH[nf2*2][1], bH[nf2*2+1][0], bH[nf2*2+1][1]);
                    ldsm_x4(sBl + so, bL[nf2*2][0], bL[nf2*2][1], bL[nf2*2+1][0], bL[nf2*2+1][1]);
                }
            }
#pragma unroll
            for (int mf = 0; mf < 4; mf++)
#pragma unroll
                for (int nf = 0; nf < 4; nf++) {
                    mma16816(acc[mf][nf], aH[mf], bH[nf]);
                    mma16816(acc[mf][nf], aL[mf], bH[nf]);
                    mma16816(acc[mf][nf], aH[mf], bL[nf]);
                }
        }
        __syncthreads();
        if (c + 2 < NC)
            g_load_stage(sb + (c & 1) * SM_STAGE, Ah, Al, Bh, Bl,
                         mBase, nBase, Kdim, (c + 2) * 64, tid);
        CP_COMMIT();
    }

#pragma unroll
    for (int mf = 0; mf < 4; mf++) {
        int row0 = mBase + wm * 64 + mf * 16 + (lane >> 2);
#pragma unroll
        for (int nf = 0; nf < 4; nf++) {
            int col = nBase + wn * 32 + nf * 8 + (lane & 3) * 2;
            *(float2*)&C[(size_t)row0 * Ntot + col]       = make_float2(acc[mf][nf][0], acc[mf][nf][1]);
            *(float2*)&C[(size_t)(row0 + 8) * Ntot + col] = make_float2(acc[mf][nf][2], acc[mf][nf][3]);
        }
    }
}

__global__ __launch_bounds__(256)
void qkv_gemm(const bf16* __restrict__ Ah, const bf16* __restrict__ Al,
              const bf16* __restrict__ WqH, const bf16* __restrict__ WqL,
              const bf16* __restrict__ WkH, const bf16* __restrict__ WkL,
              const bf16* __restrict__ WvH, const bf16* __restrict__ WvL,
              float* __restrict__ Cq, float* __restrict__ Ck, float* __restrict__ Cv)
{
    extern __shared__ char dyns[];
    uint32_t sb = smem_u32(dyns);
    int bx = blockIdx.x, mBase = blockIdx.y * 128;
    if (bx < 16)      gemm_body(Ah, Al, WqH, WqL, Cq, HID,   HID, mBase, bx*128,      sb);
    else if (bx < 20) gemm_body(Ah, Al, WkH, WkL, Ck, KVDIM, HID, mBase, (bx-16)*128, sb);
    else              gemm_body(Ah, Al, WvH, WvL, Cv, KVDIM, HID, mBase, (bx-20)*128, sb);
}

// ---------------- 2-pass fp16 GEMM for Wo: C = (Ah+Al) @ Bh^T ----------
#define STG2      16384
#define SM_STAGE2 (3*STG2)        // 48 KB
#define SM_TOTAL2 (2*SM_STAGE2)   // 96 KB -> 2 CTAs/SM

__device__ __forceinline__ void g_load_stage2(
    uint32_t sbuf,
    const __half* __restrict__ Ah, const __half* __restrict__ Al,
    const __half* __restrict__ Bh,
    int mBase, int nBase, int Kdim, int k0, int tid)
{
#pragma unroll
    for (int i = 0; i < 4; i++) {
        int u = i * 256 + tid;
        int r = u >> 3, c = u & 7;
        uint32_t so = (uint32_t)(r * 128 + ((c ^ (r & 7)) << 4));
        size_t eoffA = (size_t)(mBase + r) * Kdim + k0 + c * 8;
        size_t eoffB = (size_t)(nBase + r) * Kdim + k0 + c * 8;
        cp16(sbuf +          so, Ah + eoffA);
        cp16(sbuf +   STG2 + so, Al + eoffA);
        cp16(sbuf + 2*STG2 + so, Bh + eoffB);
    }
}

__global__ __launch_bounds__(256, 2)
void wo_gemm2(const __half* __restrict__ Ah, const __half* __restrict__ Al,
              const __half* __restrict__ Bh, float* __restrict__ C)
{
    extern __shared__ char dyns[];
    const uint32_t sb = smem_u32(dyns);
    const int tid  = threadIdx.x;
    const int lane = tid & 31;
    const int wid  = tid >> 5;
    const int wm   = wid & 1;
    const int wn   = wid >> 1;
    const int mBase = blockIdx.y * 128, nBase = blockIdx.x * 128;

    float acc[4][4][4];
#pragma unroll
    for (int i = 0; i < 4; i++)
#pragma unroll
        for (int j = 0; j < 4; j++)
#pragma unroll
            for (int k = 0; k < 4; k++) acc[i][j][k] = 0.0f;

    const int NC = HID >> 6;   // 32

    g_load_stage2(sb,             Ah, Al, Bh, mBase, nBase, HID, 0,  tid);
    CP_COMMIT();
    g_load_stage2(sb + SM_STAGE2, Ah, Al, Bh, mBase, nBase, HID, 64, tid);
    CP_COMMIT();

    const int aRow = wm * 64;
    const int bRow = wn * 32;

    for (int c = 0; c < NC; c++) {
        CP_WAIT1();
        __syncthreads();
        const uint32_t sbuf = sb + (c & 1) * SM_STAGE2;
        const uint32_t sAh = sbuf, sAl = sbuf + STG2, sBh = sbuf + 2*STG2;

#pragma unroll
        for (int ks = 0; ks < 4; ks++) {
            uint32_t aH[4][4], aL[4][4], bH[4][2];
            {
                int rA = aRow + (lane & 15);
                int ccA = ks * 2 + (lane >> 4);
#pragma unroll
                for (int mf = 0; mf < 4; mf++) {
                    int r = rA + mf * 16;
                    uint32_t so = (uint32_t)(r * 128 + ((ccA ^ (r & 7)) << 4));
                    ldsm_x4(sAh + so, aH[mf][0], aH[mf][1], aH[mf][2], aH[mf][3]);
                    ldsm_x4(sAl + so, aL[mf][0], aL[mf][1], aL[mf][2], aL[mf][3]);
                }
            }
            {
                int rB0 = bRow + (lane & 7) + ((lane >> 4) << 3);
                int ccB = ks * 2 + ((lane >> 3) & 1);
#pragma unroll
                for (int nf2 = 0; nf2 < 2; nf2++) {
                    int r = rB0 + nf2 * 16;
                    uint32_t so = (uint32_t)(r * 128 + ((ccB ^ (r & 7)) << 4));
                    ldsm_x4(sBh + so, bH[nf2*2][0], bH[nf2*2][1], bH[nf2*2+1][0], bH[nf2*2+1][1]);
                }
            }
#pragma unroll
            for (int mf = 0; mf < 4; mf++)
#pragma unroll
                for (int nf = 0; nf < 4; nf++) {
                    mma16816h(acc[mf][nf], aH[mf], bH[nf]);
                    mma16816h(acc[mf][nf], aL[mf], bH[nf]);
                }
        }
        __syncthreads();
        if (c + 2 < NC)
            g_load_stage2(sb + (c & 1) * SM_STAGE2, Ah, Al, Bh,
                          mBase, nBase, HID, (c + 2) * 64, tid);
        CP_COMMIT();
    }

#pragma unroll
    for (int mf = 0; mf < 4; mf++) {
        int row0 = mBase + wm * 64 + mf * 16 + (lane >> 2);
#pragma unroll
        for (int nf = 0; nf < 4; nf++) {
            int col = nBase + wn * 32 + nf * 8 + (lane & 3) * 2;
            *(float2*)&C[(size_t)row0 * HID + col]       = make_float2(acc[mf][nf][0], acc[mf][nf][1]);
            *(float2*)&C[(size_t)(row0 + 8) * HID + col] = make_float2(acc[mf][nf][2], acc[mf][nf][3]);
        }
    }
}

// ---------------- RoPE + split (vectorized: dim-pairs per thread) ----------
__device__ __forceinline__ void split_w2(bf16* hp, bf16* lp, float x0, float x1) {
    bf16 h0 = __float2bfloat16(x0);
    bf16 h1 = __float2bfloat16(x1);
    *(__nv_bfloat162*)hp = __nv_bfloat162(h0, h1);
    *(__nv_bfloat162*)lp = __nv_bfloat162(__float2bfloat16(x0 - __bfloat162float(h0)),
                                          __float2bfloat16(x1 - __bfloat162float(h1)));
}

__global__ void rope_split_kernel(const float* __restrict__ Q, const float* __restrict__ K,
                                  const float* __restrict__ V,
                                  bf16* __restrict__ qh, bf16* __restrict__ ql,
                                  bf16* __restrict__ kbh, bf16* __restrict__ kbl,
                                  bf16* __restrict__ knh, bf16* __restrict__ knl,
                                  __half* __restrict__ vh, __half* __restrict__ vl)
{
    const int s = blockIdx.x;
    const int tid = threadIdx.x; // 256
    const bool narrowRow = (s >= CTX);
    const float QS = 1.4426950408889634f * 0.125f;   // log2(e)/sqrt(64)

    __shared__ float cb[32], sb[32], cn[32], sn[32];
    if (tid < 32) {
        double inv = pow(10000.0, -(double)tid / 32.0);
        double ab = (double)s * inv;
        double an = ((double)s * 0.25) * inv;
        cb[tid] = (float)cos(ab); sb[tid] = (float)sin(ab);
        cn[tid] = (float)cos(an); sn[tid] = (float)sin(an);
    }
    __syncthreads();

    // Q: NH*16 = 512 dim-pair units; each handles dims (dd,dd+1) & (dd+32,dd+33)
    for (int p = tid; p < NH * 16; p += 256) {
        int h = p >> 4, dd = (p & 15) * 2;
        size_t base = (size_t)s * HID + h * HD;
        float2 x1 = *(const float2*)&Q[base + dd];
        float2 x2 = *(const float2*)&Q[base + dd + 32];
        float c0, c1, s0, s1;
        if (narrowRow) { c0 = cn[dd]; c1 = cn[dd+1]; s0 = sn[dd]; s1 = sn[dd+1]; }
        else           { c0 = cb[dd]; c1 = cb[dd+1]; s0 = sb[dd]; s1 = sb[dd+1]; }
        split_w2(qh + base + dd,      ql + base + dd,
                 (x1.x * c0 - x2.x * s0) * QS, (x1.y * c1 - x2.y * s1) * QS);
        split_w2(qh + base + dd + 32, ql + base + dd + 32,
                 (x2.x * c0 + x1.x * s0) * QS, (x2.y * c1 + x1.y * s1) * QS);
    }
    // K: NKV*16 = 128 dim-pair units, both variants
    for (int p = tid; p < NKV * 16; p += 256) {
        int h = p >> 4, dd = (p & 15) * 2;
        size_t base = (size_t)s * KVDIM + h * HD;
        float2 x1 = *(const float2*)&K[base + dd];
        float2 x2 = *(const float2*)&K[base + dd + 32];
        float cb0 = cb[dd], cb1 = cb[dd+1], sb0 = sb[dd], sb1 = sb[dd+1];
        float cn0 = cn[dd], cn1 = cn[dd+1], sn0 = sn[dd], sn1 = sn[dd+1];
        split_w2(kbh + base + dd,      kbl + base + dd,
                 x1.x * cb0 - x2.x * sb0, x1.y * cb1 - x2.y * sb1);
        split_w2(kbh + base + dd + 32, kbl + base + dd + 32,
                 x2.x * cb0 + x1.x * sb0, x2.y * cb1 + x1.y * sb1);
        split_w2(knh + base + dd,      knl + base + dd,
                 x1.x * cn0 - x2.x * sn0, x1.y * cn1 - x2.y * sn1);
        split_w2(knh + base + dd + 32, knl + base + dd + 32,
                 x2.x * cn0 + x1.x * sn0, x2.y * cn1 + x1.y * sn1);
    }
    // V: fp16 hi/lo split, 2 elems per unit (KVDIM/2 = 256 units)
    for (int e = tid; e < KVDIM / 2; e += 256) {
        size_t base = (size_t)s * KVDIM + e * 2;
        float2 v = *(const float2*)&V[base];
        __half h0 = __float2half_rn(v.x), h1 = __float2half_rn(v.y);
        *(__half2*)(vh + base) = __half2(h0, h1);
        *(__half2*)(vl + base) = __half2(__float2half_rn(v.x - __half2float(h0)),
                                         __float2half_rn(v.y - __half2float(h1)));
    }
}

// ---------------- Tensor-core flash attention (fp16 2-pass PV) -------------
template<bool DUAL>
__device__ __forceinline__ void fa_load_stage(
    uint32_t sb, int kt, int kvh, int tid,
    const bf16* __restrict__ Kbh, const bf16* __restrict__ Kbl,
    const bf16* __restrict__ Knh, const bf16* __restrict__ Knl,
    const __half* __restrict__ Vh, const __half* __restrict__ Vl)
{
#pragma unroll
    for (int i = 0; i < 4; i++) {
        int u = i * 128 + tid;      // 0..511
        int r = u >> 3, c = u & 7;
        uint32_t so = (uint32_t)(r * 128 + ((c ^ (r & 7)) << 4));
        size_t go = (size_t)(kt * 64 + r) * KVDIM + kvh * 64 + c * 8;
        cp16(sb +         so, Kbh + go);
        cp16(sb + 8192  + so, Kbl + go);
        cp16(sb + 16384 + so, Vh + go);
        cp16(sb + 24576 + so, Vl + go);
        if (DUAL) {
            cp16(sb + 32768 + so, Knh + go);
            cp16(sb + 40960 + so, Knl + go);
        }
    }
}

__device__ __forceinline__ void fa_compute_S(
    float s[8][4], uint32_t sKh, uint32_t sKl,
    const uint32_t qfh[4][4], const uint32_t qfl[4][4], int lane)
{
#pragma unroll
    for (int kk = 0; kk < 4; kk++) {
        uint32_t kh[8][2], kl[8][2];
        int rB0 = (lane & 7) + ((lane >> 4) << 3);
        int ccB = kk * 2 + ((lane >> 3) & 1);
#pragma unroll
        for (int nb = 0; nb < 4; nb++) {
            int r = nb * 16 + rB0;
            uint32_t so = (uint32_t)(r * 128 + ((ccB ^ (r & 7)) << 4));
            ldsm_x4(sKh + so, kh[nb*2][0], kh[nb*2][1], kh[nb*2+1][0], kh[nb*2+1][1]);
            ldsm_x4(sKl + so, kl[nb*2][0], kl[nb*2][1], kl[nb*2+1][0], kl[nb*2+1][1]);
        }
#pragma unroll
        for (int nf = 0; nf < 8; nf++) {
            mma16816(s[nf], qfh[kk], kh[nf]);
            mma16816(s[nf], qfl[kk], kh[nf]);
            mma16816(s[nf], qfh[kk], kl[nf]);
        }
    }
}

template<bool DUAL>
__global__ __launch_bounds__(128, DUAL ? 1 : 2)
void flash_mma(const bf16* __restrict__ Qh, const bf16* __restrict__ Ql,
               const bf16* __restrict__ Kbh, const bf16* __restrict__ Kbl,
               const bf16* __restrict__ Knh, const bf16* __restrict__ Knl,
               const __half* __restrict__ Vh,  const __half* __restrict__ Vl,
               float* __restrict__ attnOut)
{
    constexpr int STAGE = DUAL ? 49152 : 32768;
    extern __shared__ char dyn[];
    const uint32_t sQ = smem_u32(dyn);           // Qh 8K | Ql 8K | stage0 | stage1

    const int tid = threadIdx.x, lane = tid & 31, w = tid >> 5;
    const int qt = DUAL ? (S/64 - 1) : (S/64 - 2 - (int)blockIdx.x);   // heavy first
    const int h = blockIdx.y, kvh = h >> 2;

    {
        const bf16* gQh = Qh + (size_t)(qt * 64) * HID + h * 64;
        const bf16* gQl = Ql + (size_t)(qt * 64) * HID + h * 64;
#pragma unroll
        for (int i = 0; i < 4; i++) {
            int u = i * 128 + tid;
            int r = u >> 3, c = u & 7;
            uint32_t so = (uint32_t)(r * 128 + ((c ^ (r & 7)) << 4));
            cp16(sQ +        so, gQh + (size_t)r * HID + c * 8);
            cp16(sQ + 8192 + so, gQl + (size_t)r * HID + c * 8);
        }
    }
    fa_load_stage<DUAL>(sQ + 16384, 0, kvh, tid, Kbh, Kbl, Knh, Knl, Vh, Vl);
    CP_COMMIT();
    if (qt >= 1)
        fa_load_stage<DUAL>(sQ + 16384 + STAGE, 1, kvh, tid, Kbh, Kbl, Knh, Knl, Vh, Vl);
    CP_COMMIT();

    CP_WAIT1();
    __syncthreads();

    uint32_t qfh[4][4], qfl[4][4];
    {
        int rA = w * 16 + (lane & 15);
#pragma unroll
        for (int kk = 0; kk < 4; kk++) {
            int cc = kk * 2 + (lane >> 4);
            uint32_t so = (uint32_t)(rA * 128 + ((cc ^ (rA & 7)) << 4));
            ldsm_x4(sQ + so,        qfh[kk][0], qfh[kk][1], qfh[kk][2], qfh[kk][3]);
            ldsm_x4(sQ + 8192 + so, qfl[kk][0], qfl[kk][1], qfl[kk][2], qfl[kk][3]);
        }
    }

    float o[8][4];
#pragma unroll
    for (int nf = 0; nf < 8; nf++)
#pragma unroll
        for (int j = 0; j < 4; j++) o[nf][j] = 0.0f;
    float m0 = -1e30f, m1 = -1e30f, l0 = 0.0f, l1 = 0.0f;

    const int rg0 = qt * 64 + w * 16 + (lane >> 2);
    const int rg1 = rg0 + 8;

    for (int kt = 0; kt <= qt; kt++) {
        if (kt) { CP_WAIT1(); __syncthreads(); }
        const uint32_t sb = sQ + 16384 + (kt & 1) * STAGE;

        float s[8][4];
#pragma unroll
        for (int nf = 0; nf < 8; nf++)
#pragma unroll
            for (int j = 0; j < 4; j++) s[nf][j] = 0.0f;
        fa_compute_S(s, sb, sb + 8192, qfh, qfl, lane);

        if (DUAL) {
            float sn[8][4];
#pragma unroll
            for (int nf = 0; nf < 8; nf++)
#pragma unroll
                for (int j = 0; j < 4; j++) sn[nf][j] = 0.0f;
            fa_compute_S(sn, sb + 32768, sb + 40960, qfh, qfl, lane);
            if (rg0 >= CTX) {
#pragma unroll
                for (int nf = 0; nf < 8; nf++) { s[nf][0] = sn[nf][0]; s[nf][1] = sn[nf][1]; }
            }
            if (rg1 >= CTX) {
#pragma unroll
                for (int nf = 0; nf < 8; nf++) { s[nf][2] = sn[nf][2]; s[nf][3] = sn[nf][3]; }
            }
        }

        if (kt == qt) {
#pragma unroll
            for (int nf = 0; nf < 8; nf++) {
                int c0 = kt * 64 + nf * 8 + (lane & 3) * 2;
                if (c0     > rg0) s[nf][0] = -1e30f;
                if (c0 + 1 > rg0) s[nf][1] = -1e30f;
                if (c0     > rg1) s[nf][2] = -1e30f;
                if (c0 + 1 > rg1) s[nf][3] = -1e30f;
            }
        }

        float mr0 = -1e30f, mr1 = -1e30f;
#pragma unroll
        for (int nf = 0; nf < 8; nf++) {
            mr0 = fmaxf(mr0, fmaxf(s[nf][0], s[nf][1]));
            mr1 = fmaxf(mr1, fmaxf(s[nf][2], s[nf][3]));
        }
        mr0 = fmaxf(mr0, __shfl_xor_sync(0xffffffffu, mr0, 1));
        mr0 = fmaxf(mr0, __shfl_xor_sync(0xffffffffu, mr0, 2));
        mr1 = fmaxf(mr1, __shfl_xor_sync(0xffffffffu, mr1, 1));
        mr1 = fmaxf(mr1, __shfl_xor_sync(0xffffffffu, mr1, 2));

        float mn0 = fmaxf(m0, mr0), mn1 = fmaxf(m1, mr1);
        float sc0 = exp2f(m0 - mn0), sc1 = exp2f(m1 - mn1);
        m0 = mn0; m1 = mn1;
        l0 *= sc0; l1 *= sc1;
#pragma unroll
        for (int nf = 0; nf < 8; nf++) {
            o[nf][0] *= sc0; o[nf][1] *= sc0;
            o[nf][2] *= sc1; o[nf][3] *= sc1;
        }

        // P in fp16 (2-pass PV)
        uint32_t pF[4][4];
        float sum0 = 0.0f, sum1 = 0.0f;
#pragma unroll
        for (int nf = 0; nf < 8; nf++) {
            float p0 = exp2f(s[nf][0] - m0), p1 = exp2f(s[nf][1] - m0);
            float p2 = exp2f(s[nf][2] - m1), p3 = exp2f(s[nf][3] - m1);
            sum0 += p0 + p1; sum1 += p2 + p3;
            int kk = nf >> 1;
            int off = (nf & 1) * 2;
            pF[kk][off + 0] = pack_f16x2(p0, p1);
            pF[kk][off + 1] = pack_f16x2(p2, p3);
        }
        sum0 += __shfl_xor_sync(0xffffffffu, sum0, 1);
        sum0 += __shfl_xor_sync(0xffffffffu, sum0, 2);
        sum1 += __shfl_xor_sync(0xffffffffu, sum1, 1);
        sum1 += __shfl_xor_sync(0xffffffffu, sum1, 2);
        l0 += sum0; l1 += sum1;

        // O += P V (fp16, 2 passes: P·Vh + P·Vl)
        const uint32_t sVh = sb + 16384, sVl = sb + 24576;
#pragma unroll
        for (int kk = 0; kk < 4; kk++) {
            uint32_t vh[8][2], vl[8][2];
            int key0 = kk * 16 + (lane & 7) + ((lane >> 3) & 1) * 8;
#pragma unroll
            for (int nb = 0; nb < 4; nb++) {
                int chunk = nb * 2 + (lane >> 4);
                uint32_t so = (uint32_t)(key0 * 128 + ((chunk ^ (key0 & 7)) << 4));
                ldsm_x4t(sVh + so, vh[nb*2][0], vh[nb*2][1], vh[nb*2+1][0], vh[nb*2+1][1]);
                ldsm_x4t(sVl + so, vl[nb*2][0], vl[nb*2][1], vl[nb*2+1][0], vl[nb*2+1][1]);
            }
#pragma unroll
            for (int nf = 0; nf < 8; nf++) {
                mma16816h(o[nf], pF[kk], vh[nf]);
                mma16816h(o[nf], pF[kk], vl[nf]);
            }
        }

        __syncthreads();
        if (kt + 2 <= qt)
            fa_load_stage<DUAL>(sQ + 16384 + (kt & 1) * STAGE, kt + 2, kvh, tid,
                                Kbh, Kbl, Knh, Knl, Vh, Vl);
        CP_COMMIT();
    }

    float inv0 = 1.0f / l0, inv1 = 1.0f / l1;
#pragma unroll
    for (int nf = 0; nf < 8; nf++) {
        int col = h * 64 + nf * 8 + (lane & 3) * 2;
        *(float2*)&attnOut[(size_t)rg0 * HID + col] = make_float2(o[nf][0]*inv0, o[nf][1]*inv0);
        *(float2*)&attnOut[(size_t)rg1 * HID + col] = make_float2(o[nf][2]*inv1, o[nf][3]*inv1);
    }
}

// ---------------- launch ----------------
extern "C" void kernel_launch(void* const* d_in, const int* in_sizes, int n_in,
                              void* d_out, int out_size)
{
    const float* hidden = (const float*)d_in[0];
    const float* Wq = (const float*)d_in[3];
    const float* Wk = (const float*)d_in[4];
    const float* Wv = (const float*)d_in[5];
    const float* Wo = (const float*)d_in[6];
    float* out = (float*)d_out;

    float *qB, *kB, *vB, *atB;
    cudaGetSymbolAddress((void**)&qB,  g_Q);
    cudaGetSymbolAddress((void**)&kB,  g_K);
    cudaGetSymbolAddress((void**)&vB,  g_V);
    cudaGetSymbolAddress((void**)&atB, g_attn);

    bf16 *hH,*hL,*WqH,*WqL,*WkH,*WkL,*WvH,*WvL;
    cudaGetSymbolAddress((void**)&hH,  g_hH);  cudaGetSymbolAddress((void**)&hL,  g_hL);
    cudaGetSymbolAddress((void**)&WqH, g_WqH); cudaGetSymbolAddress((void**)&WqL, g_WqL);
    cudaGetSymbolAddress((void**)&WkH, g_WkH); cudaGetSymbolAddress((void**)&WkL, g_WkL);
    cudaGetSymbolAddress((void**)&WvH, g_WvH); cudaGetSymbolAddress((void**)&WvL, g_WvL);

    __half *WoF, *aHf, *aLf;
    cudaGetSymbolAddress((void**)&WoF, g_WoF);
    cudaGetSymbolAddress((void**)&aHf, g_aHf);
    cudaGetSymbolAddress((void**)&aLf, g_aLf);

    bf16 *Qh,*Ql,*bKh,*bKl,*nKh,*nKl;
    __half *Vh,*Vl;
    cudaGetSymbolAddress((void**)&Qh,  g_Qh);  cudaGetSymbolAddress((void**)&Ql,  g_Ql);
    cudaGetSymbolAddress((void**)&bKh, g_bKh); cudaGetSymbolAddress((void**)&bKl, g_bKl);
    cudaGetSymbolAddress((void**)&nKh, g_nKh); cudaGetSymbolAddress((void**)&nKl, g_nKl);
    cudaGetSymbolAddress((void**)&Vh,  g_Vh);  cudaGetSymbolAddress((void**)&Vl,  g_Vl);

    cudaFuncSetAttribute(qkv_gemm, cudaFuncAttributeMaxDynamicSharedMemorySize, SM_TOTAL);
    cudaFuncSetAttribute(wo_gemm2, cudaFuncAttributeMaxDynamicSharedMemorySize, SM_TOTAL2);
    const int FA_SMEM_N = 16384 + 2*32768;   // 81920
    const int FA_SMEM_D = 16384 + 2*49152;   // 114688
    cudaFuncSetAttribute(flash_mma<false>, cudaFuncAttributeMaxDynamicSharedMemorySize, FA_SMEM_N);
    cudaFuncSetAttribute(flash_mma<true>,  cudaFuncAttributeMaxDynamicSharedMemorySize, FA_SMEM_D);

    // input splits: hidden/Wq/Wk/Wv -> bf16 h/l (one launch); Wo -> fp16
    const int TOT4 = 1048576*2 + 262144*2;   // float4 units
    split_all_kernel<<<(TOT4/4 + 255)/256, 256>>>(hidden, Wq, Wk, Wv,
                                                  hH, hL, WqH, WqL, WkH, WkL, WvH, WvL);
    wo_half_kernel<<<(1048576/4 + 255)/256, 256>>>(Wo, WoF);

    qkv_gemm<<<dim3(24, 16), 256, SM_TOTAL>>>(hH, hL, WqH, WqL, WkH, WkL, WvH, WvL,
                                              qB, kB, vB);

    rope_split_kernel<<<S, 256>>>(qB, kB, vB, Qh, Ql, bKh, bKl, nKh, nKl, Vh, Vl);

    // boundary tile (rows 1984..2047, contains CTX) — dual-variant kernel
    flash_mma<true><<<dim3(1, NH), 128, FA_SMEM_D>>>(Qh, Ql, bKh, bKl, nKh, nKl, Vh, Vl, atB);
    // remaining tiles, heavy first
    flash_mma<false><<<dim3(S/64 - 1, NH), 128, FA_SMEM_N>>>(Qh, Ql, bKh, bKl, nKh, nKl, Vh, Vl, atB);

    // attn -> fp16 hi/lo, then 2-pass fp16 Wo GEMM into d_out
    split4h_kernel<<<(1048576/4 + 255)/256, 256>>>(atB, aHf, aLf);
    wo_gemm2<<<dim3(16, 16), 256, SM_TOTAL2>>>(aHf, aLf, WoF, out);
}

// round 12
// speedup vs baseline: 1.3140x; 1.0365x over previous
#include <cuda_runtime.h>
#include <cuda_bf16.h>
#include <cuda_fp16.h>
#include <cstdint>

#define S     2048
#define HID   2048
#define NH    32
#define NKV   8
#define HD    64
#define KVDIM (NKV*HD)   // 512
#define CTX   (S-10)     // 2038: rows >= CTX use narrow rope

typedef unsigned long long ull;
typedef __nv_bfloat16 bf16;

__device__ __forceinline__ uint32_t smem_u32(const void* p) {
    uint32_t a;
    asm("{ .reg .u64 t; cvta.to.shared.u64 t, %1; cvt.u32.u64 %0, t; }" : "=r"(a) : "l"(p));
    return a;
}

// ---------------- mma.sync primitives (compute_103-safe) ----------------
__device__ __forceinline__ void cp16(uint32_t s, const void* g) {
    asm volatile("cp.async.cg.shared.global [%0], [%1], 16;" :: "r"(s), "l"(g));
}
#define CP_COMMIT() asm volatile("cp.async.commit_group;" ::: "memory")
#define CP_WAIT1()  asm volatile("cp.async.wait_group 1;" ::: "memory")

__device__ __forceinline__ void ldsm_x4(uint32_t addr, uint32_t& r0, uint32_t& r1,
                                        uint32_t& r2, uint32_t& r3) {
    asm volatile("ldmatrix.sync.aligned.m8n8.x4.shared.b16 {%0,%1,%2,%3}, [%4];"
                 : "=r"(r0), "=r"(r1), "=r"(r2), "=r"(r3) : "r"(addr));
}
__device__ __forceinline__ void ldsm_x4t(uint32_t addr, uint32_t& r0, uint32_t& r1,
                                         uint32_t& r2, uint32_t& r3) {
    asm volatile("ldmatrix.sync.aligned.m8n8.x4.trans.shared.b16 {%0,%1,%2,%3}, [%4];"
                 : "=r"(r0), "=r"(r1), "=r"(r2), "=r"(r3) : "r"(addr));
}
__device__ __forceinline__ void mma16816(float* c, const uint32_t* a, const uint32_t* b) {
    asm volatile(
        "mma.sync.aligned.m16n8k16.row.col.f32.bf16.bf16.f32 "
        "{%0,%1,%2,%3}, {%4,%5,%6,%7}, {%8,%9}, {%0,%1,%2,%3};"
        : "+f"(c[0]), "+f"(c[1]), "+f"(c[2]), "+f"(c[3])
        : "r"(a[0]), "r"(a[1]), "r"(a[2]), "r"(a[3]), "r"(b[0]), "r"(b[1]));
}
__device__ __forceinline__ void mma16816h(float* c, const uint32_t* a, const uint32_t* b) {
    asm volatile(
        "mma.sync.aligned.m16n8k16.row.col.f32.f16.f16.f32 "
        "{%0,%1,%2,%3}, {%4,%5,%6,%7}, {%8,%9}, {%0,%1,%2,%3};"
        : "+f"(c[0]), "+f"(c[1]), "+f"(c[2]), "+f"(c[3])
        : "r"(a[0]), "r"(a[1]), "r"(a[2]), "r"(a[3]), "r"(b[0]), "r"(b[1]));
}
__device__ __forceinline__ uint32_t pack_bf16x2(float lo, float hi) {
    uint32_t r; asm("cvt.rn.bf16x2.f32 %0, %1, %2;" : "=r"(r) : "f"(hi), "f"(lo));
    return r;
}
__device__ __forceinline__ uint32_t pack_f16x2(float lo, float hi) {
    uint32_t r; asm("cvt.rn.f16x2.f32 %0, %1, %2;" : "=r"(r) : "f"(hi), "f"(lo));
    return r;
}

// ---------------- scratch (static device globals; no allocs) ----------------
__device__ float g_Q   [S*HID];
__device__ float g_K   [S*KVDIM];
__device__ float g_V   [S*KVDIM];
__device__ bf16 g_hH[S*HID],     g_hL[S*HID];
__device__ bf16 g_WqH[HID*HID],  g_WqL[HID*HID];
__device__ bf16 g_WkH[KVDIM*HID],g_WkL[KVDIM*HID];
__device__ bf16 g_WvH[KVDIM*HID],g_WvL[KVDIM*HID];
__device__ __half g_WoF[HID*HID];                  // Wo in fp16 (hi only)
__device__ __half g_aHf[S*HID],  g_aLf[S*HID];     // attn out fp16 hi/lo
__device__ bf16 g_Qh[S*HID],    g_Ql[S*HID];
__device__ bf16 g_bKh[S*KVDIM], g_bKl[S*KVDIM];
__device__ bf16 g_nKh[S*KVDIM], g_nKl[S*KVDIM];
__device__ __half g_Vh[S*KVDIM], g_Vl[S*KVDIM];    // fp16 split of V

// ---------------- fp32 -> bf16 hi/lo split ----------------
__device__ __forceinline__ void split_body(const float* __restrict__ x,
                                           bf16* __restrict__ hi, bf16* __restrict__ lo,
                                           int i)
{
    float4 v = ((const float4*)x)[i];
    bf16 h0 = __float2bfloat16(v.x);
    bf16 h1 = __float2bfloat16(v.y);
    bf16 h2 = __float2bfloat16(v.z);
    bf16 h3 = __float2bfloat16(v.w);
    __nv_bfloat162 H0 = __nv_bfloat162(h0, h1), H1 = __nv_bfloat162(h2, h3);
    __nv_bfloat162 L0 = __nv_bfloat162(__float2bfloat16(v.x - __bfloat162float(h0)),
                                       __float2bfloat16(v.y - __bfloat162float(h1)));
    __nv_bfloat162 L1 = __nv_bfloat162(__float2bfloat16(v.z - __bfloat162float(h2)),
                                       __float2bfloat16(v.w - __bfloat162float(h3)));
    ((__nv_bfloat162*)hi)[i*2+0] = H0; ((__nv_bfloat162*)hi)[i*2+1] = H1;
    ((__nv_bfloat162*)lo)[i*2+0] = L0; ((__nv_bfloat162*)lo)[i*2+1] = L1;
}

// merged split of hidden/Wq/Wk/Wv (bf16 hi/lo) + Wo (fp16 hi), 4 float4/thread.
// float4 regions: hidden 1048576 | Wq 1048576 | Wk 262144 | Wv 262144 | Wo 1048576
__global__ __launch_bounds__(256)
void split_all_kernel(const float* __restrict__ hid, const float* __restrict__ Wq,
                      const float* __restrict__ Wk,  const float* __restrict__ Wv,
                      const float* __restrict__ Wo,
                      bf16* __restrict__ hH, bf16* __restrict__ hL,
                      bf16* __restrict__ qH, bf16* __restrict__ qL,
                      bf16* __restrict__ kH, bf16* __restrict__ kL,
                      bf16* __restrict__ vH, bf16* __restrict__ vL,
                      __half* __restrict__ oF)
{
    int g0 = (blockIdx.x * 256 + threadIdx.x) * 4;   // region bounds all %4==0
    const int R0 = 1048576, R1 = R0 + 1048576, R2 = R1 + 262144, R3 = R2 + 262144;
    const int TOT = R3 + 1048576;
    if (g0 >= TOT) return;
    if (g0 >= R3) {
        // Wo -> fp16 hi only
#pragma unroll
        for (int k = 0; k < 4; k++) {
            int i = g0 - R3 + k;
            float4 v = ((const float4*)Wo)[i];
            ((__half2*)oF)[i*2+0] = __half2(__float2half_rn(v.x), __float2half_rn(v.y));
            ((__half2*)oF)[i*2+1] = __half2(__float2half_rn(v.z), __float2half_rn(v.w));
        }
        return;
    }
    const float* src; bf16 *dh, *dl; int rb;
    if (g0 < R0)      { src = hid; dh = hH; dl = hL; rb = 0;  }
    else if (g0 < R1) { src = Wq;  dh = qH; dl = qL; rb = R0; }
    else if (g0 < R2) { src = Wk;  dh = kH; dl = kL; rb = R1; }
    else              { src = Wv;  dh = vH; dl = vL; rb = R2; }
#pragma unroll
    for (int k = 0; k < 4; k++) split_body(src, dh, dl, g0 - rb + k);
}

// ---------------- mma.sync split-bf16 GEMM core (3-pass, unchanged) ----
#define STG      16384
#define SM_STAGE (4*STG)          // 64 KB
#define SM_TOTAL (2*SM_STAGE)     // 128 KB

__device__ __forceinline__ void g_load_stage(
    uint32_t sbuf,
    const bf16* __restrict__ Ah, const bf16* __restrict__ Al,
    const bf16* __restrict__ Bh, const bf16* __restrict__ Bl,
    int mBase, int nBase, int Kdim, int k0, int tid)
{
#pragma unroll
    for (int i = 0; i < 4; i++) {
        int u = i * 256 + tid;
        int r = u >> 3, c = u & 7;
        uint32_t so = (uint32_t)(r * 128 + ((c ^ (r & 7)) << 4));
        size_t eoffA = (size_t)(mBase + r) * Kdim + k0 + c * 8;
        size_t eoffB = (size_t)(nBase + r) * Kdim + k0 + c * 8;
        cp16(sbuf +          so, Ah + eoffA);
        cp16(sbuf +   STG  + so, Al + eoffA);
        cp16(sbuf + 2*STG  + so, Bh + eoffB);
        cp16(sbuf + 3*STG  + so, Bl + eoffB);
    }
}

__device__ __forceinline__ void gemm_body(
    const bf16* __restrict__ Ah, const bf16* __restrict__ Al,
    const bf16* __restrict__ Bh, const bf16* __restrict__ Bl,
    float* __restrict__ C, int Ntot, int Kdim, int mBase, int nBase, uint32_t sb)
{
    const int tid  = threadIdx.x;
    const int lane = tid & 31;
    const int wid  = tid >> 5;
    const int wm   = wid & 1;
    const int wn   = wid >> 1;

    float acc[4][4][4];
#pragma unroll
    for (int i = 0; i < 4; i++)
#pragma unroll
        for (int j = 0; j < 4; j++)
#pragma unroll
            for (int k = 0; k < 4; k++) acc[i][j][k] = 0.0f;

    const int NC = Kdim >> 6;

    g_load_stage(sb,            Ah, Al, Bh, Bl, mBase, nBase, Kdim, 0,  tid);
    CP_COMMIT();
    g_load_stage(sb + SM_STAGE, Ah, Al, Bh, Bl, mBase, nBase, Kdim, 64, tid);
    CP_COMMIT();

    const int aRow = wm * 64;
    const int bRow = wn * 32;

    for (int c = 0; c < NC; c++) {
        CP_WAIT1();
        __syncthreads();
        const uint32_t sbuf = sb + (c & 1) * SM_STAGE;
        const uint32_t sAh = sbuf, sAl = sbuf + STG, sBh = sbuf + 2*STG, sBl = sbuf + 3*STG;

#pragma unroll
        for (int ks = 0; ks < 4; ks++) {
            uint32_t aH[4][4], aL[4][4], bH[4][2], bL[4][2];
            {
                int rA = aRow + (lane & 15);
                int ccA = ks * 2 + (lane >> 4);
#pragma unroll
                for (int mf = 0; mf < 4; mf++) {
                    int r = rA + mf * 16;
                    uint32_t so = (uint32_t)(r * 128 + ((ccA ^ (r & 7)) << 4));
                    ldsm_x4(sAh + so, aH[mf][0], aH[mf][1], aH[mf][2], aH[mf][3]);
                    ldsm_x4(sAl + so, aL[mf][0], aL[mf][1], aL[mf][2], aL[mf][3]);
                }
            }
            {
                int rB0 = bRow + (lane & 7) + ((lane >> 4) << 3);
                int ccB = ks * 2 + ((lane >> 3) & 1);
#pragma unroll
                for (int nf2 = 0; nf2 < 2; nf2++) {
                    int r = rB0 + nf2 * 16;
                    uint32_t so = (uint32_t)(r * 128 + ((ccB ^ (r & 7)) << 4));
                    ldsm_x4(sBh + so, bH[nf2*2][0], bH[nf2*2][1], bH[nf2*2+1][0], bH[nf2*2+1][1]);
                    ldsm_x4(sBl + so, bL[nf2*2][0], bL[nf2*2][1], bL[nf2*2+1][0], bL[nf2*2+1][1]);
                }
            }
#pragma unroll
            for (int mf = 0; mf < 4; mf++)
#pragma unroll
                for (int nf = 0; nf < 4; nf++) {
                    mma16816(acc[mf][nf], aH[mf], bH[nf]);
                    mma16816(acc[mf][nf], aL[mf], bH[nf]);
                    mma16816(acc[mf][nf], aH[mf], bL[nf]);
                }
        }
        __syncthreads();
        if (c + 2 < NC)
            g_load_stage(sb + (c & 1) * SM_STAGE, Ah, Al, Bh, Bl,
                         mBase, nBase, Kdim, (c + 2) * 64, tid);
        CP_COMMIT();
    }

#pragma unroll
    for (int mf = 0; mf < 4; mf++) {
        int row0 = mBase + wm * 64 + mf * 16 + (lane >> 2);
#pragma unroll
        for (int nf = 0; nf < 4; nf++) {
            int col = nBase + wn * 32 + nf * 8 + (lane & 3) * 2;
            *(float2*)&C[(size_t)row0 * Ntot + col]       = make_float2(acc[mf][nf][0], acc[mf][nf][1]);
            *(float2*)&C[(size_t)(row0 + 8) * Ntot + col] = make_float2(acc[mf][nf][2], acc[mf][nf][3]);
        }
    }
}

__global__ __launch_bounds__(256)
void qkv_gemm(const bf16* __restrict__ Ah, const bf16* __restrict__ Al,
              const bf16* __restrict__ WqH, const bf16* __restrict__ WqL,
              const bf16* __restrict__ WkH, const bf16* __restrict__ WkL,
              const bf16* __restrict__ WvH, const bf16* __restrict__ WvL,
              float* __restrict__ Cq, float* __restrict__ Ck, float* __restrict__ Cv)
{
    extern __shared__ char dyns[];
    uint32_t sb = smem_u32(dyns);
    int bx = blockIdx.x, mBase = blockIdx.y * 128;
    if (bx < 16)      gemm_body(Ah, Al, WqH, WqL, Cq, HID,   HID, mBase, bx*128,      sb);
    else if (bx < 20) gemm_body(Ah, Al, WkH, WkL, Ck, KVDIM, HID, mBase, (bx-16)*128, sb);
    else              gemm_body(Ah, Al, WvH, WvL, Cv, KVDIM, HID, mBase, (bx-20)*128, sb);
}

// ---------------- 2-pass fp16 GEMM for Wo: C = (Ah+Al) @ Bh^T ----------
#define STG2      16384
#define SM_STAGE2 (3*STG2)        // 48 KB
#define SM_TOTAL2 (2*SM_STAGE2)   // 96 KB -> 2 CTAs/SM

__device__ __forceinline__ void g_load_stage2(
    uint32_t sbuf,
    const __half* __restrict__ Ah, const __half* __restrict__ Al,
    const __half* __restrict__ Bh,
    int mBase, int nBase, int Kdim, int k0, int tid)
{
#pragma unroll
    for (int i = 0; i < 4; i++) {
        int u = i * 256 + tid;
        int r = u >> 3, c = u & 7;
        uint32_t so = (uint32_t)(r * 128 + ((c ^ (r & 7)) << 4));
        size_t eoffA = (size_t)(mBase + r) * Kdim + k0 + c * 8;
        size_t eoffB = (size_t)(nBase + r) * Kdim + k0 + c * 8;
        cp16(sbuf +          so, Ah + eoffA);
        cp16(sbuf +   STG2 + so, Al + eoffA);
        cp16(sbuf + 2*STG2 + so, Bh + eoffB);
    }
}

__global__ __launch_bounds__(256, 2)
void wo_gemm2(const __half* __restrict__ Ah, const __half* __restrict__ Al,
              const __half* __restrict__ Bh, float* __restrict__ C)
{
    extern __shared__ char dyns[];
    const uint32_t sb = smem_u32(dyns);
    const int tid  = threadIdx.x;
    const int lane = tid & 31;
    const int wid  = tid >> 5;
    const int wm   = wid & 1;
    const int wn   = wid >> 1;
    const int mBase = blockIdx.y * 128, nBase = blockIdx.x * 128;

    float acc[4][4][4];
#pragma unroll
    for (int i = 0; i < 4; i++)
#pragma unroll
        for (int j = 0; j < 4; j++)
#pragma unroll
            for (int k = 0; k < 4; k++) acc[i][j][k] = 0.0f;

    const int NC = HID >> 6;   // 32

    g_load_stage2(sb,             Ah, Al, Bh, mBase, nBase, HID, 0,  tid);
    CP_COMMIT();
    g_load_stage2(sb + SM_STAGE2, Ah, Al, Bh, mBase, nBase, HID, 64, tid);
    CP_COMMIT();

    const int aRow = wm * 64;
    const int bRow = wn * 32;

    for (int c = 0; c < NC; c++) {
        CP_WAIT1();
        __syncthreads();
        const uint32_t sbuf = sb + (c & 1) * SM_STAGE2;
        const uint32_t sAh = sbuf, sAl = sbuf + STG2, sBh = sbuf + 2*STG2;

#pragma unroll
        for (int ks = 0; ks < 4; ks++) {
            uint32_t aH[4][4], aL[4][4], bH[4][2];
            {
                int rA = aRow + (lane & 15);
                int ccA = ks * 2 + (lane >> 4);
#pragma unroll
                for (int mf = 0; mf < 4; mf++) {
                    int r = rA + mf * 16;
                    uint32_t so = (uint32_t)(r * 128 + ((ccA ^ (r & 7)) << 4));
                    ldsm_x4(sAh + so, aH[mf][0], aH[mf][1], aH[mf][2], aH[mf][3]);
                    ldsm_x4(sAl + so, aL[mf][0], aL[mf][1], aL[mf][2], aL[mf][3]);
                }
            }
            {
                int rB0 = bRow + (lane & 7) + ((lane >> 4) << 3);
                int ccB = ks * 2 + ((lane >> 3) & 1);
#pragma unroll
                for (int nf2 = 0; nf2 < 2; nf2++) {
                    int r = rB0 + nf2 * 16;
                    uint32_t so = (uint32_t)(r * 128 + ((ccB ^ (r & 7)) << 4));
                    ldsm_x4(sBh + so, bH[nf2*2][0], bH[nf2*2][1], bH[nf2*2+1][0], bH[nf2*2+1][1]);
                }
            }
#pragma unroll
            for (int mf = 0; mf < 4; mf++)
#pragma unroll
                for (int nf = 0; nf < 4; nf++) {
                    mma16816h(acc[mf][nf], aH[mf], bH[nf]);
                    mma16816h(acc[mf][nf], aL[mf], bH[nf]);
                }
        }
        __syncthreads();
        if (c + 2 < NC)
            g_load_stage2(sb + (c & 1) * SM_STAGE2, Ah, Al, Bh,
                          mBase, nBase, HID, (c + 2) * 64, tid);
        CP_COMMIT();
    }

#pragma unroll
    for (int mf = 0; mf < 4; mf++) {
        int row0 = mBase + wm * 64 + mf * 16 + (lane >> 2);
#pragma unroll
        for (int nf = 0; nf < 4; nf++) {
            int col = nBase + wn * 32 + nf * 8 + (lane & 3) * 2;
            *(float2*)&C[(size_t)row0 * HID + col]       = make_float2(acc[mf][nf][0], acc[mf][nf][1]);
            *(float2*)&C[(size_t)(row0 + 8) * HID + col] = make_float2(acc[mf][nf][2], acc[mf][nf][3]);
        }
    }
}

// ---------------- RoPE + split (float4-vectorized) --------------------------
__device__ __forceinline__ void split_w2(bf16* hp, bf16* lp, float x0, float x1) {
    bf16 h0 = __float2bfloat16(x0);
    bf16 h1 = __float2bfloat16(x1);
    *(__nv_bfloat162*)hp = __nv_bfloat162(h0, h1);
    *(__nv_bfloat162*)lp = __nv_bfloat162(__float2bfloat16(x0 - __bfloat162float(h0)),
                                          __float2bfloat16(x1 - __bfloat162float(h1)));
}

__global__ void rope_split_kernel(const float* __restrict__ Q, const float* __restrict__ K,
                                  const float* __restrict__ V,
                                  bf16* __restrict__ qh, bf16* __restrict__ ql,
                                  bf16* __restrict__ kbh, bf16* __restrict__ kbl,
                                  bf16* __restrict__ knh, bf16* __restrict__ knl,
                                  __half* __restrict__ vh, __half* __restrict__ vl)
{
    const int s = blockIdx.x;
    const int tid = threadIdx.x; // 256
    const bool narrowRow = (s >= CTX);
    const float QS = 1.4426950408889634f * 0.125f;   // log2(e)/sqrt(64)

    __shared__ float cb[32], sb[32], cn[32], sn[32];
    if (tid < 32) {
        double inv = pow(10000.0, -(double)tid / 32.0);
        double ab = (double)s * inv;
        double an = ((double)s * 0.25) * inv;
        cb[tid] = (float)cos(ab); sb[tid] = (float)sin(ab);
        cn[tid] = (float)cos(an); sn[tid] = (float)sin(an);
    }
    __syncthreads();

    // Q: NH*8 = 256 units; each handles 4 dims [d4,d4+4) and [d4+32,d4+36)
    {
        int p = tid;                      // exactly one unit per thread
        int h = p >> 3, d4 = (p & 7) * 4;
        size_t base = (size_t)s * HID + h * HD;
        float4 x1 = *(const float4*)&Q[base + d4];
        float4 x2 = *(const float4*)&Q[base + d4 + 32];
        const float* cc = narrowRow ? cn : cb;
        const float* ss = narrowRow ? sn : sb;
        float c0 = cc[d4], c1 = cc[d4+1], c2 = cc[d4+2], c3 = cc[d4+3];
        float s0 = ss[d4], s1 = ss[d4+1], s2 = ss[d4+2], s3 = ss[d4+3];
        split_w2(qh + base + d4,     ql + base + d4,
                 (x1.x*c0 - x2.x*s0)*QS, (x1.y*c1 - x2.y*s1)*QS);
        split_w2(qh + base + d4 + 2, ql + base + d4 + 2,
                 (x1.z*c2 - x2.z*s2)*QS, (x1.w*c3 - x2.w*s3)*QS);
        split_w2(qh + base + d4 + 32, ql + base + d4 + 32,
                 (x2.x*c0 + x1.x*s0)*QS, (x2.y*c1 + x1.y*s1)*QS);
        split_w2(qh + base + d4 + 34, ql + base + d4 + 34,
                 (x2.z*c2 + x1.z*s2)*QS, (x2.w*c3 + x1.w*s3)*QS);
    }
    // K: NKV*8 = 64 units, both variants
    if (tid < NKV * 8) {
        int p = tid;
        int h = p >> 3, d4 = (p & 7) * 4;
        size_t base = (size_t)s * KVDIM + h * HD;
        float4 x1 = *(const float4*)&K[base + d4];
        float4 x2 = *(const float4*)&K[base + d4 + 32];
        float cb0 = cb[d4], cb1 = cb[d4+1], cb2 = cb[d4+2], cb3 = cb[d4+3];
        float sb0 = sb[d4], sb1 = sb[d4+1], sb2 = sb[d4+2], sb3 = sb[d4+3];
        float cn0 = cn[d4], cn1 = cn[d4+1], cn2 = cn[d4+2], cn3 = cn[d4+3];
        float sn0 = sn[d4], sn1 = sn[d4+1], sn2 = sn[d4+2], sn3 = sn[d4+3];
        split_w2(kbh + base + d4,     kbl + base + d4,
                 x1.x*cb0 - x2.x*sb0, x1.y*cb1 - x2.y*sb1);
        split_w2(kbh + base + d4 + 2, kbl + base + d4 + 2,
                 x1.z*cb2 - x2.z*sb2, x1.w*cb3 - x2.w*sb3);
        split_w2(kbh + base + d4 + 32, kbl + base + d4 + 32,
                 x2.x*cb0 + x1.x*sb0, x2.y*cb1 + x1.y*sb1);
        split_w2(kbh + base + d4 + 34, kbl + base + d4 + 34,
                 x2.z*cb2 + x1.z*sb2, x2.w*cb3 + x1.w*sb3);
        split_w2(knh + base + d4,     knl + base + d4,
                 x1.x*cn0 - x2.x*sn0, x1.y*cn1 - x2.y*sn1);
        split_w2(knh + base + d4 + 2, knl + base + d4 + 2,
                 x1.z*cn2 - x2.z*sn2, x1.w*cn3 - x2.w*sn3);
        split_w2(knh + base + d4 + 32, knl + base + d4 + 32,
                 x2.x*cn0 + x1.x*sn0, x2.y*cn1 + x1.y*sn1);
        split_w2(knh + base + d4 + 34, knl + base + d4 + 34,
                 x2.z*cn2 + x1.z*sn2, x2.w*cn3 + x1.w*sn3);
    }
    // V: fp16 hi/lo split, float4 per unit (KVDIM/4 = 128 units)
    if (tid < KVDIM / 4) {
        size_t base = (size_t)s * KVDIM + tid * 4;
        float4 v = *(const float4*)&V[base];
        __half h0 = __float2half_rn(v.x), h1 = __float2half_rn(v.y);
        __half h2 = __float2half_rn(v.z), h3 = __float2half_rn(v.w);
        *(__half2*)(vh + base)     = __half2(h0, h1);
        *(__half2*)(vh + base + 2) = __half2(h2, h3);
        *(__half2*)(vl + base)     = __half2(__float2half_rn(v.x - __half2float(h0)),
                                             __float2half_rn(v.y - __half2float(h1)));
        *(__half2*)(vl + base + 2) = __half2(__float2half_rn(v.z - __half2float(h2)),
                                             __float2half_rn(v.w - __half2float(h3)));
    }
}

// ---------------- Tensor-core flash attention (fp16 2-pass PV) -------------
// Epilogue writes attn output directly as fp16 hi/lo splits (for wo_gemm2).
template<bool DUAL>
__device__ __forceinline__ void fa_load_stage(
    uint32_t sb, int kt, int kvh, int tid,
    const bf16* __restrict__ Kbh, const bf16* __restrict__ Kbl,
    const bf16* __restrict__ Knh, const bf16* __restrict__ Knl,
    const __half* __restrict__ Vh, const __half* __restrict__ Vl)
{
#pragma unroll
    for (int i = 0; i < 4; i++) {
        int u = i * 128 + tid;      // 0..511
        int r = u >> 3, c = u & 7;
        uint32_t so = (uint32_t)(r * 128 + ((c ^ (r & 7)) << 4));
        size_t go = (size_t)(kt * 64 + r) * KVDIM + kvh * 64 + c * 8;
        cp16(sb +         so, Kbh + go);
        cp16(sb + 8192  + so, Kbl + go);
        cp16(sb + 16384 + so, Vh + go);
        cp16(sb + 24576 + so, Vl + go);
        if (DUAL) {
            cp16(sb + 32768 + so, Knh + go);
            cp16(sb + 40960 + so, Knl + go);
        }
    }
}

__device__ __forceinline__ void fa_compute_S(
    float s[8][4], uint32_t sKh, uint32_t sKl,
    const uint32_t qfh[4][4], const uint32_t qfl[4][4], int lane)
{
#pragma unroll
    for (int kk = 0; kk < 4; kk++) {
        uint32_t kh[8][2], kl[8][2];
        int rB0 = (lane & 7) + ((lane >> 4) << 3);
        int ccB = kk * 2 + ((lane >> 3) & 1);
#pragma unroll
        for (int nb = 0; nb < 4; nb++) {
            int r = nb * 16 + rB0;
            uint32_t so = (uint32_t)(r * 128 + ((ccB ^ (r & 7)) << 4));
            ldsm_x4(sKh + so, kh[nb*2][0], kh[nb*2][1], kh[nb*2+1][0], kh[nb*2+1][1]);
            ldsm_x4(sKl + so, kl[nb*2][0], kl[nb*2][1], kl[nb*2+1][0], kl[nb*2+1][1]);
        }
#pragma unroll
        for (int nf = 0; nf < 8; nf++) {
            mma16816(s[nf], qfh[kk], kh[nf]);
            mma16816(s[nf], qfl[kk], kh[nf]);
            mma16816(s[nf], qfh[kk], kl[nf]);
        }
    }
}

template<bool DUAL>
__global__ __launch_bounds__(128, DUAL ? 1 : 2)
void flash_mma(const bf16* __restrict__ Qh, const bf16* __restrict__ Ql,
               const bf16* __restrict__ Kbh, const bf16* __restrict__ Kbl,
               const bf16* __restrict__ Knh, const bf16* __restrict__ Knl,
               const __half* __restrict__ Vh,  const __half* __restrict__ Vl,
               __half* __restrict__ aHf, __half* __restrict__ aLf)
{
    constexpr int STAGE = DUAL ? 49152 : 32768;
    extern __shared__ char dyn[];
    const uint32_t sQ = smem_u32(dyn);           // Qh 8K | Ql 8K | stage0 | stage1

    const int tid = threadIdx.x, lane = tid & 31, w = tid >> 5;
    const int qt = DUAL ? (S/64 - 1) : (S/64 - 2 - (int)blockIdx.x);   // heavy first
    const int h = blockIdx.y, kvh = h >> 2;

    {
        const bf16* gQh = Qh + (size_t)(qt * 64) * HID + h * 64;
        const bf16* gQl = Ql + (size_t)(qt * 64) * HID + h * 64;
#pragma unroll
        for (int i = 0; i < 4; i++) {
            int u = i * 128 + tid;
            int r = u >> 3, c = u & 7;
            uint32_t so = (uint32_t)(r * 128 + ((c ^ (r & 7)) << 4));
            cp16(sQ +        so, gQh + (size_t)r * HID + c * 8);
            cp16(sQ + 8192 + so, gQl + (size_t)r * HID + c * 8);
        }
    }
    fa_load_stage<DUAL>(sQ + 16384, 0, kvh, tid, Kbh, Kbl, Knh, Knl, Vh, Vl);
    CP_COMMIT();
    if (qt >= 1)
        fa_load_stage<DUAL>(sQ + 16384 + STAGE, 1, kvh, tid, Kbh, Kbl, Knh, Knl, Vh, Vl);
    CP_COMMIT();

    CP_WAIT1();
    __syncthreads();

    uint32_t qfh[4][4], qfl[4][4];
    {
        int rA = w * 16 + (lane & 15);
#pragma unroll
        for (int kk = 0; kk < 4; kk++) {
            int cc = kk * 2 + (lane >> 4);
            uint32_t so = (uint32_t)(rA * 128 + ((cc ^ (rA & 7)) << 4));
            ldsm_x4(sQ + so,        qfh[kk][0], qfh[kk][1], qfh[kk][2], qfh[kk][3]);
            ldsm_x4(sQ + 8192 + so, qfl[kk][0], qfl[kk][1], qfl[kk][2], qfl[kk][3]);
        }
    }

    float o[8][4];
#pragma unroll
    for (int nf = 0; nf < 8; nf++)
#pragma unroll
        for (int j = 0; j < 4; j++) o[nf][j] = 0.0f;
    float m0 = -1e30f, m1 = -1e30f, l0 = 0.0f, l1 = 0.0f;

    const int rg0 = qt * 64 + w * 16 + (lane >> 2);
    const int rg1 = rg0 + 8;

    for (int kt = 0; kt <= qt; kt++) {
        if (kt) { CP_WAIT1(); __syncthreads(); }
        const uint32_t sb = sQ + 16384 + (kt & 1) * STAGE;

        float s[8][4];
#pragma unroll
        for (int nf = 0; nf < 8; nf++)
#pragma unroll
            for (int j = 0; j < 4; j++) s[nf][j] = 0.0f;
        fa_compute_S(s, sb, sb + 8192, qfh, qfl, lane);

        if (DUAL) {
            float sn[8][4];
#pragma unroll
            for (int nf = 0; nf < 8; nf++)
#pragma unroll
                for (int j = 0; j < 4; j++) sn[nf][j] = 0.0f;
            fa_compute_S(sn, sb + 32768, sb + 40960, qfh, qfl, lane);
            if (rg0 >= CTX) {
#pragma unroll
                for (int nf = 0; nf < 8; nf++) { s[nf][0] = sn[nf][0]; s[nf][1] = sn[nf][1]; }
            }
            if (rg1 >= CTX) {
#pragma unroll
                for (int nf = 0; nf < 8; nf++) { s[nf][2] = sn[nf][2]; s[nf][3] = sn[nf][3]; }
            }
        }

        if (kt == qt) {
#pragma unroll
            for (int nf = 0; nf < 8; nf++) {
                int c0 = kt * 64 + nf * 8 + (lane & 3) * 2;
                if (c0     > rg0) s[nf][0] = -1e30f;
                if (c0 + 1 > rg0) s[nf][1] = -1e30f;
                if (c0     > rg1) s[nf][2] = -1e30f;
                if (c0 + 1 > rg1) s[nf][3] = -1e30f;
            }
        }

        float mr0 = -1e30f, mr1 = -1e30f;
#pragma unroll
        for (int nf = 0; nf < 8; nf++) {
            mr0 = fmaxf(mr0, fmaxf(s[nf][0], s[nf][1]));
            mr1 = fmaxf(mr1, fmaxf(s[nf][2], s[nf][3]));
        }
        mr0 = fmaxf(mr0, __shfl_xor_sync(0xffffffffu, mr0, 1));
        mr0 = fmaxf(mr0, __shfl_xor_sync(0xffffffffu, mr0, 2));
        mr1 = fmaxf(mr1, __shfl_xor_sync(0xffffffffu, mr1, 1));
        mr1 = fmaxf(mr1, __shfl_xor_sync(0xffffffffu, mr1, 2));

        float mn0 = fmaxf(m0, mr0), mn1 = fmaxf(m1, mr1);
        float sc0 = exp2f(m0 - mn0), sc1 = exp2f(m1 - mn1);
        m0 = mn0; m1 = mn1;
        l0 *= sc0; l1 *= sc1;
#pragma unroll
        for (int nf = 0; nf < 8; nf++) {
            o[nf][0] *= sc0; o[nf][1] *= sc0;
            o[nf][2] *= sc1; o[nf][3] *= sc1;
        }

        // P in fp16 (2-pass PV)
        uint32_t pF[4][4];
        float sum0 = 0.0f, sum1 = 0.0f;
#pragma unroll
        for (int nf = 0; nf < 8; nf++) {
            float p0 = exp2f(s[nf][0] - m0), p1 = exp2f(s[nf][1] - m0);
            float p2 = exp2f(s[nf][2] - m1), p3 = exp2f(s[nf][3] - m1);
            sum0 += p0 + p1; sum1 += p2 + p3;
            int kk = nf >> 1;
            int off = (nf & 1) * 2;
            pF[kk][off + 0] = pack_f16x2(p0, p1);
            pF[kk][off + 1] = pack_f16x2(p2, p3);
        }
        sum0 += __shfl_xor_sync(0xffffffffu, sum0, 1);
        sum0 += __shfl_xor_sync(0xffffffffu, sum0, 2);
        sum1 += __shfl_xor_sync(0xffffffffu, sum1, 1);
        sum1 += __shfl_xor_sync(0xffffffffu, sum1, 2);
        l0 += sum0; l1 += sum1;

        // O += P V (fp16, 2 passes: P·Vh + P·Vl)
        const uint32_t sVh = sb + 16384, sVl = sb + 24576;
#pragma unroll
        for (int kk = 0; kk < 4; kk++) {
            uint32_t vh[8][2], vl[8][2];
            int key0 = kk * 16 + (lane & 7) + ((lane >> 3) & 1) * 8;
#pragma unroll
            for (int nb = 0; nb < 4; nb++) {
                int chunk = nb * 2 + (lane >> 4);
                uint32_t so = (uint32_t)(key0 * 128 + ((chunk ^ (key0 & 7)) << 4));
                ldsm_x4t(sVh + so, vh[nb*2][0], vh[nb*2][1], vh[nb*2+1][0], vh[nb*2+1][1]);
                ldsm_x4t(sVl + so, vl[nb*2][0], vl[nb*2][1], vl[nb*2+1][0], vl[nb*2+1][1]);
            }
#pragma unroll
            for (int nf = 0; nf < 8; nf++) {
                mma16816h(o[nf], pF[kk], vh[nf]);
                mma16816h(o[nf], pF[kk], vl[nf]);
            }
        }

        __syncthreads();
        if (kt + 2 <= qt)
            fa_load_stage<DUAL>(sQ + 16384 + (kt & 1) * STAGE, kt + 2, kvh, tid,
                                Kbh, Kbl, Knh, Knl, Vh, Vl);
        CP_COMMIT();
    }

    // epilogue: write attn output as fp16 hi/lo splits (feeds wo_gemm2)
    float inv0 = 1.0f / l0, inv1 = 1.0f / l1;
#pragma unroll
    for (int nf = 0; nf < 8; nf++) {
        int col = h * 64 + nf * 8 + (lane & 3) * 2;
        float x0 = o[nf][0]*inv0, x1 = o[nf][1]*inv0;
        float x2 = o[nf][2]*inv1, x3 = o[nf][3]*inv1;
        float r0 = __half2float(__float2half_rn(x0));
        float r1 = __half2float(__float2half_rn(x1));
        float r2 = __half2float(__float2half_rn(x2));
        float r3 = __half2float(__float2half_rn(x3));
        *(uint32_t*)&aHf[(size_t)rg0 * HID + col] = pack_f16x2(x0, x1);
        *(uint32_t*)&aLf[(size_t)rg0 * HID + col] = pack_f16x2(x0 - r0, x1 - r1);
        *(uint32_t*)&aHf[(size_t)rg1 * HID + col] = pack_f16x2(x2, x3);
        *(uint32_t*)&aLf[(size_t)rg1 * HID + col] = pack_f16x2(x2 - r2, x3 - r3);
    }
}

// ---------------- launch ----------------
extern "C" void kernel_launch(void* const* d_in, const int* in_sizes, int n_in,
                              void* d_out, int out_size)
{
    const float* hidden = (const float*)d_in[0];
    const float* Wq = (const float*)d_in[3];
    const float* Wk = (const float*)d_in[4];
    const float* Wv = (const float*)d_in[5];
    const float* Wo = (const float*)d_in[6];
    float* out = (float*)d_out;

    float *qB, *kB, *vB;
    cudaGetSymbolAddress((void**)&qB,  g_Q);
    cudaGetSymbolAddress((void**)&kB,  g_K);
    cudaGetSymbolAddress((void**)&vB,  g_V);

    bf16 *hH,*hL,*WqH,*WqL,*WkH,*WkL,*WvH,*WvL;
    cudaGetSymbolAddress((void**)&hH,  g_hH);  cudaGetSymbolAddress((void**)&hL,  g_hL);
    cudaGetSymbolAddress((void**)&WqH, g_WqH); cudaGetSymbolAddress((void**)&WqL, g_WqL);
    cudaGetSymbolAddress((void**)&WkH, g_WkH); cudaGetSymbolAddress((void**)&WkL, g_WkL);
    cudaGetSymbolAddress((void**)&WvH, g_WvH); cudaGetSymbolAddress((void**)&WvL, g_WvL);

    __half *WoF, *aHf, *aLf;
    cudaGetSymbolAddress((void**)&WoF, g_WoF);
    cudaGetSymbolAddress((void**)&aHf, g_aHf);
    cudaGetSymbolAddress((void**)&aLf, g_aLf);

    bf16 *Qh,*Ql,*bKh,*bKl,*nKh,*nKl;
    __half *Vh,*Vl;
    cudaGetSymbolAddress((void**)&Qh,  g_Qh);  cudaGetSymbolAddress((void**)&Ql,  g_Ql);
    cudaGetSymbolAddress((void**)&bKh, g_bKh); cudaGetSymbolAddress((void**)&bKl, g_bKl);
    cudaGetSymbolAddress((void**)&nKh, g_nKh); cudaGetSymbolAddress((void**)&nKl, g_nKl);
    cudaGetSymbolAddress((void**)&Vh,  g_Vh);  cudaGetSymbolAddress((void**)&Vl,  g_Vl);

    cudaFuncSetAttribute(qkv_gemm, cudaFuncAttributeMaxDynamicSharedMemorySize, SM_TOTAL);
    cudaFuncSetAttribute(wo_gemm2, cudaFuncAttributeMaxDynamicSharedMemorySize, SM_TOTAL2);
    const int FA_SMEM_N = 16384 + 2*32768;   // 81920
    const int FA_SMEM_D = 16384 + 2*49152;   // 114688
    cudaFuncSetAttribute(flash_mma<false>, cudaFuncAttributeMaxDynamicSharedMemorySize, FA_SMEM_N);
    cudaFuncSetAttribute(flash_mma<true>,  cudaFuncAttributeMaxDynamicSharedMemorySize, FA_SMEM_D);

    // all 5 input conversions in one launch
    const int TOT4 = 1048576*3 + 262144*2;   // float4 units
    split_all_kernel<<<(TOT4/4 + 255)/256, 256>>>(hidden, Wq, Wk, Wv, Wo,
                                                  hH, hL, WqH, WqL, WkH, WkL,
                                                  WvH, WvL, WoF);

    qkv_gemm<<<dim3(24, 16), 256, SM_TOTAL>>>(hH, hL, WqH, WqL, WkH, WkL, WvH, WvL,
                                              qB, kB, vB);

    rope_split_kernel<<<S, 256>>>(qB, kB, vB, Qh, Ql, bKh, bKl, nKh, nKl, Vh, Vl);

    // boundary tile (rows 1984..2047, contains CTX) — dual-variant kernel
    flash_mma<true><<<dim3(1, NH), 128, FA_SMEM_D>>>(Qh, Ql, bKh, bKl, nKh, nKl, Vh, Vl, aHf, aLf);
    // remaining tiles, heavy first
    flash_mma<false><<<dim3(S/64 - 1, NH), 128, FA_SMEM_N>>>(Qh, Ql, bKh, bKl, nKh, nKl, Vh, Vl, aHf, aLf);

    // 2-pass fp16 Wo GEMM into d_out
    wo_gemm2<<<dim3(16, 16), 256, SM_TOTAL2>>>(aHf, aLf, WoF, out);
}

// round 13
// speedup vs baseline: 1.3669x; 1.0403x over previous
#include <cuda_runtime.h>
#include <cuda_bf16.h>
#include <cuda_fp16.h>
#include <cstdint>

#define S     2048
#define HID   2048
#define NH    32
#define NKV   8
#define HD    64
#define KVDIM (NKV*HD)   // 512
#define CTX   (S-10)     // 2038: rows >= CTX use narrow rope

typedef unsigned long long ull;
typedef __nv_bfloat16 bf16;

__device__ __forceinline__ uint32_t smem_u32(const void* p) {
    uint32_t a;
    asm("{ .reg .u64 t; cvta.to.shared.u64 t, %1; cvt.u32.u64 %0, t; }" : "=r"(a) : "l"(p));
    return a;
}

// ---------------- mma.sync primitives (compute_103-safe) ----------------
__device__ __forceinline__ void cp16(uint32_t s, const void* g) {
    asm volatile("cp.async.cg.shared.global [%0], [%1], 16;" :: "r"(s), "l"(g));
}
#define CP_COMMIT() asm volatile("cp.async.commit_group;" ::: "memory")
#define CP_WAIT1()  asm volatile("cp.async.wait_group 1;" ::: "memory")

__device__ __forceinline__ void ldsm_x4(uint32_t addr, uint32_t& r0, uint32_t& r1,
                                        uint32_t& r2, uint32_t& r3) {
    asm volatile("ldmatrix.sync.aligned.m8n8.x4.shared.b16 {%0,%1,%2,%3}, [%4];"
                 : "=r"(r0), "=r"(r1), "=r"(r2), "=r"(r3) : "r"(addr));
}
__device__ __forceinline__ void ldsm_x4t(uint32_t addr, uint32_t& r0, uint32_t& r1,
                                         uint32_t& r2, uint32_t& r3) {
    asm volatile("ldmatrix.sync.aligned.m8n8.x4.trans.shared.b16 {%0,%1,%2,%3}, [%4];"
                 : "=r"(r0), "=r"(r1), "=r"(r2), "=r"(r3) : "r"(addr));
}
__device__ __forceinline__ void mma16816(float* c, const uint32_t* a, const uint32_t* b) {
    asm volatile(
        "mma.sync.aligned.m16n8k16.row.col.f32.bf16.bf16.f32 "
        "{%0,%1,%2,%3}, {%4,%5,%6,%7}, {%8,%9}, {%0,%1,%2,%3};"
        : "+f"(c[0]), "+f"(c[1]), "+f"(c[2]), "+f"(c[3])
        : "r"(a[0]), "r"(a[1]), "r"(a[2]), "r"(a[3]), "r"(b[0]), "r"(b[1]));
}
__device__ __forceinline__ void mma16816h(float* c, const uint32_t* a, const uint32_t* b) {
    asm volatile(
        "mma.sync.aligned.m16n8k16.row.col.f32.f16.f16.f32 "
        "{%0,%1,%2,%3}, {%4,%5,%6,%7}, {%8,%9}, {%0,%1,%2,%3};"
        : "+f"(c[0]), "+f"(c[1]), "+f"(c[2]), "+f"(c[3])
        : "r"(a[0]), "r"(a[1]), "r"(a[2]), "r"(a[3]), "r"(b[0]), "r"(b[1]));
}
__device__ __forceinline__ uint32_t pack_bf16x2(float lo, float hi) {
    uint32_t r; asm("cvt.rn.bf16x2.f32 %0, %1, %2;" : "=r"(r) : "f"(hi), "f"(lo));
    return r;
}
__device__ __forceinline__ uint32_t pack_f16x2(float lo, float hi) {
    uint32_t r; asm("cvt.rn.f16x2.f32 %0, %1, %2;" : "=r"(r) : "f"(hi), "f"(lo));
    return r;
}

// ---------------- scratch (static device globals; no allocs) ----------------
__device__ float g_Q   [S*HID];
__device__ float g_K   [S*KVDIM];
__device__ float g_V   [S*KVDIM];
__device__ bf16 g_hH[S*HID],     g_hL[S*HID];
__device__ bf16 g_WqH[HID*HID],  g_WqL[HID*HID];
__device__ bf16 g_WkH[KVDIM*HID],g_WkL[KVDIM*HID];
__device__ bf16 g_WvH[KVDIM*HID],g_WvL[KVDIM*HID];
__device__ __half g_WoF[HID*HID];                  // Wo in fp16 (hi only)
__device__ __half g_aHf[S*HID],  g_aLf[S*HID];     // attn out fp16 hi/lo
__device__ bf16 g_Qh[S*HID],    g_Ql[S*HID];
__device__ bf16 g_bKh[S*KVDIM], g_bKl[S*KVDIM];
__device__ bf16 g_nKh[S*KVDIM], g_nKl[S*KVDIM];
__device__ __half g_Vh[S*KVDIM], g_Vl[S*KVDIM];    // fp16 split of V
// dual split-K partials: [split][head][row 0..63][dim 0..63] + m/l
#define DSPLIT 4
#define DTILES (32/DSPLIT)   // 8 key tiles per split
__device__ float g_pO[DSPLIT*NH*64*64];
__device__ float g_pm[DSPLIT*NH*64];
__device__ float g_pl[DSPLIT*NH*64];

// ---------------- fp32 -> bf16 hi/lo split ----------------
__device__ __forceinline__ void split_body(const float* __restrict__ x,
                                           bf16* __restrict__ hi, bf16* __restrict__ lo,
                                           int i)
{
    float4 v = ((const float4*)x)[i];
    bf16 h0 = __float2bfloat16(v.x);
    bf16 h1 = __float2bfloat16(v.y);
    bf16 h2 = __float2bfloat16(v.z);
    bf16 h3 = __float2bfloat16(v.w);
    __nv_bfloat162 H0 = __nv_bfloat162(h0, h1), H1 = __nv_bfloat162(h2, h3);
    __nv_bfloat162 L0 = __nv_bfloat162(__float2bfloat16(v.x - __bfloat162float(h0)),
                                       __float2bfloat16(v.y - __bfloat162float(h1)));
    __nv_bfloat162 L1 = __nv_bfloat162(__float2bfloat16(v.z - __bfloat162float(h2)),
                                       __float2bfloat16(v.w - __bfloat162float(h3)));
    ((__nv_bfloat162*)hi)[i*2+0] = H0; ((__nv_bfloat162*)hi)[i*2+1] = H1;
    ((__nv_bfloat162*)lo)[i*2+0] = L0; ((__nv_bfloat162*)lo)[i*2+1] = L1;
}

// merged split of hidden/Wq/Wk/Wv (bf16 hi/lo) + Wo (fp16 hi), 4 float4/thread.
__global__ __launch_bounds__(256)
void split_all_kernel(const float* __restrict__ hid, const float* __restrict__ Wq,
                      const float* __restrict__ Wk,  const float* __restrict__ Wv,
                      const float* __restrict__ Wo,
                      bf16* __restrict__ hH, bf16* __restrict__ hL,
                      bf16* __restrict__ qH, bf16* __restrict__ qL,
                      bf16* __restrict__ kH, bf16* __restrict__ kL,
                      bf16* __restrict__ vH, bf16* __restrict__ vL,
                      __half* __restrict__ oF)
{
    int g0 = (blockIdx.x * 256 + threadIdx.x) * 4;   // region bounds all %4==0
    const int R0 = 1048576, R1 = R0 + 1048576, R2 = R1 + 262144, R3 = R2 + 262144;
    const int TOT = R3 + 1048576;
    if (g0 >= TOT) return;
    if (g0 >= R3) {
#pragma unroll
        for (int k = 0; k < 4; k++) {
            int i = g0 - R3 + k;
            float4 v = ((const float4*)Wo)[i];
            ((__half2*)oF)[i*2+0] = __half2(__float2half_rn(v.x), __float2half_rn(v.y));
            ((__half2*)oF)[i*2+1] = __half2(__float2half_rn(v.z), __float2half_rn(v.w));
        }
        return;
    }
    const float* src; bf16 *dh, *dl; int rb;
    if (g0 < R0)      { src = hid; dh = hH; dl = hL; rb = 0;  }
    else if (g0 < R1) { src = Wq;  dh = qH; dl = qL; rb = R0; }
    else if (g0 < R2) { src = Wk;  dh = kH; dl = kL; rb = R1; }
    else              { src = Wv;  dh = vH; dl = vL; rb = R2; }
#pragma unroll
    for (int k = 0; k < 4; k++) split_body(src, dh, dl, g0 - rb + k);
}

// ---------------- mma.sync split-bf16 GEMM core (3-pass, unchanged) ----
#define STG      16384
#define SM_STAGE (4*STG)          // 64 KB
#define SM_TOTAL (2*SM_STAGE)     // 128 KB

__device__ __forceinline__ void g_load_stage(
    uint32_t sbuf,
    const bf16* __restrict__ Ah, const bf16* __restrict__ Al,
    const bf16* __restrict__ Bh, const bf16* __restrict__ Bl,
    int mBase, int nBase, int Kdim, int k0, int tid)
{
#pragma unroll
    for (int i = 0; i < 4; i++) {
        int u = i * 256 + tid;
        int r = u >> 3, c = u & 7;
        uint32_t so = (uint32_t)(r * 128 + ((c ^ (r & 7)) << 4));
        size_t eoffA = (size_t)(mBase + r) * Kdim + k0 + c * 8;
        size_t eoffB = (size_t)(nBase + r) * Kdim + k0 + c * 8;
        cp16(sbuf +          so, Ah + eoffA);
        cp16(sbuf +   STG  + so, Al + eoffA);
        cp16(sbuf + 2*STG  + so, Bh + eoffB);
        cp16(sbuf + 3*STG  + so, Bl + eoffB);
    }
}

__device__ __forceinline__ void gemm_body(
    const bf16* __restrict__ Ah, const bf16* __restrict__ Al,
    const bf16* __restrict__ Bh, const bf16* __restrict__ Bl,
    float* __restrict__ C, int Ntot, int Kdim, int mBase, int nBase, uint32_t sb)
{
    const int tid  = threadIdx.x;
    const int lane = tid & 31;
    const int wid  = tid >> 5;
    const int wm   = wid & 1;
    const int wn   = wid >> 1;

    float acc[4][4][4];
#pragma unroll
    for (int i = 0; i < 4; i++)
#pragma unroll
        for (int j = 0; j < 4; j++)
#pragma unroll
            for (int k = 0; k < 4; k++) acc[i][j][k] = 0.0f;

    const int NC = Kdim >> 6;

    g_load_stage(sb,            Ah, Al, Bh, Bl, mBase, nBase, Kdim, 0,  tid);
    CP_COMMIT();
    g_load_stage(sb + SM_STAGE, Ah, Al, Bh, Bl, mBase, nBase, Kdim, 64, tid);
    CP_COMMIT();

    const int aRow = wm * 64;
    const int bRow = wn * 32;

    for (int c = 0; c < NC; c++) {
        CP_WAIT1();
        __syncthreads();
        const uint32_t sbuf = sb + (c & 1) * SM_STAGE;
        const uint32_t sAh = sbuf, sAl = sbuf + STG, sBh = sbuf + 2*STG, sBl = sbuf + 3*STG;

#pragma unroll
        for (int ks = 0; ks < 4; ks++) {
            uint32_t aH[4][4], aL[4][4], bH[4][2], bL[4][2];
            {
                int rA = aRow + (lane & 15);
                int ccA = ks * 2 + (lane >> 4);
#pragma unroll
                for (int mf = 0; mf < 4; mf++) {
                    int r = rA + mf * 16;
                    uint32_t so = (uint32_t)(r * 128 + ((ccA ^ (r & 7)) << 4));
                    ldsm_x4(sAh + so, aH[mf][0], aH[mf][1], aH[mf][2], aH[mf][3]);
                    ldsm_x4(sAl + so, aL[mf][0], aL[mf][1], aL[mf][2], aL[mf][3]);
                }
            }
            {
                int rB0 = bRow + (lane & 7) + ((lane >> 4) << 3);
                int ccB = ks * 2 + ((lane >> 3) & 1);
#pragma unroll
                for (int nf2 = 0; nf2 < 2; nf2++) {
                    int r = rB0 + nf2 * 16;
                    uint32_t so = (uint32_t)(r * 128 + ((ccB ^ (r & 7)) << 4));
                    ldsm_x4(sBh + so, bH[nf2*2][0], bH[nf2*2][1], bH[nf2*2+1][0], bH[nf2*2+1][1]);
                    ldsm_x4(sBl + so, bL[nf2*2][0], bL[nf2*2][1], bL[nf2*2+1][0], bL[nf2*2+1][1]);
                }
            }
#pragma unroll
            for (int mf = 0; mf < 4; mf++)
#pragma unroll
                for (int nf = 0; nf < 4; nf++) {
                    mma16816(acc[mf][nf], aH[mf], bH[nf]);
                    mma16816(acc[mf][nf], aL[mf], bH[nf]);
                    mma16816(acc[mf][nf], aH[mf], bL[nf]);
                }
        }
        __syncthreads();
        if (c + 2 < NC)
            g_load_stage(sb + (c & 1) * SM_STAGE, Ah, Al, Bh, Bl,
                         mBase, nBase, Kdim, (c + 2) * 64, tid);
        CP_COMMIT();
    }

#pragma unroll
    for (int mf = 0; mf < 4; mf++) {
        int row0 = mBase + wm * 64 + mf * 16 + (lane >> 2);
#pragma unroll
        for (int nf = 0; nf < 4; nf++) {
            int col = nBase + wn * 32 + nf * 8 + (lane & 3) * 2;
            *(float2*)&C[(size_t)row0 * Ntot + col]       = make_float2(acc[mf][nf][0], acc[mf][nf][1]);
            *(float2*)&C[(size_t)(row0 + 8) * Ntot + col] = make_float2(acc[mf][nf][2], acc[mf][nf][3]);
        }
    }
}

__global__ __launch_bounds__(256)
void qkv_gemm(const bf16* __restrict__ Ah, const bf16* __restrict__ Al,
              const bf16* __restrict__ WqH, const bf16* __restrict__ WqL,
              const bf16* __restrict__ WkH, const bf16* __restrict__ WkL,
              const bf16* __restrict__ WvH, const bf16* __restrict__ WvL,
              float* __restrict__ Cq, float* __restrict__ Ck, float* __restrict__ Cv)
{
    extern __shared__ char dyns[];
    uint32_t sb = smem_u32(dyns);
    int bx = blockIdx.x, mBase = blockIdx.y * 128;
    if (bx < 16)      gemm_body(Ah, Al, WqH, WqL, Cq, HID,   HID, mBase, bx*128,      sb);
    else if (bx < 20) gemm_body(Ah, Al, WkH, WkL, Ck, KVDIM, HID, mBase, (bx-16)*128, sb);
    else              gemm_body(Ah, Al, WvH, WvL, Cv, KVDIM, HID, mBase, (bx-20)*128, sb);
}

// ---------------- 2-pass fp16 GEMM for Wo: C = (Ah+Al) @ Bh^T ----------
#define STG2      16384
#define SM_STAGE2 (3*STG2)        // 48 KB
#define SM_TOTAL2 (2*SM_STAGE2)   // 96 KB -> 2 CTAs/SM

__device__ __forceinline__ void g_load_stage2(
    uint32_t sbuf,
    const __half* __restrict__ Ah, const __half* __restrict__ Al,
    const __half* __restrict__ Bh,
    int mBase, int nBase, int Kdim, int k0, int tid)
{
#pragma unroll
    for (int i = 0; i < 4; i++) {
        int u = i * 256 + tid;
        int r = u >> 3, c = u & 7;
        uint32_t so = (uint32_t)(r * 128 + ((c ^ (r & 7)) << 4));
        size_t eoffA = (size_t)(mBase + r) * Kdim + k0 + c * 8;
        size_t eoffB = (size_t)(nBase + r) * Kdim + k0 + c * 8;
        cp16(sbuf +          so, Ah + eoffA);
        cp16(sbuf +   STG2 + so, Al + eoffA);
        cp16(sbuf + 2*STG2 + so, Bh + eoffB);
    }
}

__global__ __launch_bounds__(256, 2)
void wo_gemm2(const __half* __restrict__ Ah, const __half* __restrict__ Al,
              const __half* __restrict__ Bh, float* __restrict__ C)
{
    extern __shared__ char dyns[];
    const uint32_t sb = smem_u32(dyns);
    const int tid  = threadIdx.x;
    const int lane = tid & 31;
    const int wid  = tid >> 5;
    const int wm   = wid & 1;
    const int wn   = wid >> 1;
    const int mBase = blockIdx.y * 128, nBase = blockIdx.x * 128;

    float acc[4][4][4];
#pragma unroll
    for (int i = 0; i < 4; i++)
#pragma unroll
        for (int j = 0; j < 4; j++)
#pragma unroll
            for (int k = 0; k < 4; k++) acc[i][j][k] = 0.0f;

    const int NC = HID >> 6;   // 32

    g_load_stage2(sb,             Ah, Al, Bh, mBase, nBase, HID, 0,  tid);
    CP_COMMIT();
    g_load_stage2(sb + SM_STAGE2, Ah, Al, Bh, mBase, nBase, HID, 64, tid);
    CP_COMMIT();

    const int aRow = wm * 64;
    const int bRow = wn * 32;

    for (int c = 0; c < NC; c++) {
        CP_WAIT1();
        __syncthreads();
        const uint32_t sbuf = sb + (c & 1) * SM_STAGE2;
        const uint32_t sAh = sbuf, sAl = sbuf + STG2, sBh = sbuf + 2*STG2;

#pragma unroll
        for (int ks = 0; ks < 4; ks++) {
            uint32_t aH[4][4], aL[4][4], bH[4][2];
            {
                int rA = aRow + (lane & 15);
                int ccA = ks * 2 + (lane >> 4);
#pragma unroll
                for (int mf = 0; mf < 4; mf++) {
                    int r = rA + mf * 16;
                    uint32_t so = (uint32_t)(r * 128 + ((ccA ^ (r & 7)) << 4));
                    ldsm_x4(sAh + so, aH[mf][0], aH[mf][1], aH[mf][2], aH[mf][3]);
                    ldsm_x4(sAl + so, aL[mf][0], aL[mf][1], aL[mf][2], aL[mf][3]);
                }
            }
            {
                int rB0 = bRow + (lane & 7) + ((lane >> 4) << 3);
                int ccB = ks * 2 + ((lane >> 3) & 1);
#pragma unroll
                for (int nf2 = 0; nf2 < 2; nf2++) {
                    int r = rB0 + nf2 * 16;
                    uint32_t so = (uint32_t)(r * 128 + ((ccB ^ (r & 7)) << 4));
                    ldsm_x4(sBh + so, bH[nf2*2][0], bH[nf2*2][1], bH[nf2*2+1][0], bH[nf2*2+1][1]);
                }
            }
#pragma unroll
            for (int mf = 0; mf < 4; mf++)
#pragma unroll
                for (int nf = 0; nf < 4; nf++) {
                    mma16816h(acc[mf][nf], aH[mf], bH[nf]);
                    mma16816h(acc[mf][nf], aL[mf], bH[nf]);
                }
        }
        __syncthreads();
        if (c + 2 < NC)
            g_load_stage2(sb + (c & 1) * SM_STAGE2, Ah, Al, Bh,
                          mBase, nBase, HID, (c + 2) * 64, tid);
        CP_COMMIT();
    }

#pragma unroll
    for (int mf = 0; mf < 4; mf++) {
        int row0 = mBase + wm * 64 + mf * 16 + (lane >> 2);
#pragma unroll
        for (int nf = 0; nf < 4; nf++) {
            int col = nBase + wn * 32 + nf * 8 + (lane & 3) * 2;
            *(float2*)&C[(size_t)row0 * HID + col]       = make_float2(acc[mf][nf][0], acc[mf][nf][1]);
            *(float2*)&C[(size_t)(row0 + 8) * HID + col] = make_float2(acc[mf][nf][2], acc[mf][nf][3]);
        }
    }
}

// ---------------- RoPE + split (float4-vectorized) --------------------------
__device__ __forceinline__ void split_w2(bf16* hp, bf16* lp, float x0, float x1) {
    bf16 h0 = __float2bfloat16(x0);
    bf16 h1 = __float2bfloat16(x1);
    *(__nv_bfloat162*)hp = __nv_bfloat162(h0, h1);
    *(__nv_bfloat162*)lp = __nv_bfloat162(__float2bfloat16(x0 - __bfloat162float(h0)),
                                          __float2bfloat16(x1 - __bfloat162float(h1)));
}

__global__ void rope_split_kernel(const float* __restrict__ Q, const float* __restrict__ K,
                                  const float* __restrict__ V,
                                  bf16* __restrict__ qh, bf16* __restrict__ ql,
                                  bf16* __restrict__ kbh, bf16* __restrict__ kbl,
                                  bf16* __restrict__ knh, bf16* __restrict__ knl,
                                  __half* __restrict__ vh, __half* __restrict__ vl)
{
    const int s = blockIdx.x;
    const int tid = threadIdx.x; // 256
    const bool narrowRow = (s >= CTX);
    const float QS = 1.4426950408889634f * 0.125f;   // log2(e)/sqrt(64)

    __shared__ float cb[32], sb[32], cn[32], sn[32];
    if (tid < 32) {
        double inv = pow(10000.0, -(double)tid / 32.0);
        double ab = (double)s * inv;
        double an = ((double)s * 0.25) * inv;
        cb[tid] = (float)cos(ab); sb[tid] = (float)sin(ab);
        cn[tid] = (float)cos(an); sn[tid] = (float)sin(an);
    }
    __syncthreads();

    {
        int p = tid;
        int h = p >> 3, d4 = (p & 7) * 4;
        size_t base = (size_t)s * HID + h * HD;
        float4 x1 = *(const float4*)&Q[base + d4];
        float4 x2 = *(const float4*)&Q[base + d4 + 32];
        const float* cc = narrowRow ? cn : cb;
        const float* ss = narrowRow ? sn : sb;
        float c0 = cc[d4], c1 = cc[d4+1], c2 = cc[d4+2], c3 = cc[d4+3];
        float s0 = ss[d4], s1 = ss[d4+1], s2 = ss[d4+2], s3 = ss[d4+3];
        split_w2(qh + base + d4,     ql + base + d4,
                 (x1.x*c0 - x2.x*s0)*QS, (x1.y*c1 - x2.y*s1)*QS);
        split_w2(qh + base + d4 + 2, ql + base + d4 + 2,
                 (x1.z*c2 - x2.z*s2)*QS, (x1.w*c3 - x2.w*s3)*QS);
        split_w2(qh + base + d4 + 32, ql + base + d4 + 32,
                 (x2.x*c0 + x1.x*s0)*QS, (x2.y*c1 + x1.y*s1)*QS);
        split_w2(qh + base + d4 + 34, ql + base + d4 + 34,
                 (x2.z*c2 + x1.z*s2)*QS, (x2.w*c3 + x1.w*s3)*QS);
    }
    if (tid < NKV * 8) {
        int p = tid;
        int h = p >> 3, d4 = (p & 7) * 4;
        size_t base = (size_t)s * KVDIM + h * HD;
        float4 x1 = *(const float4*)&K[base + d4];
        float4 x2 = *(const float4*)&K[base + d4 + 32];
        float cb0 = cb[d4], cb1 = cb[d4+1], cb2 = cb[d4+2], cb3 = cb[d4+3];
        float sb0 = sb[d4], sb1 = sb[d4+1], sb2 = sb[d4+2], sb3 = sb[d4+3];
        float cn0 = cn[d4], cn1 = cn[d4+1], cn2 = cn[d4+2], cn3 = cn[d4+3];
        float sn0 = sn[d4], sn1 = sn[d4+1], sn2 = sn[d4+2], sn3 = sn[d4+3];
        split_w2(kbh + base + d4,     kbl + base + d4,
                 x1.x*cb0 - x2.x*sb0, x1.y*cb1 - x2.y*sb1);
        split_w2(kbh + base + d4 + 2, kbl + base + d4 + 2,
                 x1.z*cb2 - x2.z*sb2, x1.w*cb3 - x2.w*sb3);
        split_w2(kbh + base + d4 + 32, kbl + base + d4 + 32,
                 x2.x*cb0 + x1.x*sb0, x2.y*cb1 + x1.y*sb1);
        split_w2(kbh + base + d4 + 34, kbl + base + d4 + 34,
                 x2.z*cb2 + x1.z*sb2, x2.w*cb3 + x1.w*sb3);
        split_w2(knh + base + d4,     knl + base + d4,
                 x1.x*cn0 - x2.x*sn0, x1.y*cn1 - x2.y*sn1);
        split_w2(knh + base + d4 + 2, knl + base + d4 + 2,
                 x1.z*cn2 - x2.z*sn2, x1.w*cn3 - x2.w*sn3);
        split_w2(knh + base + d4 + 32, knl + base + d4 + 32,
                 x2.x*cn0 + x1.x*sn0, x2.y*cn1 + x1.y*sn1);
        split_w2(knh + base + d4 + 34, knl + base + d4 + 34,
                 x2.z*cn2 + x1.z*sn2, x2.w*cn3 + x1.w*sn3);
    }
    if (tid < KVDIM / 4) {
        size_t base = (size_t)s * KVDIM + tid * 4;
        float4 v = *(const float4*)&V[base];
        __half h0 = __float2half_rn(v.x), h1 = __float2half_rn(v.y);
        __half h2 = __float2half_rn(v.z), h3 = __float2half_rn(v.w);
        *(__half2*)(vh + base)     = __half2(h0, h1);
        *(__half2*)(vh + base + 2) = __half2(h2, h3);
        *(__half2*)(vl + base)     = __half2(__float2half_rn(v.x - __half2float(h0)),
                                             __float2half_rn(v.y - __half2float(h1)));
        *(__half2*)(vl + base + 2) = __half2(__float2half_rn(v.z - __half2float(h2)),
                                             __float2half_rn(v.w - __half2float(h3)));
    }
}

// ---------------- Tensor-core flash attention (fp16 2-pass PV) -------------
template<bool DUAL>
__device__ __forceinline__ void fa_load_stage(
    uint32_t sb, int kt, int kvh, int tid,
    const bf16* __restrict__ Kbh, const bf16* __restrict__ Kbl,
    const bf16* __restrict__ Knh, const bf16* __restrict__ Knl,
    const __half* __restrict__ Vh, const __half* __restrict__ Vl)
{
#pragma unroll
    for (int i = 0; i < 4; i++) {
        int u = i * 128 + tid;      // 0..511
        int r = u >> 3, c = u & 7;
        uint32_t so = (uint32_t)(r * 128 + ((c ^ (r & 7)) << 4));
        size_t go = (size_t)(kt * 64 + r) * KVDIM + kvh * 64 + c * 8;
        cp16(sb +         so, Kbh + go);
        cp16(sb + 8192  + so, Kbl + go);
        cp16(sb + 16384 + so, Vh + go);
        cp16(sb + 24576 + so, Vl + go);
        if (DUAL) {
            cp16(sb + 32768 + so, Knh + go);
            cp16(sb + 40960 + so, Knl + go);
        }
    }
}

__device__ __forceinline__ void fa_compute_S(
    float s[8][4], uint32_t sKh, uint32_t sKl,
    const uint32_t qfh[4][4], const uint32_t qfl[4][4], int lane)
{
#pragma unroll
    for (int kk = 0; kk < 4; kk++) {
        uint32_t kh[8][2], kl[8][2];
        int rB0 = (lane & 7) + ((lane >> 4) << 3);
        int ccB = kk * 2 + ((lane >> 3) & 1);
#pragma unroll
        for (int nb = 0; nb < 4; nb++) {
            int r = nb * 16 + rB0;
            uint32_t so = (uint32_t)(r * 128 + ((ccB ^ (r & 7)) << 4));
            ldsm_x4(sKh + so, kh[nb*2][0], kh[nb*2][1], kh[nb*2+1][0], kh[nb*2+1][1]);
            ldsm_x4(sKl + so, kl[nb*2][0], kl[nb*2][1], kl[nb*2+1][0], kl[nb*2+1][1]);
        }
#pragma unroll
        for (int nf = 0; nf < 8; nf++) {
            mma16816(s[nf], qfh[kk], kh[nf]);
            mma16816(s[nf], qfl[kk], kh[nf]);
            mma16816(s[nf], qfh[kk], kl[nf]);
        }
    }
}

// ---- main flash (boost only, 31 tiles), writes fp16 hi/lo attn output ----
__global__ __launch_bounds__(128, 2)
void flash_main(const bf16* __restrict__ Qh, const bf16* __restrict__ Ql,
                const bf16* __restrict__ Kbh, const bf16* __restrict__ Kbl,
                const __half* __restrict__ Vh,  const __half* __restrict__ Vl,
                __half* __restrict__ aHf, __half* __restrict__ aLf)
{
    constexpr int STAGE = 32768;
    extern __shared__ char dyn[];
    const uint32_t sQ = smem_u32(dyn);

    const int tid = threadIdx.x, lane = tid & 31, w = tid >> 5;
    const int qt = (S/64 - 2) - (int)blockIdx.x;   // heavy first, tiles 0..30
    const int h = blockIdx.y, kvh = h >> 2;

    {
        const bf16* gQh = Qh + (size_t)(qt * 64) * HID + h * 64;
        const bf16* gQl = Ql + (size_t)(qt * 64) * HID + h * 64;
#pragma unroll
        for (int i = 0; i < 4; i++) {
            int u = i * 128 + tid;
            int r = u >> 3, c = u & 7;
            uint32_t so = (uint32_t)(r * 128 + ((c ^ (r & 7)) << 4));
            cp16(sQ +        so, gQh + (size_t)r * HID + c * 8);
            cp16(sQ + 8192 + so, gQl + (size_t)r * HID + c * 8);
        }
    }
    fa_load_stage<false>(sQ + 16384, 0, kvh, tid, Kbh, Kbl, nullptr, nullptr, Vh, Vl);
    CP_COMMIT();
    if (qt >= 1)
        fa_load_stage<false>(sQ + 16384 + STAGE, 1, kvh, tid, Kbh, Kbl, nullptr, nullptr, Vh, Vl);
    CP_COMMIT();

    CP_WAIT1();
    __syncthreads();

    uint32_t qfh[4][4], qfl[4][4];
    {
        int rA = w * 16 + (lane & 15);
#pragma unroll
        for (int kk = 0; kk < 4; kk++) {
            int cc = kk * 2 + (lane >> 4);
            uint32_t so = (uint32_t)(rA * 128 + ((cc ^ (rA & 7)) << 4));
            ldsm_x4(sQ + so,        qfh[kk][0], qfh[kk][1], qfh[kk][2], qfh[kk][3]);
            ldsm_x4(sQ + 8192 + so, qfl[kk][0], qfl[kk][1], qfl[kk][2], qfl[kk][3]);
        }
    }

    float o[8][4];
#pragma unroll
    for (int nf = 0; nf < 8; nf++)
#pragma unroll
        for (int j = 0; j < 4; j++) o[nf][j] = 0.0f;
    float m0 = -1e30f, m1 = -1e30f, l0 = 0.0f, l1 = 0.0f;

    const int rg0 = qt * 64 + w * 16 + (lane >> 2);
    const int rg1 = rg0 + 8;

    for (int kt = 0; kt <= qt; kt++) {
        if (kt) { CP_WAIT1(); __syncthreads(); }
        const uint32_t sb = sQ + 16384 + (kt & 1) * STAGE;

        float s[8][4];
#pragma unroll
        for (int nf = 0; nf < 8; nf++)
#pragma unroll
            for (int j = 0; j < 4; j++) s[nf][j] = 0.0f;
        fa_compute_S(s, sb, sb + 8192, qfh, qfl, lane);

        if (kt == qt) {
#pragma unroll
            for (int nf = 0; nf < 8; nf++) {
                int c0 = kt * 64 + nf * 8 + (lane & 3) * 2;
                if (c0     > rg0) s[nf][0] = -1e30f;
                if (c0 + 1 > rg0) s[nf][1] = -1e30f;
                if (c0     > rg1) s[nf][2] = -1e30f;
                if (c0 + 1 > rg1) s[nf][3] = -1e30f;
            }
        }

        float mr0 = -1e30f, mr1 = -1e30f;
#pragma unroll
        for (int nf = 0; nf < 8; nf++) {
            mr0 = fmaxf(mr0, fmaxf(s[nf][0], s[nf][1]));
            mr1 = fmaxf(mr1, fmaxf(s[nf][2], s[nf][3]));
        }
        mr0 = fmaxf(mr0, __shfl_xor_sync(0xffffffffu, mr0, 1));
        mr0 = fmaxf(mr0, __shfl_xor_sync(0xffffffffu, mr0, 2));
        mr1 = fmaxf(mr1, __shfl_xor_sync(0xffffffffu, mr1, 1));
        mr1 = fmaxf(mr1, __shfl_xor_sync(0xffffffffu, mr1, 2));

        float mn0 = fmaxf(m0, mr0), mn1 = fmaxf(m1, mr1);
        float sc0 = exp2f(m0 - mn0), sc1 = exp2f(m1 - mn1);
        m0 = mn0; m1 = mn1;
        l0 *= sc0; l1 *= sc1;
#pragma unroll
        for (int nf = 0; nf < 8; nf++) {
            o[nf][0] *= sc0; o[nf][1] *= sc0;
            o[nf][2] *= sc1; o[nf][3] *= sc1;
        }

        uint32_t pF[4][4];
        float sum0 = 0.0f, sum1 = 0.0f;
#pragma unroll
        for (int nf = 0; nf < 8; nf++) {
            float p0 = exp2f(s[nf][0] - m0), p1 = exp2f(s[nf][1] - m0);
            float p2 = exp2f(s[nf][2] - m1), p3 = exp2f(s[nf][3] - m1);
            sum0 += p0 + p1; sum1 += p2 + p3;
            int kk = nf >> 1;
            int off = (nf & 1) * 2;
            pF[kk][off + 0] = pack_f16x2(p0, p1);
            pF[kk][off + 1] = pack_f16x2(p2, p3);
        }
        sum0 += __shfl_xor_sync(0xffffffffu, sum0, 1);
        sum0 += __shfl_xor_sync(0xffffffffu, sum0, 2);
        sum1 += __shfl_xor_sync(0xffffffffu, sum1, 1);
        sum1 += __shfl_xor_sync(0xffffffffu, sum1, 2);
        l0 += sum0; l1 += sum1;

        const uint32_t sVh = sb + 16384, sVl = sb + 24576;
#pragma unroll
        for (int kk = 0; kk < 4; kk++) {
            uint32_t vh[8][2], vl[8][2];
            int key0 = kk * 16 + (lane & 7) + ((lane >> 3) & 1) * 8;
#pragma unroll
            for (int nb = 0; nb < 4; nb++) {
                int chunk = nb * 2 + (lane >> 4);
                uint32_t so = (uint32_t)(key0 * 128 + ((chunk ^ (key0 & 7)) << 4));
                ldsm_x4t(sVh + so, vh[nb*2][0], vh[nb*2][1], vh[nb*2+1][0], vh[nb*2+1][1]);
                ldsm_x4t(sVl + so, vl[nb*2][0], vl[nb*2][1], vl[nb*2+1][0], vl[nb*2+1][1]);
            }
#pragma unroll
            for (int nf = 0; nf < 8; nf++) {
                mma16816h(o[nf], pF[kk], vh[nf]);
                mma16816h(o[nf], pF[kk], vl[nf]);
            }
        }

        __syncthreads();
        if (kt + 2 <= qt)
            fa_load_stage<false>(sQ + 16384 + (kt & 1) * STAGE, kt + 2, kvh, tid,
                                 Kbh, Kbl, nullptr, nullptr, Vh, Vl);
        CP_COMMIT();
    }

    float inv0 = 1.0f / l0, inv1 = 1.0f / l1;
#pragma unroll
    for (int nf = 0; nf < 8; nf++) {
        int col = h * 64 + nf * 8 + (lane & 3) * 2;
        float x0 = o[nf][0]*inv0, x1 = o[nf][1]*inv0;
        float x2 = o[nf][2]*inv1, x3 = o[nf][3]*inv1;
        float r0 = __half2float(__float2half_rn(x0));
        float r1 = __half2float(__float2half_rn(x1));
        float r2 = __half2float(__float2half_rn(x2));
        float r3 = __half2float(__float2half_rn(x3));
        *(uint32_t*)&aHf[(size_t)rg0 * HID + col] = pack_f16x2(x0, x1);
        *(uint32_t*)&aLf[(size_t)rg0 * HID + col] = pack_f16x2(x0 - r0, x1 - r1);
        *(uint32_t*)&aHf[(size_t)rg1 * HID + col] = pack_f16x2(x2, x3);
        *(uint32_t*)&aLf[(size_t)rg1 * HID + col] = pack_f16x2(x2 - r2, x3 - r3);
    }
}

// ---- dual boundary tile, split-K over key tiles: grid (DSPLIT, NH) --------
__global__ __launch_bounds__(128, 1)
void flash_dual_split(const bf16* __restrict__ Qh, const bf16* __restrict__ Ql,
                      const bf16* __restrict__ Kbh, const bf16* __restrict__ Kbl,
                      const bf16* __restrict__ Knh, const bf16* __restrict__ Knl,
                      const __half* __restrict__ Vh,  const __half* __restrict__ Vl,
                      float* __restrict__ pO, float* __restrict__ pm,
                      float* __restrict__ pl)
{
    constexpr int STAGE = 49152;
    extern __shared__ char dyn[];
    const uint32_t sQ = smem_u32(dyn);

    const int tid = threadIdx.x, lane = tid & 31, w = tid >> 5;
    const int split = blockIdx.x;                 // 0..DSPLIT-1
    const int h = blockIdx.y, kvh = h >> 2;
    const int qt = S/64 - 1;                      // 31
    const int kt0 = split * DTILES, kt1 = kt0 + DTILES;

    {
        const bf16* gQh = Qh + (size_t)(qt * 64) * HID + h * 64;
        const bf16* gQl = Ql + (size_t)(qt * 64) * HID + h * 64;
#pragma unroll
        for (int i = 0; i < 4; i++) {
            int u = i * 128 + tid;
            int r = u >> 3, c = u & 7;
            uint32_t so = (uint32_t)(r * 128 + ((c ^ (r & 7)) << 4));
            cp16(sQ +        so, gQh + (size_t)r * HID + c * 8);
            cp16(sQ + 8192 + so, gQl + (size_t)r * HID + c * 8);
        }
    }
    fa_load_stage<true>(sQ + 16384, kt0, kvh, tid, Kbh, Kbl, Knh, Knl, Vh, Vl);
    CP_COMMIT();
    fa_load_stage<true>(sQ + 16384 + STAGE, kt0 + 1, kvh, tid, Kbh, Kbl, Knh, Knl, Vh, Vl);
    CP_COMMIT();

    CP_WAIT1();
    __syncthreads();

    uint32_t qfh[4][4], qfl[4][4];
    {
        int rA = w * 16 + (lane & 15);
#pragma unroll
        for (int kk = 0; kk < 4; kk++) {
            int cc = kk * 2 + (lane >> 4);
            uint32_t so = (uint32_t)(rA * 128 + ((cc ^ (rA & 7)) << 4));
            ldsm_x4(sQ + so,        qfh[kk][0], qfh[kk][1], qfh[kk][2], qfh[kk][3]);
            ldsm_x4(sQ + 8192 + so, qfl[kk][0], qfl[kk][1], qfl[kk][2], qfl[kk][3]);
        }
    }

    float o[8][4];
#pragma unroll
    for (int nf = 0; nf < 8; nf++)
#pragma unroll
        for (int j = 0; j < 4; j++) o[nf][j] = 0.0f;
    float m0 = -1e30f, m1 = -1e30f, l0 = 0.0f, l1 = 0.0f;

    const int rl0 = w * 16 + (lane >> 2);         // local row 0..63
    const int rl1 = rl0 + 8;
    const int rg0 = qt * 64 + rl0, rg1 = qt * 64 + rl1;

    for (int kt = kt0; kt < kt1; kt++) {
        if (kt > kt0) { CP_WAIT1(); __syncthreads(); }
        const uint32_t sb = sQ + 16384 + (kt & 1) * STAGE;

        float s[8][4];
#pragma unroll
        for (int nf = 0; nf < 8; nf++)
#pragma unroll
            for (int j = 0; j < 4; j++) s[nf][j] = 0.0f;
        fa_compute_S(s, sb, sb + 8192, qfh, qfl, lane);

        {
            float sn[8][4];
#pragma unroll
            for (int nf = 0; nf < 8; nf++)
#pragma unroll
                for (int j = 0; j < 4; j++) sn[nf][j] = 0.0f;
            fa_compute_S(sn, sb + 32768, sb + 40960, qfh, qfl, lane);
            if (rg0 >= CTX) {
#pragma unroll
                for (int nf = 0; nf < 8; nf++) { s[nf][0] = sn[nf][0]; s[nf][1] = sn[nf][1]; }
            }
            if (rg1 >= CTX) {
#pragma unroll
                for (int nf = 0; nf < 8; nf++) { s[nf][2] = sn[nf][2]; s[nf][3] = sn[nf][3]; }
            }
        }

        if (kt == qt) {
#pragma unroll
            for (int nf = 0; nf < 8; nf++) {
                int c0 = kt * 64 + nf * 8 + (lane & 3) * 2;
                if (c0     > rg0) s[nf][0] = -1e30f;
                if (c0 + 1 > rg0) s[nf][1] = -1e30f;
                if (c0     > rg1) s[nf][2] = -1e30f;
                if (c0 + 1 > rg1) s[nf][3] = -1e30f;
            }
        }

        float mr0 = -1e30f, mr1 = -1e30f;
#pragma unroll
        for (int nf = 0; nf < 8; nf++) {
            mr0 = fmaxf(mr0, fmaxf(s[nf][0], s[nf][1]));
            mr1 = fmaxf(mr1, fmaxf(s[nf][2], s[nf][3]));
        }
        mr0 = fmaxf(mr0, __shfl_xor_sync(0xffffffffu, mr0, 1));
        mr0 = fmaxf(mr0, __shfl_xor_sync(0xffffffffu, mr0, 2));
        mr1 = fmaxf(mr1, __shfl_xor_sync(0xffffffffu, mr1, 1));
        mr1 = fmaxf(mr1, __shfl_xor_sync(0xffffffffu, mr1, 2));

        float mn0 = fmaxf(m0, mr0), mn1 = fmaxf(m1, mr1);
        float sc0 = exp2f(m0 - mn0), sc1 = exp2f(m1 - mn1);
        m0 = mn0; m1 = mn1;
        l0 *= sc0; l1 *= sc1;
#pragma unroll
        for (int nf = 0; nf < 8; nf++) {
            o[nf][0] *= sc0; o[nf][1] *= sc0;
            o[nf][2] *= sc1; o[nf][3] *= sc1;
        }

        uint32_t pF[4][4];
        float sum0 = 0.0f, sum1 = 0.0f;
#pragma unroll
        for (int nf = 0; nf < 8; nf++) {
            float p0 = exp2f(s[nf][0] - m0), p1 = exp2f(s[nf][1] - m0);
            float p2 = exp2f(s[nf][2] - m1), p3 = exp2f(s[nf][3] - m1);
            sum0 += p0 + p1; sum1 += p2 + p3;
            int kk = nf >> 1;
            int off = (nf & 1) * 2;
            pF[kk][off + 0] = pack_f16x2(p0, p1);
            pF[kk][off + 1] = pack_f16x2(p2, p3);
        }
        sum0 += __shfl_xor_sync(0xffffffffu, sum0, 1);
        sum0 += __shfl_xor_sync(0xffffffffu, sum0, 2);
        sum1 += __shfl_xor_sync(0xffffffffu, sum1, 1);
        sum1 += __shfl_xor_sync(0xffffffffu, sum1, 2);
        l0 += sum0; l1 += sum1;

        const uint32_t sVh = sb + 16384, sVl = sb + 24576;
#pragma unroll
        for (int kk = 0; kk < 4; kk++) {
            uint32_t vh[8][2], vl[8][2];
            int key0 = kk * 16 + (lane & 7) + ((lane >> 3) & 1) * 8;
#pragma unroll
            for (int nb = 0; nb < 4; nb++) {
                int chunk = nb * 2 + (lane >> 4);
                uint32_t so = (uint32_t)(key0 * 128 + ((chunk ^ (key0 & 7)) << 4));
                ldsm_x4t(sVh + so, vh[nb*2][0], vh[nb*2][1], vh[nb*2+1][0], vh[nb*2+1][1]);
                ldsm_x4t(sVl + so, vl[nb*2][0], vl[nb*2][1], vl[nb*2+1][0], vl[nb*2+1][1]);
            }
#pragma unroll
            for (int nf = 0; nf < 8; nf++) {
                mma16816h(o[nf], pF[kk], vh[nf]);
                mma16816h(o[nf], pF[kk], vl[nf]);
            }
        }

        __syncthreads();
        if (kt + 2 < kt1)
            fa_load_stage<true>(sQ + 16384 + (kt & 1) * STAGE, kt + 2, kvh, tid,
                                Kbh, Kbl, Knh, Knl, Vh, Vl);
        CP_COMMIT();
    }

    // write unnormalized partials
    const int hb = (split * NH + h) * 64;
#pragma unroll
    for (int nf = 0; nf < 8; nf++) {
        int col = nf * 8 + (lane & 3) * 2;
        *(float2*)&pO[(size_t)(hb + rl0) * 64 + col] = make_float2(o[nf][0], o[nf][1]);
        *(float2*)&pO[(size_t)(hb + rl1) * 64 + col] = make_float2(o[nf][2], o[nf][3]);
    }
    if ((lane & 3) == 0) {
        pm[hb + rl0] = m0; pl[hb + rl0] = l0;
        pm[hb + rl1] = m1; pl[hb + rl1] = l1;
    }
}

// ---- merge dual partials -> fp16 hi/lo attn output (exact reassociation) --
__global__ __launch_bounds__(256)
void dual_merge(const float* __restrict__ pO, const float* __restrict__ pm,
                const float* __restrict__ pl,
                __half* __restrict__ aHf, __half* __restrict__ aLf)
{
    int idx = blockIdx.x * 256 + threadIdx.x;     // 64*32*32 = 65536 dim-pairs
    if (idx >= 64 * NH * 32) return;
    int dp = idx & 31;                             // dim pair 0..31
    int h  = (idx >> 5) & 31;
    int rl = idx >> 10;                            // local row 0..63

    float m[DSPLIT], l[DSPLIT];
#pragma unroll
    for (int i = 0; i < DSPLIT; i++) {
        m[i] = pm[(i * NH + h) * 64 + rl];
        l[i] = pl[(i * NH + h) * 64 + rl];
    }
    float M = m[0];
#pragma unroll
    for (int i = 1; i < DSPLIT; i++) M = fmaxf(M, m[i]);
    float wgt[DSPLIT], L = 0.0f;
#pragma unroll
    for (int i = 0; i < DSPLIT; i++) { wgt[i] = exp2f(m[i] - M); L += l[i] * wgt[i]; }

    float o0 = 0.0f, o1 = 0.0f;
#pragma unroll
    for (int i = 0; i < DSPLIT; i++) {
        float2 v = *(const float2*)&pO[(size_t)((i * NH + h) * 64 + rl) * 64 + dp * 2];
        o0 += v.x * wgt[i];
        o1 += v.y * wgt[i];
    }
    float inv = 1.0f / L;
    o0 *= inv; o1 *= inv;

    size_t off = (size_t)((S - 64) + rl) * HID + h * 64 + dp * 2;
    float r0 = __half2float(__float2half_rn(o0));
    float r1 = __half2float(__float2half_rn(o1));
    *(uint32_t*)&aHf[off] = pack_f16x2(o0, o1);
    *(uint32_t*)&aLf[off] = pack_f16x2(o0 - r0, o1 - r1);
}

// ---------------- launch ----------------
extern "C" void kernel_launch(void* const* d_in, const int* in_sizes, int n_in,
                              void* d_out, int out_size)
{
    const float* hidden = (const float*)d_in[0];
    const float* Wq = (const float*)d_in[3];
    const float* Wk = (const float*)d_in[4];
    const float* Wv = (const float*)d_in[5];
    const float* Wo = (const float*)d_in[6];
    float* out = (float*)d_out;

    float *qB, *kB, *vB;
    cudaGetSymbolAddress((void**)&qB,  g_Q);
    cudaGetSymbolAddress((void**)&kB,  g_K);
    cudaGetSymbolAddress((void**)&vB,  g_V);

    bf16 *hH,*hL,*WqH,*WqL,*WkH,*WkL,*WvH,*WvL;
    cudaGetSymbolAddress((void**)&hH,  g_hH);  cudaGetSymbolAddress((void**)&hL,  g_hL);
    cudaGetSymbolAddress((void**)&WqH, g_WqH); cudaGetSymbolAddress((void**)&WqL, g_WqL);
    cudaGetSymbolAddress((void**)&WkH, g_WkH); cudaGetSymbolAddress((void**)&WkL, g_WkL);
    cudaGetSymbolAddress((void**)&WvH, g_WvH); cudaGetSymbolAddress((void**)&WvL, g_WvL);

    __half *WoF, *aHf, *aLf;
    cudaGetSymbolAddress((void**)&WoF, g_WoF);
    cudaGetSymbolAddress((void**)&aHf, g_aHf);
    cudaGetSymbolAddress((void**)&aLf, g_aLf);

    bf16 *Qh,*Ql,*bKh,*bKl,*nKh,*nKl;
    __half *Vh,*Vl;
    cudaGetSymbolAddress((void**)&Qh,  g_Qh);  cudaGetSymbolAddress((void**)&Ql,  g_Ql);
    cudaGetSymbolAddress((void**)&bKh, g_bKh); cudaGetSymbolAddress((void**)&bKl, g_bKl);
    cudaGetSymbolAddress((void**)&nKh, g_nKh); cudaGetSymbolAddress((void**)&nKl, g_nKl);
    cudaGetSymbolAddress((void**)&Vh,  g_Vh);  cudaGetSymbolAddress((void**)&Vl,  g_Vl);

    float *pO, *pm, *pl;
    cudaGetSymbolAddress((void**)&pO, g_pO);
    cudaGetSymbolAddress((void**)&pm, g_pm);
    cudaGetSymbolAddress((void**)&pl, g_pl);

    cudaFuncSetAttribute(qkv_gemm, cudaFuncAttributeMaxDynamicSharedMemorySize, SM_TOTAL);
    cudaFuncSetAttribute(wo_gemm2, cudaFuncAttributeMaxDynamicSharedMemorySize, SM_TOTAL2);
    const int FA_SMEM_N = 16384 + 2*32768;   // 81920
    const int FA_SMEM_D = 16384 + 2*49152;   // 114688
    cudaFuncSetAttribute(flash_main, cudaFuncAttributeMaxDynamicSharedMemorySize, FA_SMEM_N);
    cudaFuncSetAttribute(flash_dual_split, cudaFuncAttributeMaxDynamicSharedMemorySize, FA_SMEM_D);

    // all 5 input conversions in one launch
    const int TOT4 = 1048576*3 + 262144*2;   // float4 units
    split_all_kernel<<<(TOT4/4 + 255)/256, 256>>>(hidden, Wq, Wk, Wv, Wo,
                                                  hH, hL, WqH, WqL, WkH, WkL,
                                                  WvH, WvL, WoF);

    qkv_gemm<<<dim3(24, 16), 256, SM_TOTAL>>>(hH, hL, WqH, WqL, WkH, WkL, WvH, WvL,
                                              qB, kB, vB);

    rope_split_kernel<<<S, 256>>>(qB, kB, vB, Qh, Ql, bKh, bKl, nKh, nKl, Vh, Vl);

    // boundary tile via split-K (128 CTAs, one wave)
    flash_dual_split<<<dim3(DSPLIT, NH), 128, FA_SMEM_D>>>(Qh, Ql, bKh, bKl, nKh, nKl,
                                                           Vh, Vl, pO, pm, pl);
    // main tiles 0..30, heavy first
    flash_main<<<dim3(S/64 - 1, NH), 128, FA_SMEM_N>>>(Qh, Ql, bKh, bKl, Vh, Vl, aHf, aLf);
    // exact merge of dual partials
    dual_merge<<<(64*NH*32 + 255)/256, 256>>>(pO, pm, pl, aHf, aLf);

    // 2-pass fp16 Wo GEMM into d_out
    wo_gemm2<<<dim3(16, 16), 256, SM_TOTAL2>>>(aHf, aLf, WoF, out);
}

// round 14
// speedup vs baseline: 1.4167x; 1.0364x over previous
#include <cuda_runtime.h>
#include <cuda_bf16.h>
#include <cuda_fp16.h>
#include <cstdint>

#define S     2048
#define HID   2048
#define NH    32
#define NKV   8
#define HD    64
#define KVDIM (NKV*HD)   // 512
#define CTX   (S-10)     // 2038: rows >= CTX use narrow rope

typedef unsigned long long ull;
typedef __nv_bfloat16 bf16;

__device__ __forceinline__ uint32_t smem_u32(const void* p) {
    uint32_t a;
    asm("{ .reg .u64 t; cvta.to.shared.u64 t, %1; cvt.u32.u64 %0, t; }" : "=r"(a) : "l"(p));
    return a;
}

// ---------------- mma.sync primitives (compute_103-safe) ----------------
__device__ __forceinline__ void cp16(uint32_t s, const void* g) {
    asm volatile("cp.async.cg.shared.global [%0], [%1], 16;" :: "r"(s), "l"(g));
}
#define CP_COMMIT() asm volatile("cp.async.commit_group;" ::: "memory")
#define CP_WAIT1()  asm volatile("cp.async.wait_group 1;" ::: "memory")

__device__ __forceinline__ void ldsm_x4(uint32_t addr, uint32_t& r0, uint32_t& r1,
                                        uint32_t& r2, uint32_t& r3) {
    asm volatile("ldmatrix.sync.aligned.m8n8.x4.shared.b16 {%0,%1,%2,%3}, [%4];"
                 : "=r"(r0), "=r"(r1), "=r"(r2), "=r"(r3) : "r"(addr));
}
__device__ __forceinline__ void ldsm_x4t(uint32_t addr, uint32_t& r0, uint32_t& r1,
                                         uint32_t& r2, uint32_t& r3) {
    asm volatile("ldmatrix.sync.aligned.m8n8.x4.trans.shared.b16 {%0,%1,%2,%3}, [%4];"
                 : "=r"(r0), "=r"(r1), "=r"(r2), "=r"(r3) : "r"(addr));
}
__device__ __forceinline__ void mma16816(float* c, const uint32_t* a, const uint32_t* b) {
    asm volatile(
        "mma.sync.aligned.m16n8k16.row.col.f32.bf16.bf16.f32 "
        "{%0,%1,%2,%3}, {%4,%5,%6,%7}, {%8,%9}, {%0,%1,%2,%3};"
        : "+f"(c[0]), "+f"(c[1]), "+f"(c[2]), "+f"(c[3])
        : "r"(a[0]), "r"(a[1]), "r"(a[2]), "r"(a[3]), "r"(b[0]), "r"(b[1]));
}
__device__ __forceinline__ void mma16816h(float* c, const uint32_t* a, const uint32_t* b) {
    asm volatile(
        "mma.sync.aligned.m16n8k16.row.col.f32.f16.f16.f32 "
        "{%0,%1,%2,%3}, {%4,%5,%6,%7}, {%8,%9}, {%0,%1,%2,%3};"
        : "+f"(c[0]), "+f"(c[1]), "+f"(c[2]), "+f"(c[3])
        : "r"(a[0]), "r"(a[1]), "r"(a[2]), "r"(a[3]), "r"(b[0]), "r"(b[1]));
}
__device__ __forceinline__ uint32_t pack_bf16x2(float lo, float hi) {
    uint32_t r; asm("cvt.rn.bf16x2.f32 %0, %1, %2;" : "=r"(r) : "f"(hi), "f"(lo));
    return r;
}
__device__ __forceinline__ uint32_t pack_f16x2(float lo, float hi) {
    uint32_t r; asm("cvt.rn.f16x2.f32 %0, %1, %2;" : "=r"(r) : "f"(hi), "f"(lo));
    return r;
}

// ---------------- scratch (static device globals; no allocs) ----------------
__device__ float g_Q   [S*HID];
__device__ float g_K   [S*KVDIM];
__device__ float g_V   [S*KVDIM];
__device__ bf16 g_hH[S*HID],     g_hL[S*HID];
__device__ bf16 g_WqH[HID*HID],  g_WqL[HID*HID];
__device__ bf16 g_WkH[KVDIM*HID],g_WkL[KVDIM*HID];
__device__ bf16 g_WvH[KVDIM*HID],g_WvL[KVDIM*HID];
__device__ __half g_WoF[HID*HID];                  // Wo in fp16 (hi only)
__device__ __half g_aHf[S*HID],  g_aLf[S*HID];     // attn out fp16 hi/lo
__device__ bf16 g_Qh[S*HID],    g_Ql[S*HID];
__device__ bf16 g_bKh[S*KVDIM], g_bKl[S*KVDIM];
__device__ bf16 g_nKh[S*KVDIM], g_nKl[S*KVDIM];
__device__ __half g_Vh[S*KVDIM], g_Vl[S*KVDIM];    // fp16 split of V
// dual split-K partials: [split][head][row 0..63][dim 0..63] + m/l
#define DSPLIT 4
#define DTILES (32/DSPLIT)   // 8 key tiles per split
__device__ float g_pO[DSPLIT*NH*64*64];
__device__ float g_pm[DSPLIT*NH*64];
__device__ float g_pl[DSPLIT*NH*64];

// ---------------- fp32 -> bf16 hi/lo split ----------------
__device__ __forceinline__ void split_body(const float* __restrict__ x,
                                           bf16* __restrict__ hi, bf16* __restrict__ lo,
                                           int i)
{
    float4 v = ((const float4*)x)[i];
    bf16 h0 = __float2bfloat16(v.x);
    bf16 h1 = __float2bfloat16(v.y);
    bf16 h2 = __float2bfloat16(v.z);
    bf16 h3 = __float2bfloat16(v.w);
    __nv_bfloat162 H0 = __nv_bfloat162(h0, h1), H1 = __nv_bfloat162(h2, h3);
    __nv_bfloat162 L0 = __nv_bfloat162(__float2bfloat16(v.x - __bfloat162float(h0)),
                                       __float2bfloat16(v.y - __bfloat162float(h1)));
    __nv_bfloat162 L1 = __nv_bfloat162(__float2bfloat16(v.z - __bfloat162float(h2)),
                                       __float2bfloat16(v.w - __bfloat162float(h3)));
    ((__nv_bfloat162*)hi)[i*2+0] = H0; ((__nv_bfloat162*)hi)[i*2+1] = H1;
    ((__nv_bfloat162*)lo)[i*2+0] = L0; ((__nv_bfloat162*)lo)[i*2+1] = L1;
}

// merged split of hidden/Wq/Wk/Wv (bf16 hi/lo) + Wo (fp16 hi), 4 float4/thread.
__global__ __launch_bounds__(256)
void split_all_kernel(const float* __restrict__ hid, const float* __restrict__ Wq,
                      const float* __restrict__ Wk,  const float* __restrict__ Wv,
                      const float* __restrict__ Wo,
                      bf16* __restrict__ hH, bf16* __restrict__ hL,
                      bf16* __restrict__ qH, bf16* __restrict__ qL,
                      bf16* __restrict__ kH, bf16* __restrict__ kL,
                      bf16* __restrict__ vH, bf16* __restrict__ vL,
                      __half* __restrict__ oF)
{
    int g0 = (blockIdx.x * 256 + threadIdx.x) * 4;   // region bounds all %4==0
    const int R0 = 1048576, R1 = R0 + 1048576, R2 = R1 + 262144, R3 = R2 + 262144;
    const int TOT = R3 + 1048576;
    if (g0 >= TOT) return;
    if (g0 >= R3) {
#pragma unroll
        for (int k = 0; k < 4; k++) {
            int i = g0 - R3 + k;
            float4 v = ((const float4*)Wo)[i];
            ((__half2*)oF)[i*2+0] = __half2(__float2half_rn(v.x), __float2half_rn(v.y));
            ((__half2*)oF)[i*2+1] = __half2(__float2half_rn(v.z), __float2half_rn(v.w));
        }
        return;
    }
    const float* src; bf16 *dh, *dl; int rb;
    if (g0 < R0)      { src = hid; dh = hH; dl = hL; rb = 0;  }
    else if (g0 < R1) { src = Wq;  dh = qH; dl = qL; rb = R0; }
    else if (g0 < R2) { src = Wk;  dh = kH; dl = kL; rb = R1; }
    else              { src = Wv;  dh = vH; dl = vL; rb = R2; }
#pragma unroll
    for (int k = 0; k < 4; k++) split_body(src, dh, dl, g0 - rb + k);
}

// ---------------- mma.sync split-bf16 GEMM core (3-pass, unchanged) ----
#define STG      16384
#define SM_STAGE (4*STG)          // 64 KB
#define SM_TOTAL (2*SM_STAGE)     // 128 KB

__device__ __forceinline__ void g_load_stage(
    uint32_t sbuf,
    const bf16* __restrict__ Ah, const bf16* __restrict__ Al,
    const bf16* __restrict__ Bh, const bf16* __restrict__ Bl,
    int mBase, int nBase, int Kdim, int k0, int tid)
{
#pragma unroll
    for (int i = 0; i < 4; i++) {
        int u = i * 256 + tid;
        int r = u >> 3, c = u & 7;
        uint32_t so = (uint32_t)(r * 128 + ((c ^ (r & 7)) << 4));
        size_t eoffA = (size_t)(mBase + r) * Kdim + k0 + c * 8;
        size_t eoffB = (size_t)(nBase + r) * Kdim + k0 + c * 8;
        cp16(sbuf +          so, Ah + eoffA);
        cp16(sbuf +   STG  + so, Al + eoffA);
        cp16(sbuf + 2*STG  + so, Bh + eoffB);
        cp16(sbuf + 3*STG  + so, Bl + eoffB);
    }
}

__device__ __forceinline__ void gemm_body(
    const bf16* __restrict__ Ah, const bf16* __restrict__ Al,
    const bf16* __restrict__ Bh, const bf16* __restrict__ Bl,
    float* __restrict__ C, int Ntot, int Kdim, int mBase, int nBase, uint32_t sb)
{
    const int tid  = threadIdx.x;
    const int lane = tid & 31;
    const int wid  = tid >> 5;
    const int wm   = wid & 1;
    const int wn   = wid >> 1;

    float acc[4][4][4];
#pragma unroll
    for (int i = 0; i < 4; i++)
#pragma unroll
        for (int j = 0; j < 4; j++)
#pragma unroll
            for (int k = 0; k < 4; k++) acc[i][j][k] = 0.0f;

    const int NC = Kdim >> 6;

    g_load_stage(sb,            Ah, Al, Bh, Bl, mBase, nBase, Kdim, 0,  tid);
    CP_COMMIT();
    g_load_stage(sb + SM_STAGE, Ah, Al, Bh, Bl, mBase, nBase, Kdim, 64, tid);
    CP_COMMIT();

    const int aRow = wm * 64;
    const int bRow = wn * 32;

    for (int c = 0; c < NC; c++) {
        CP_WAIT1();
        __syncthreads();
        const uint32_t sbuf = sb + (c & 1) * SM_STAGE;
        const uint32_t sAh = sbuf, sAl = sbuf + STG, sBh = sbuf + 2*STG, sBl = sbuf + 3*STG;

#pragma unroll
        for (int ks = 0; ks < 4; ks++) {
            uint32_t aH[4][4], aL[4][4], bH[4][2], bL[4][2];
            {
                int rA = aRow + (lane & 15);
                int ccA = ks * 2 + (lane >> 4);
#pragma unroll
                for (int mf = 0; mf < 4; mf++) {
                    int r = rA + mf * 16;
                    uint32_t so = (uint32_t)(r * 128 + ((ccA ^ (r & 7)) << 4));
                    ldsm_x4(sAh + so, aH[mf][0], aH[mf][1], aH[mf][2], aH[mf][3]);
                    ldsm_x4(sAl + so, aL[mf][0], aL[mf][1], aL[mf][2], aL[mf][3]);
                }
            }
            {
                int rB0 = bRow + (lane & 7) + ((lane >> 4) << 3);
                int ccB = ks * 2 + ((lane >> 3) & 1);
#pragma unroll
                for (int nf2 = 0; nf2 < 2; nf2++) {
                    int r = rB0 + nf2 * 16;
                    uint32_t so = (uint32_t)(r * 128 + ((ccB ^ (r & 7)) << 4));
                    ldsm_x4(sBh + so, bH[nf2*2][0], bH[nf2*2][1], bH[nf2*2+1][0], bH[nf2*2+1][1]);
                    ldsm_x4(sBl + so, bL[nf2*2][0], bL[nf2*2][1], bL[nf2*2+1][0], bL[nf2*2+1][1]);
                }
            }
#pragma unroll
            for (int mf = 0; mf < 4; mf++)
#pragma unroll
                for (int nf = 0; nf < 4; nf++) {
                    mma16816(acc[mf][nf], aH[mf], bH[nf]);
                    mma16816(acc[mf][nf], aL[mf], bH[nf]);
                    mma16816(acc[mf][nf], aH[mf], bL[nf]);
                }
        }
        __syncthreads();
        if (c + 2 < NC)
            g_load_stage(sb + (c & 1) * SM_STAGE, Ah, Al, Bh, Bl,
                         mBase, nBase, Kdim, (c + 2) * 64, tid);
        CP_COMMIT();
    }

#pragma unroll
    for (int mf = 0; mf < 4; mf++) {
        int row0 = mBase + wm * 64 + mf * 16 + (lane >> 2);
#pragma unroll
        for (int nf = 0; nf < 4; nf++) {
            int col = nBase + wn * 32 + nf * 8 + (lane & 3) * 2;
            *(float2*)&C[(size_t)row0 * Ntot + col]       = make_float2(acc[mf][nf][0], acc[mf][nf][1]);
            *(float2*)&C[(size_t)(row0 + 8) * Ntot + col] = make_float2(acc[mf][nf][2], acc[mf][nf][3]);
        }
    }
}

__global__ __launch_bounds__(256)
void qkv_gemm(const bf16* __restrict__ Ah, const bf16* __restrict__ Al,
              const bf16* __restrict__ WqH, const bf16* __restrict__ WqL,
              const bf16* __restrict__ WkH, const bf16* __restrict__ WkL,
              const bf16* __restrict__ WvH, const bf16* __restrict__ WvL,
              float* __restrict__ Cq, float* __restrict__ Ck, float* __restrict__ Cv)
{
    extern __shared__ char dyns[];
    uint32_t sb = smem_u32(dyns);
    int bx = blockIdx.x, mBase = blockIdx.y * 128;
    if (bx < 16)      gemm_body(Ah, Al, WqH, WqL, Cq, HID,   HID, mBase, bx*128,      sb);
    else if (bx < 20) gemm_body(Ah, Al, WkH, WkL, Ck, KVDIM, HID, mBase, (bx-16)*128, sb);
    else              gemm_body(Ah, Al, WvH, WvL, Cv, KVDIM, HID, mBase, (bx-20)*128, sb);
}

// ---------------- 2-pass fp16 GEMM for Wo: C = (Ah+Al) @ Bh^T ----------
#define STG2      16384
#define SM_STAGE2 (3*STG2)        // 48 KB
#define SM_TOTAL2 (2*SM_STAGE2)   // 96 KB -> 2 CTAs/SM

__device__ __forceinline__ void g_load_stage2(
    uint32_t sbuf,
    const __half* __restrict__ Ah, const __half* __restrict__ Al,
    const __half* __restrict__ Bh,
    int mBase, int nBase, int Kdim, int k0, int tid)
{
#pragma unroll
    for (int i = 0; i < 4; i++) {
        int u = i * 256 + tid;
        int r = u >> 3, c = u & 7;
        uint32_t so = (uint32_t)(r * 128 + ((c ^ (r & 7)) << 4));
        size_t eoffA = (size_t)(mBase + r) * Kdim + k0 + c * 8;
        size_t eoffB = (size_t)(nBase + r) * Kdim + k0 + c * 8;
        cp16(sbuf +          so, Ah + eoffA);
        cp16(sbuf +   STG2 + so, Al + eoffA);
        cp16(sbuf + 2*STG2 + so, Bh + eoffB);
    }
}

__global__ __launch_bounds__(256, 2)
void wo_gemm2(const __half* __restrict__ Ah, const __half* __restrict__ Al,
              const __half* __restrict__ Bh, float* __restrict__ C)
{
    extern __shared__ char dyns[];
    const uint32_t sb = smem_u32(dyns);
    const int tid  = threadIdx.x;
    const int lane = tid & 31;
    const int wid  = tid >> 5;
    const int wm   = wid & 1;
    const int wn   = wid >> 1;
    const int mBase = blockIdx.y * 128, nBase = blockIdx.x * 128;

    float acc[4][4][4];
#pragma unroll
    for (int i = 0; i < 4; i++)
#pragma unroll
        for (int j = 0; j < 4; j++)
#pragma unroll
            for (int k = 0; k < 4; k++) acc[i][j][k] = 0.0f;

    const int NC = HID >> 6;   // 32

    g_load_stage2(sb,             Ah, Al, Bh, mBase, nBase, HID, 0,  tid);
    CP_COMMIT();
    g_load_stage2(sb + SM_STAGE2, Ah, Al, Bh, mBase, nBase, HID, 64, tid);
    CP_COMMIT();

    const int aRow = wm * 64;
    const int bRow = wn * 32;

    for (int c = 0; c < NC; c++) {
        CP_WAIT1();
        __syncthreads();
        const uint32_t sbuf = sb + (c & 1) * SM_STAGE2;
        const uint32_t sAh = sbuf, sAl = sbuf + STG2, sBh = sbuf + 2*STG2;

#pragma unroll
        for (int ks = 0; ks < 4; ks++) {
            uint32_t aH[4][4], aL[4][4], bH[4][2];
            {
                int rA = aRow + (lane & 15);
                int ccA = ks * 2 + (lane >> 4);
#pragma unroll
                for (int mf = 0; mf < 4; mf++) {
                    int r = rA + mf * 16;
                    uint32_t so = (uint32_t)(r * 128 + ((ccA ^ (r & 7)) << 4));
                    ldsm_x4(sAh + so, aH[mf][0], aH[mf][1], aH[mf][2], aH[mf][3]);
                    ldsm_x4(sAl + so, aL[mf][0], aL[mf][1], aL[mf][2], aL[mf][3]);
                }
            }
            {
                int rB0 = bRow + (lane & 7) + ((lane >> 4) << 3);
                int ccB = ks * 2 + ((lane >> 3) & 1);
#pragma unroll
                for (int nf2 = 0; nf2 < 2; nf2++) {
                    int r = rB0 + nf2 * 16;
                    uint32_t so = (uint32_t)(r * 128 + ((ccB ^ (r & 7)) << 4));
                    ldsm_x4(sBh + so, bH[nf2*2][0], bH[nf2*2][1], bH[nf2*2+1][0], bH[nf2*2+1][1]);
                }
            }
#pragma unroll
            for (int mf = 0; mf < 4; mf++)
#pragma unroll
                for (int nf = 0; nf < 4; nf++) {
                    mma16816h(acc[mf][nf], aH[mf], bH[nf]);
                    mma16816h(acc[mf][nf], aL[mf], bH[nf]);
                }
        }
        __syncthreads();
        if (c + 2 < NC)
            g_load_stage2(sb + (c & 1) * SM_STAGE2, Ah, Al, Bh,
                          mBase, nBase, HID, (c + 2) * 64, tid);
        CP_COMMIT();
    }

#pragma unroll
    for (int mf = 0; mf < 4; mf++) {
        int row0 = mBase + wm * 64 + mf * 16 + (lane >> 2);
#pragma unroll
        for (int nf = 0; nf < 4; nf++) {
            int col = nBase + wn * 32 + nf * 8 + (lane & 3) * 2;
            *(float2*)&C[(size_t)row0 * HID + col]       = make_float2(acc[mf][nf][0], acc[mf][nf][1]);
            *(float2*)&C[(size_t)(row0 + 8) * HID + col] = make_float2(acc[mf][nf][2], acc[mf][nf][3]);
        }
    }
}

// ---------------- RoPE + split (float4-vectorized) --------------------------
__device__ __forceinline__ void split_w2(bf16* hp, bf16* lp, float x0, float x1) {
    bf16 h0 = __float2bfloat16(x0);
    bf16 h1 = __float2bfloat16(x1);
    *(__nv_bfloat162*)hp = __nv_bfloat162(h0, h1);
    *(__nv_bfloat162*)lp = __nv_bfloat162(__float2bfloat16(x0 - __bfloat162float(h0)),
                                          __float2bfloat16(x1 - __bfloat162float(h1)));
}

__global__ void rope_split_kernel(const float* __restrict__ Q, const float* __restrict__ K,
                                  const float* __restrict__ V,
                                  bf16* __restrict__ qh, bf16* __restrict__ ql,
                                  bf16* __restrict__ kbh, bf16* __restrict__ kbl,
                                  bf16* __restrict__ knh, bf16* __restrict__ knl,
                                  __half* __restrict__ vh, __half* __restrict__ vl)
{
    const int s = blockIdx.x;
    const int tid = threadIdx.x; // 256
    const bool narrowRow = (s >= CTX);
    const float QS = 1.4426950408889634f * 0.125f;   // log2(e)/sqrt(64)

    __shared__ float cb[32], sb[32], cn[32], sn[32];
    if (tid < 32) {
        double inv = pow(10000.0, -(double)tid / 32.0);
        double ab = (double)s * inv;
        double an = ((double)s * 0.25) * inv;
        cb[tid] = (float)cos(ab); sb[tid] = (float)sin(ab);
        cn[tid] = (float)cos(an); sn[tid] = (float)sin(an);
    }
    __syncthreads();

    {
        int p = tid;
        int h = p >> 3, d4 = (p & 7) * 4;
        size_t base = (size_t)s * HID + h * HD;
        float4 x1 = *(const float4*)&Q[base + d4];
        float4 x2 = *(const float4*)&Q[base + d4 + 32];
        const float* cc = narrowRow ? cn : cb;
        const float* ss = narrowRow ? sn : sb;
        float c0 = cc[d4], c1 = cc[d4+1], c2 = cc[d4+2], c3 = cc[d4+3];
        float s0 = ss[d4], s1 = ss[d4+1], s2 = ss[d4+2], s3 = ss[d4+3];
        split_w2(qh + base + d4,     ql + base + d4,
                 (x1.x*c0 - x2.x*s0)*QS, (x1.y*c1 - x2.y*s1)*QS);
        split_w2(qh + base + d4 + 2, ql + base + d4 + 2,
                 (x1.z*c2 - x2.z*s2)*QS, (x1.w*c3 - x2.w*s3)*QS);
        split_w2(qh + base + d4 + 32, ql + base + d4 + 32,
                 (x2.x*c0 + x1.x*s0)*QS, (x2.y*c1 + x1.y*s1)*QS);
        split_w2(qh + base + d4 + 34, ql + base + d4 + 34,
                 (x2.z*c2 + x1.z*s2)*QS, (x2.w*c3 + x1.w*s3)*QS);
    }
    if (tid < NKV * 8) {
        int p = tid;
        int h = p >> 3, d4 = (p & 7) * 4;
        size_t base = (size_t)s * KVDIM + h * HD;
        float4 x1 = *(const float4*)&K[base + d4];
        float4 x2 = *(const float4*)&K[base + d4 + 32];
        float cb0 = cb[d4], cb1 = cb[d4+1], cb2 = cb[d4+2], cb3 = cb[d4+3];
        float sb0 = sb[d4], sb1 = sb[d4+1], sb2 = sb[d4+2], sb3 = sb[d4+3];
        float cn0 = cn[d4], cn1 = cn[d4+1], cn2 = cn[d4+2], cn3 = cn[d4+3];
        float sn0 = sn[d4], sn1 = sn[d4+1], sn2 = sn[d4+2], sn3 = sn[d4+3];
        split_w2(kbh + base + d4,     kbl + base + d4,
                 x1.x*cb0 - x2.x*sb0, x1.y*cb1 - x2.y*sb1);
        split_w2(kbh + base + d4 + 2, kbl + base + d4 + 2,
                 x1.z*cb2 - x2.z*sb2, x1.w*cb3 - x2.w*sb3);
        split_w2(kbh + base + d4 + 32, kbl + base + d4 + 32,
                 x2.x*cb0 + x1.x*sb0, x2.y*cb1 + x1.y*sb1);
        split_w2(kbh + base + d4 + 34, kbl + base + d4 + 34,
                 x2.z*cb2 + x1.z*sb2, x2.w*cb3 + x1.w*sb3);
        split_w2(knh + base + d4,     knl + base + d4,
                 x1.x*cn0 - x2.x*sn0, x1.y*cn1 - x2.y*sn1);
        split_w2(knh + base + d4 + 2, knl + base + d4 + 2,
                 x1.z*cn2 - x2.z*sn2, x1.w*cn3 - x2.w*sn3);
        split_w2(knh + base + d4 + 32, knl + base + d4 + 32,
                 x2.x*cn0 + x1.x*sn0, x2.y*cn1 + x1.y*sn1);
        split_w2(knh + base + d4 + 34, knl + base + d4 + 34,
                 x2.z*cn2 + x1.z*sn2, x2.w*cn3 + x1.w*sn3);
    }
    if (tid < KVDIM / 4) {
        size_t base = (size_t)s * KVDIM + tid * 4;
        float4 v = *(const float4*)&V[base];
        __half h0 = __float2half_rn(v.x), h1 = __float2half_rn(v.y);
        __half h2 = __float2half_rn(v.z), h3 = __float2half_rn(v.w);
        *(__half2*)(vh + base)     = __half2(h0, h1);
        *(__half2*)(vh + base + 2) = __half2(h2, h3);
        *(__half2*)(vl + base)     = __half2(__float2half_rn(v.x - __half2float(h0)),
                                             __float2half_rn(v.y - __half2float(h1)));
        *(__half2*)(vl + base + 2) = __half2(__float2half_rn(v.z - __half2float(h2)),
                                             __float2half_rn(v.w - __half2float(h3)));
    }
}

// ---------------- Tensor-core flash attention (fp16 2-pass PV) -------------
template<bool DUAL>
__device__ __forceinline__ void fa_load_stage(
    uint32_t sb, int kt, int kvh, int tid,
    const bf16* __restrict__ Kbh, const bf16* __restrict__ Kbl,
    const bf16* __restrict__ Knh, const bf16* __restrict__ Knl,
    const __half* __restrict__ Vh, const __half* __restrict__ Vl)
{
#pragma unroll
    for (int i = 0; i < 4; i++) {
        int u = i * 128 + tid;      // 0..511
        int r = u >> 3, c = u & 7;
        uint32_t so = (uint32_t)(r * 128 + ((c ^ (r & 7)) << 4));
        size_t go = (size_t)(kt * 64 + r) * KVDIM + kvh * 64 + c * 8;
        cp16(sb +         so, Kbh + go);
        cp16(sb + 8192  + so, Kbl + go);
        cp16(sb + 16384 + so, Vh + go);
        cp16(sb + 24576 + so, Vl + go);
        if (DUAL) {
            cp16(sb + 32768 + so, Knh + go);
            cp16(sb + 40960 + so, Knl + go);
        }
    }
}

__device__ __forceinline__ void fa_compute_S(
    float s[8][4], uint32_t sKh, uint32_t sKl,
    const uint32_t qfh[4][4], const uint32_t qfl[4][4], int lane)
{
#pragma unroll
    for (int kk = 0; kk < 4; kk++) {
        uint32_t kh[8][2], kl[8][2];
        int rB0 = (lane & 7) + ((lane >> 4) << 3);
        int ccB = kk * 2 + ((lane >> 3) & 1);
#pragma unroll
        for (int nb = 0; nb < 4; nb++) {
            int r = nb * 16 + rB0;
            uint32_t so = (uint32_t)(r * 128 + ((ccB ^ (r & 7)) << 4));
            ldsm_x4(sKh + so, kh[nb*2][0], kh[nb*2][1], kh[nb*2+1][0], kh[nb*2+1][1]);
            ldsm_x4(sKl + so, kl[nb*2][0], kl[nb*2][1], kl[nb*2+1][0], kl[nb*2+1][1]);
        }
#pragma unroll
        for (int nf = 0; nf < 8; nf++) {
            mma16816(s[nf], qfh[kk], kh[nf]);
            mma16816(s[nf], qfl[kk], kh[nf]);
            mma16816(s[nf], qfh[kk], kl[nf]);
        }
    }
}

// load Q tile fragments (shared by both paths)
__device__ __forceinline__ void fa_load_qfrag(
    uint32_t sQ, const bf16* __restrict__ Qh, const bf16* __restrict__ Ql,
    int qt, int h, int tid, int lane, int w,
    uint32_t qfh[4][4], uint32_t qfl[4][4])
{
    const bf16* gQh = Qh + (size_t)(qt * 64) * HID + h * 64;
    const bf16* gQl = Ql + (size_t)(qt * 64) * HID + h * 64;
#pragma unroll
    for (int i = 0; i < 4; i++) {
        int u = i * 128 + tid;
        int r = u >> 3, c = u & 7;
        uint32_t so = (uint32_t)(r * 128 + ((c ^ (r & 7)) << 4));
        cp16(sQ +        so, gQh + (size_t)r * HID + c * 8);
        cp16(sQ + 8192 + so, gQl + (size_t)r * HID + c * 8);
    }
    // NOTE: caller issues commits/waits around K stage loads; Q is in group 0
    (void)qfh; (void)qfl;
}

// ---- softmax + PV step (shared, boost/selected scores already in s) ----
struct FaState {
    float o[8][4];
    float m0, m1, l0, l1;
};

__device__ __forceinline__ void fa_softmax_pv(
    FaState& st, float s[8][4], uint32_t sb, int lane)
{
    float mr0 = -1e30f, mr1 = -1e30f;
#pragma unroll
    for (int nf = 0; nf < 8; nf++) {
        mr0 = fmaxf(mr0, fmaxf(s[nf][0], s[nf][1]));
        mr1 = fmaxf(mr1, fmaxf(s[nf][2], s[nf][3]));
    }
    mr0 = fmaxf(mr0, __shfl_xor_sync(0xffffffffu, mr0, 1));
    mr0 = fmaxf(mr0, __shfl_xor_sync(0xffffffffu, mr0, 2));
    mr1 = fmaxf(mr1, __shfl_xor_sync(0xffffffffu, mr1, 1));
    mr1 = fmaxf(mr1, __shfl_xor_sync(0xffffffffu, mr1, 2));

    float mn0 = fmaxf(st.m0, mr0), mn1 = fmaxf(st.m1, mr1);
    float sc0 = exp2f(st.m0 - mn0), sc1 = exp2f(st.m1 - mn1);
    st.m0 = mn0; st.m1 = mn1;
    st.l0 *= sc0; st.l1 *= sc1;
#pragma unroll
    for (int nf = 0; nf < 8; nf++) {
        st.o[nf][0] *= sc0; st.o[nf][1] *= sc0;
        st.o[nf][2] *= sc1; st.o[nf][3] *= sc1;
    }

    uint32_t pF[4][4];
    float sum0 = 0.0f, sum1 = 0.0f;
#pragma unroll
    for (int nf = 0; nf < 8; nf++) {
        float p0 = exp2f(s[nf][0] - st.m0), p1 = exp2f(s[nf][1] - st.m0);
        float p2 = exp2f(s[nf][2] - st.m1), p3 = exp2f(s[nf][3] - st.m1);
        sum0 += p0 + p1; sum1 += p2 + p3;
        int kk = nf >> 1;
        int off = (nf & 1) * 2;
        pF[kk][off + 0] = pack_f16x2(p0, p1);
        pF[kk][off + 1] = pack_f16x2(p2, p3);
    }
    sum0 += __shfl_xor_sync(0xffffffffu, sum0, 1);
    sum0 += __shfl_xor_sync(0xffffffffu, sum0, 2);
    sum1 += __shfl_xor_sync(0xffffffffu, sum1, 1);
    sum1 += __shfl_xor_sync(0xffffffffu, sum1, 2);
    st.l0 += sum0; st.l1 += sum1;

    const uint32_t sVh = sb + 16384, sVl = sb + 24576;
#pragma unroll
    for (int kk = 0; kk < 4; kk++) {
        uint32_t vh[8][2], vl[8][2];
        int key0 = kk * 16 + (lane & 7) + ((lane >> 3) & 1) * 8;
#pragma unroll
        for (int nb = 0; nb < 4; nb++) {
            int chunk = nb * 2 + (lane >> 4);
            uint32_t so = (uint32_t)(key0 * 128 + ((chunk ^ (key0 & 7)) << 4));
            ldsm_x4t(sVh + so, vh[nb*2][0], vh[nb*2][1], vh[nb*2+1][0], vh[nb*2+1][1]);
            ldsm_x4t(sVl + so, vl[nb*2][0], vl[nb*2][1], vl[nb*2+1][0], vl[nb*2+1][1]);
        }
#pragma unroll
        for (int nf = 0; nf < 8; nf++) {
            mma16816h(st.o[nf], pF[kk], vh[nf]);
            mma16816h(st.o[nf], pF[kk], vl[nf]);
        }
    }
}

// merged flash: blockIdx.x < DSPLIT -> dual split path; else main tile.
__global__ __launch_bounds__(128, 2)
void flash_all(const bf16* __restrict__ Qh, const bf16* __restrict__ Ql,
               const bf16* __restrict__ Kbh, const bf16* __restrict__ Kbl,
               const bf16* __restrict__ Knh, const bf16* __restrict__ Knl,
               const __half* __restrict__ Vh,  const __half* __restrict__ Vl,
               __half* __restrict__ aHf, __half* __restrict__ aLf,
               float* __restrict__ pO, float* __restrict__ pm,
               float* __restrict__ pl)
{
    extern __shared__ char dyn[];
    const uint32_t sQ = smem_u32(dyn);
    const int tid = threadIdx.x, lane = tid & 31, w = tid >> 5;
    const int h = blockIdx.y, kvh = h >> 2;
    const bool isDual = (blockIdx.x < DSPLIT);

    FaState st;
#pragma unroll
    for (int nf = 0; nf < 8; nf++)
#pragma unroll
        for (int j = 0; j < 4; j++) st.o[nf][j] = 0.0f;
    st.m0 = -1e30f; st.m1 = -1e30f; st.l0 = 0.0f; st.l1 = 0.0f;

    if (isDual) {
        // ---------------- dual split-K path (STAGE = 49152) ----------------
        constexpr int STAGE = 49152;
        const int split = blockIdx.x;
        const int qt = S/64 - 1;                      // 31
        const int kt0 = split * DTILES, kt1 = kt0 + DTILES;

        fa_load_qfrag(sQ, Qh, Ql, qt, h, tid, lane, w, nullptr, nullptr);
        fa_load_stage<true>(sQ + 16384, kt0, kvh, tid, Kbh, Kbl, Knh, Knl, Vh, Vl);
        CP_COMMIT();
        fa_load_stage<true>(sQ + 16384 + STAGE, kt0 + 1, kvh, tid, Kbh, Kbl, Knh, Knl, Vh, Vl);
        CP_COMMIT();
        CP_WAIT1();
        __syncthreads();

        uint32_t qfh[4][4], qfl[4][4];
        {
            int rA = w * 16 + (lane & 15);
#pragma unroll
            for (int kk = 0; kk < 4; kk++) {
                int cc = kk * 2 + (lane >> 4);
                uint32_t so = (uint32_t)(rA * 128 + ((cc ^ (rA & 7)) << 4));
                ldsm_x4(sQ + so,        qfh[kk][0], qfh[kk][1], qfh[kk][2], qfh[kk][3]);
                ldsm_x4(sQ + 8192 + so, qfl[kk][0], qfl[kk][1], qfl[kk][2], qfl[kk][3]);
            }
        }

        const int rl0 = w * 16 + (lane >> 2);
        const int rl1 = rl0 + 8;
        const int rg0 = qt * 64 + rl0, rg1 = qt * 64 + rl1;

        for (int kt = kt0; kt < kt1; kt++) {
            if (kt > kt0) { CP_WAIT1(); __syncthreads(); }
            const uint32_t sb = sQ + 16384 + (kt & 1) * STAGE;

            float s[8][4];
#pragma unroll
            for (int nf = 0; nf < 8; nf++)
#pragma unroll
                for (int j = 0; j < 4; j++) s[nf][j] = 0.0f;
            fa_compute_S(s, sb, sb + 8192, qfh, qfl, lane);

            {
                float sn[8][4];
#pragma unroll
                for (int nf = 0; nf < 8; nf++)
#pragma unroll
                    for (int j = 0; j < 4; j++) sn[nf][j] = 0.0f;
                fa_compute_S(sn, sb + 32768, sb + 40960, qfh, qfl, lane);
                if (rg0 >= CTX) {
#pragma unroll
                    for (int nf = 0; nf < 8; nf++) { s[nf][0] = sn[nf][0]; s[nf][1] = sn[nf][1]; }
                }
                if (rg1 >= CTX) {
#pragma unroll
                    for (int nf = 0; nf < 8; nf++) { s[nf][2] = sn[nf][2]; s[nf][3] = sn[nf][3]; }
                }
            }

            if (kt == qt) {
#pragma unroll
                for (int nf = 0; nf < 8; nf++) {
                    int c0 = kt * 64 + nf * 8 + (lane & 3) * 2;
                    if (c0     > rg0) s[nf][0] = -1e30f;
                    if (c0 + 1 > rg0) s[nf][1] = -1e30f;
                    if (c0     > rg1) s[nf][2] = -1e30f;
                    if (c0 + 1 > rg1) s[nf][3] = -1e30f;
                }
            }

            fa_softmax_pv(st, s, sb, lane);

            __syncthreads();
            if (kt + 2 < kt1)
                fa_load_stage<true>(sQ + 16384 + (kt & 1) * STAGE, kt + 2, kvh, tid,
                                    Kbh, Kbl, Knh, Knl, Vh, Vl);
            CP_COMMIT();
        }

        const int hb = (split * NH + h) * 64;
#pragma unroll
        for (int nf = 0; nf < 8; nf++) {
            int col = nf * 8 + (lane & 3) * 2;
            *(float2*)&pO[(size_t)(hb + rl0) * 64 + col] = make_float2(st.o[nf][0], st.o[nf][1]);
            *(float2*)&pO[(size_t)(hb + rl1) * 64 + col] = make_float2(st.o[nf][2], st.o[nf][3]);
        }
        if ((lane & 3) == 0) {
            pm[hb + rl0] = st.m0; pl[hb + rl0] = st.l0;
            pm[hb + rl1] = st.m1; pl[hb + rl1] = st.l1;
        }
        return;
    }

    // ---------------- main path (STAGE = 32768) ----------------
    {
        constexpr int STAGE = 32768;
        const int qt = (S/64 - 2) - ((int)blockIdx.x - DSPLIT);   // heavy first

        fa_load_qfrag(sQ, Qh, Ql, qt, h, tid, lane, w, nullptr, nullptr);
        fa_load_stage<false>(sQ + 16384, 0, kvh, tid, Kbh, Kbl, nullptr, nullptr, Vh, Vl);
        CP_COMMIT();
        if (qt >= 1)
            fa_load_stage<false>(sQ + 16384 + STAGE, 1, kvh, tid, Kbh, Kbl, nullptr, nullptr, Vh, Vl);
        CP_COMMIT();
        CP_WAIT1();
        __syncthreads();

        uint32_t qfh[4][4], qfl[4][4];
        {
            int rA = w * 16 + (lane & 15);
#pragma unroll
            for (int kk = 0; kk < 4; kk++) {
                int cc = kk * 2 + (lane >> 4);
                uint32_t so = (uint32_t)(rA * 128 + ((cc ^ (rA & 7)) << 4));
                ldsm_x4(sQ + so,        qfh[kk][0], qfh[kk][1], qfh[kk][2], qfh[kk][3]);
                ldsm_x4(sQ + 8192 + so, qfl[kk][0], qfl[kk][1], qfl[kk][2], qfl[kk][3]);
            }
        }

        const int rg0 = qt * 64 + w * 16 + (lane >> 2);
        const int rg1 = rg0 + 8;

        for (int kt = 0; kt <= qt; kt++) {
            if (kt) { CP_WAIT1(); __syncthreads(); }
            const uint32_t sb = sQ + 16384 + (kt & 1) * STAGE;

            float s[8][4];
#pragma unroll
            for (int nf = 0; nf < 8; nf++)
#pragma unroll
                for (int j = 0; j < 4; j++) s[nf][j] = 0.0f;
            fa_compute_S(s, sb, sb + 8192, qfh, qfl, lane);

            if (kt == qt) {
#pragma unroll
                for (int nf = 0; nf < 8; nf++) {
                    int c0 = kt * 64 + nf * 8 + (lane & 3) * 2;
                    if (c0     > rg0) s[nf][0] = -1e30f;
                    if (c0 + 1 > rg0) s[nf][1] = -1e30f;
                    if (c0     > rg1) s[nf][2] = -1e30f;
                    if (c0 + 1 > rg1) s[nf][3] = -1e30f;
                }
            }

            fa_softmax_pv(st, s, sb, lane);

            __syncthreads();
            if (kt + 2 <= qt)
                fa_load_stage<false>(sQ + 16384 + (kt & 1) * STAGE, kt + 2, kvh, tid,
                                     Kbh, Kbl, nullptr, nullptr, Vh, Vl);
            CP_COMMIT();
        }

        float inv0 = 1.0f / st.l0, inv1 = 1.0f / st.l1;
#pragma unroll
        for (int nf = 0; nf < 8; nf++) {
            int col = h * 64 + nf * 8 + (lane & 3) * 2;
            float x0 = st.o[nf][0]*inv0, x1 = st.o[nf][1]*inv0;
            float x2 = st.o[nf][2]*inv1, x3 = st.o[nf][3]*inv1;
            float r0 = __half2float(__float2half_rn(x0));
            float r1 = __half2float(__float2half_rn(x1));
            float r2 = __half2float(__float2half_rn(x2));
            float r3 = __half2float(__float2half_rn(x3));
            *(uint32_t*)&aHf[(size_t)rg0 * HID + col] = pack_f16x2(x0, x1);
            *(uint32_t*)&aLf[(size_t)rg0 * HID + col] = pack_f16x2(x0 - r0, x1 - r1);
            *(uint32_t*)&aHf[(size_t)rg1 * HID + col] = pack_f16x2(x2, x3);
            *(uint32_t*)&aLf[(size_t)rg1 * HID + col] = pack_f16x2(x2 - r2, x3 - r3);
        }
    }
}

// ---- merge dual partials -> fp16 hi/lo attn output (exact reassociation) --
__global__ __launch_bounds__(256)
void dual_merge(const float* __restrict__ pO, const float* __restrict__ pm,
                const float* __restrict__ pl,
                __half* __restrict__ aHf, __half* __restrict__ aLf)
{
    int idx = blockIdx.x * 256 + threadIdx.x;     // 64*32*32 = 65536 dim-pairs
    if (idx >= 64 * NH * 32) return;
    int dp = idx & 31;
    int h  = (idx >> 5) & 31;
    int rl = idx >> 10;

    float m[DSPLIT], l[DSPLIT];
#pragma unroll
    for (int i = 0; i < DSPLIT; i++) {
        m[i] = pm[(i * NH + h) * 64 + rl];
        l[i] = pl[(i * NH + h) * 64 + rl];
    }
    float M = m[0];
#pragma unroll
    for (int i = 1; i < DSPLIT; i++) M = fmaxf(M, m[i]);
    float wgt[DSPLIT], L = 0.0f;
#pragma unroll
    for (int i = 0; i < DSPLIT; i++) { wgt[i] = exp2f(m[i] - M); L += l[i] * wgt[i]; }

    float o0 = 0.0f, o1 = 0.0f;
#pragma unroll
    for (int i = 0; i < DSPLIT; i++) {
        float2 v = *(const float2*)&pO[(size_t)((i * NH + h) * 64 + rl) * 64 + dp * 2];
        o0 += v.x * wgt[i];
        o1 += v.y * wgt[i];
    }
    float inv = 1.0f / L;
    o0 *= inv; o1 *= inv;

    size_t off = (size_t)((S - 64) + rl) * HID + h * 64 + dp * 2;
    float r0 = __half2float(__float2half_rn(o0));
    float r1 = __half2float(__float2half_rn(o1));
    *(uint32_t*)&aHf[off] = pack_f16x2(o0, o1);
    *(uint32_t*)&aLf[off] = pack_f16x2(o0 - r0, o1 - r1);
}

// ---------------- launch ----------------
extern "C" void kernel_launch(void* const* d_in, const int* in_sizes, int n_in,
                              void* d_out, int out_size)
{
    const float* hidden = (const float*)d_in[0];
    const float* Wq = (const float*)d_in[3];
    const float* Wk = (const float*)d_in[4];
    const float* Wv = (const float*)d_in[5];
    const float* Wo = (const float*)d_in[6];
    float* out = (float*)d_out;

    float *qB, *kB, *vB;
    cudaGetSymbolAddress((void**)&qB,  g_Q);
    cudaGetSymbolAddress((void**)&kB,  g_K);
    cudaGetSymbolAddress((void**)&vB,  g_V);

    bf16 *hH,*hL,*WqH,*WqL,*WkH,*WkL,*WvH,*WvL;
    cudaGetSymbolAddress((void**)&hH,  g_hH);  cudaGetSymbolAddress((void**)&hL,  g_hL);
    cudaGetSymbolAddress((void**)&WqH, g_WqH); cudaGetSymbolAddress((void**)&WqL, g_WqL);
    cudaGetSymbolAddress((void**)&WkH, g_WkH); cudaGetSymbolAddress((void**)&WkL, g_WkL);
    cudaGetSymbolAddress((void**)&WvH, g_WvH); cudaGetSymbolAddress((void**)&WvL, g_WvL);

    __half *WoF, *aHf, *aLf;
    cudaGetSymbolAddress((void**)&WoF, g_WoF);
    cudaGetSymbolAddress((void**)&aHf, g_aHf);
    cudaGetSymbolAddress((void**)&aLf, g_aLf);

    bf16 *Qh,*Ql,*bKh,*bKl,*nKh,*nKl;
    __half *Vh,*Vl;
    cudaGetSymbolAddress((void**)&Qh,  g_Qh);  cudaGetSymbolAddress((void**)&Ql,  g_Ql);
    cudaGetSymbolAddress((void**)&bKh, g_bKh); cudaGetSymbolAddress((void**)&bKl, g_bKl);
    cudaGetSymbolAddress((void**)&nKh, g_nKh); cudaGetSymbolAddress((void**)&nKl, g_nKl);
    cudaGetSymbolAddress((void**)&Vh,  g_Vh);  cudaGetSymbolAddress((void**)&Vl,  g_Vl);

    float *pO, *pm, *pl;
    cudaGetSymbolAddress((void**)&pO, g_pO);
    cudaGetSymbolAddress((void**)&pm, g_pm);
    cudaGetSymbolAddress((void**)&pl, g_pl);

    cudaFuncSetAttribute(qkv_gemm, cudaFuncAttributeMaxDynamicSharedMemorySize, SM_TOTAL);
    cudaFuncSetAttribute(wo_gemm2, cudaFuncAttributeMaxDynamicSharedMemorySize, SM_TOTAL2);
    const int FA_SMEM_D = 16384 + 2*49152;   // 114688 (covers both paths)
    cudaFuncSetAttribute(flash_all, cudaFuncAttributeMaxDynamicSharedMemorySize, FA_SMEM_D);

    // all 5 input conversions in one launch
    const int TOT4 = 1048576*3 + 262144*2;   // float4 units
    split_all_kernel<<<(TOT4/4 + 255)/256, 256>>>(hidden, Wq, Wk, Wv, Wo,
                                                  hH, hL, WqH, WqL, WkH, WkL,
                                                  WvH, WvL, WoF);

    qkv_gemm<<<dim3(24, 16), 256, SM_TOTAL>>>(hH, hL, WqH, WqL, WkH, WkL, WvH, WvL,
                                              qB, kB, vB);

    rope_split_kernel<<<S, 256>>>(qB, kB, vB, Qh, Ql, bKh, bKl, nKh, nKl, Vh, Vl);

    // single flash launch: 4 dual-split CTAs first, then 31 main tiles (heavy first)
    flash_all<<<dim3(DSPLIT + S/64 - 1, NH), 128, FA_SMEM_D>>>(
        Qh, Ql, bKh, bKl, nKh, nKl, Vh, Vl, aHf, aLf, pO, pm, pl);
    // exact merge of dual partials
    dual_merge<<<(64*NH*32 + 255)/256, 256>>>(pO, pm, pl, aHf, aLf);

    // 2-pass fp16 Wo GEMM into d_out
    wo_gemm2<<<dim3(16, 16), 256, SM_TOTAL2>>>(aHf, aLf, WoF, out);
}

// round 15
// speedup vs baseline: 1.7069x; 1.2048x over previous
#include <cuda_runtime.h>
#include <cuda_bf16.h>
#include <cuda_fp16.h>
#include <cstdint>

#define S     2048
#define HID   2048
#define NH    32
#define NKV   8
#define HD    64
#define KVDIM (NKV*HD)   // 512
#define CTX   (S-10)     // 2038: rows >= CTX use narrow rope

typedef unsigned long long ull;
typedef __nv_bfloat16 bf16;

__device__ __forceinline__ uint32_t smem_u32(const void* p) {
    uint32_t a;
    asm("{ .reg .u64 t; cvta.to.shared.u64 t, %1; cvt.u32.u64 %0, t; }" : "=r"(a) : "l"(p));
    return a;
}

// ---------------- mma.sync primitives (compute_103-safe) ----------------
__device__ __forceinline__ void cp16(uint32_t s, const void* g) {
    asm volatile("cp.async.cg.shared.global [%0], [%1], 16;" :: "r"(s), "l"(g));
}
#define CP_COMMIT() asm volatile("cp.async.commit_group;" ::: "memory")
#define CP_WAIT1()  asm volatile("cp.async.wait_group 1;" ::: "memory")

__device__ __forceinline__ void ldsm_x4(uint32_t addr, uint32_t& r0, uint32_t& r1,
                                        uint32_t& r2, uint32_t& r3) {
    asm volatile("ldmatrix.sync.aligned.m8n8.x4.shared.b16 {%0,%1,%2,%3}, [%4];"
                 : "=r"(r0), "=r"(r1), "=r"(r2), "=r"(r3) : "r"(addr));
}
__device__ __forceinline__ void ldsm_x4t(uint32_t addr, uint32_t& r0, uint32_t& r1,
                                         uint32_t& r2, uint32_t& r3) {
    asm volatile("ldmatrix.sync.aligned.m8n8.x4.trans.shared.b16 {%0,%1,%2,%3}, [%4];"
                 : "=r"(r0), "=r"(r1), "=r"(r2), "=r"(r3) : "r"(addr));
}
__device__ __forceinline__ void mma16816(float* c, const uint32_t* a, const uint32_t* b) {
    asm volatile(
        "mma.sync.aligned.m16n8k16.row.col.f32.bf16.bf16.f32 "
        "{%0,%1,%2,%3}, {%4,%5,%6,%7}, {%8,%9}, {%0,%1,%2,%3};"
        : "+f"(c[0]), "+f"(c[1]), "+f"(c[2]), "+f"(c[3])
        : "r"(a[0]), "r"(a[1]), "r"(a[2]), "r"(a[3]), "r"(b[0]), "r"(b[1]));
}
__device__ __forceinline__ void mma16816h(float* c, const uint32_t* a, const uint32_t* b) {
    asm volatile(
        "mma.sync.aligned.m16n8k16.row.col.f32.f16.f16.f32 "
        "{%0,%1,%2,%3}, {%4,%5,%6,%7}, {%8,%9}, {%0,%1,%2,%3};"
        : "+f"(c[0]), "+f"(c[1]), "+f"(c[2]), "+f"(c[3])
        : "r"(a[0]), "r"(a[1]), "r"(a[2]), "r"(a[3]), "r"(b[0]), "r"(b[1]));
}
__device__ __forceinline__ uint32_t pack_bf16x2(float lo, float hi) {
    uint32_t r; asm("cvt.rn.bf16x2.f32 %0, %1, %2;" : "=r"(r) : "f"(hi), "f"(lo));
    return r;
}
__device__ __forceinline__ uint32_t pack_f16x2(float lo, float hi) {
    uint32_t r; asm("cvt.rn.f16x2.f32 %0, %1, %2;" : "=r"(r) : "f"(hi), "f"(lo));
    return r;
}

// ---------------- scratch (static device globals; no allocs) ----------------
__device__ float g_Q   [S*HID];
__device__ float g_K   [S*KVDIM];
__device__ float g_V   [S*KVDIM];
__device__ __half g_hHf[S*HID],   g_hLf[S*HID];    // hidden fp16 hi/lo
__device__ __half g_WqF[HID*HID];                  // Wq fp16 (hi only)
__device__ __half g_WkF[KVDIM*HID];
__device__ __half g_WvF[KVDIM*HID];
__device__ __half g_WoF[HID*HID];
__device__ __half g_aHf[S*HID],  g_aLf[S*HID];     // attn out fp16 hi/lo
__device__ bf16 g_Qh[S*HID],    g_Ql[S*HID];
__device__ bf16 g_bKh[S*KVDIM], g_bKl[S*KVDIM];
__device__ bf16 g_nKh[S*KVDIM], g_nKl[S*KVDIM];
__device__ __half g_Vh[S*KVDIM], g_Vl[S*KVDIM];    // fp16 split of V
// dual split-K partials
#define DSPLIT 4
#define DTILES (32/DSPLIT)
__device__ float g_pO[DSPLIT*NH*64*64];
__device__ float g_pm[DSPLIT*NH*64];
__device__ float g_pl[DSPLIT*NH*64];

// ---------------- input conversions (one launch) ----------------------------
// regions (float4 units): hidden 1048576 (fp16 hi/lo) | Wq 1048576 | Wk 262144
//                         | Wv 262144 | Wo 1048576 (all fp16 hi only)
__global__ __launch_bounds__(256)
void split_all_kernel(const float* __restrict__ hid, const float* __restrict__ Wq,
                      const float* __restrict__ Wk,  const float* __restrict__ Wv,
                      const float* __restrict__ Wo,
                      __half* __restrict__ hH, __half* __restrict__ hL,
                      __half* __restrict__ qF, __half* __restrict__ kF,
                      __half* __restrict__ vF, __half* __restrict__ oF)
{
    int g0 = (blockIdx.x * 256 + threadIdx.x) * 4;
    const int R0 = 1048576, R1 = R0 + 1048576, R2 = R1 + 262144, R3 = R2 + 262144;
    const int TOT = R3 + 1048576;
    if (g0 >= TOT) return;
    if (g0 < R0) {
        // hidden -> fp16 hi/lo
#pragma unroll
        for (int k = 0; k < 4; k++) {
            int i = g0 + k;
            float4 v = ((const float4*)hid)[i];
            __half h0 = __float2half_rn(v.x), h1 = __float2half_rn(v.y);
            __half h2 = __float2half_rn(v.z), h3 = __float2half_rn(v.w);
            ((__half2*)hH)[i*2+0] = __half2(h0, h1);
            ((__half2*)hH)[i*2+1] = __half2(h2, h3);
            ((__half2*)hL)[i*2+0] = __half2(__float2half_rn(v.x - __half2float(h0)),
                                            __float2half_rn(v.y - __half2float(h1)));
            ((__half2*)hL)[i*2+1] = __half2(__float2half_rn(v.z - __half2float(h2)),
                                            __float2half_rn(v.w - __half2float(h3)));
        }
        return;
    }
    const float* src; __half* dst; int rb;
    if (g0 < R1)      { src = Wq; dst = qF; rb = R0; }
    else if (g0 < R2) { src = Wk; dst = kF; rb = R1; }
    else if (g0 < R3) { src = Wv; dst = vF; rb = R2; }
    else              { src = Wo; dst = oF; rb = R3; }
#pragma unroll
    for (int k = 0; k < 4; k++) {
        int i = g0 - rb + k;
        float4 v = ((const float4*)src)[i];
        ((__half2*)dst)[i*2+0] = __half2(__float2half_rn(v.x), __float2half_rn(v.y));
        ((__half2*)dst)[i*2+1] = __half2(__float2half_rn(v.z), __float2half_rn(v.w));
    }
}

// ---------------- 2-pass fp16 GEMM core: C = (Ah+Al) @ Bh^T ----------------
#define STG2      16384
#define SM_STAGE2 (3*STG2)        // 48 KB
#define SM_TOTAL2 (2*SM_STAGE2)   // 96 KB -> 2 CTAs/SM

__device__ __forceinline__ void g_load_stage2(
    uint32_t sbuf,
    const __half* __restrict__ Ah, const __half* __restrict__ Al,
    const __half* __restrict__ Bh,
    int mBase, int nBase, int Kdim, int k0, int tid)
{
#pragma unroll
    for (int i = 0; i < 4; i++) {
        int u = i * 256 + tid;
        int r = u >> 3, c = u & 7;
        uint32_t so = (uint32_t)(r * 128 + ((c ^ (r & 7)) << 4));
        size_t eoffA = (size_t)(mBase + r) * Kdim + k0 + c * 8;
        size_t eoffB = (size_t)(nBase + r) * Kdim + k0 + c * 8;
        cp16(sbuf +          so, Ah + eoffA);
        cp16(sbuf +   STG2 + so, Al + eoffA);
        cp16(sbuf + 2*STG2 + so, Bh + eoffB);
    }
}

__device__ __forceinline__ void gemm2_body(
    const __half* __restrict__ Ah, const __half* __restrict__ Al,
    const __half* __restrict__ Bh, float* __restrict__ C,
    int Ntot, int Kdim, int mBase, int nBase, uint32_t sb)
{
    const int tid  = threadIdx.x;
    const int lane = tid & 31;
    const int wid  = tid >> 5;
    const int wm   = wid & 1;
    const int wn   = wid >> 1;

    float acc[4][4][4];
#pragma unroll
    for (int i = 0; i < 4; i++)
#pragma unroll
        for (int j = 0; j < 4; j++)
#pragma unroll
            for (int k = 0; k < 4; k++) acc[i][j][k] = 0.0f;

    const int NC = Kdim >> 6;

    g_load_stage2(sb,             Ah, Al, Bh, mBase, nBase, Kdim, 0,  tid);
    CP_COMMIT();
    g_load_stage2(sb + SM_STAGE2, Ah, Al, Bh, mBase, nBase, Kdim, 64, tid);
    CP_COMMIT();

    const int aRow = wm * 64;
    const int bRow = wn * 32;

    for (int c = 0; c < NC; c++) {
        CP_WAIT1();
        __syncthreads();
        const uint32_t sbuf = sb + (c & 1) * SM_STAGE2;
        const uint32_t sAh = sbuf, sAl = sbuf + STG2, sBh = sbuf + 2*STG2;

#pragma unroll
        for (int ks = 0; ks < 4; ks++) {
            uint32_t aH[4][4], aL[4][4], bH[4][2];
            {
                int rA = aRow + (lane & 15);
                int ccA = ks * 2 + (lane >> 4);
#pragma unroll
                for (int mf = 0; mf < 4; mf++) {
                    int r = rA + mf * 16;
                    uint32_t so = (uint32_t)(r * 128 + ((ccA ^ (r & 7)) << 4));
                    ldsm_x4(sAh + so, aH[mf][0], aH[mf][1], aH[mf][2], aH[mf][3]);
                    ldsm_x4(sAl + so, aL[mf][0], aL[mf][1], aL[mf][2], aL[mf][3]);
                }
            }
            {
                int rB0 = bRow + (lane & 7) + ((lane >> 4) << 3);
                int ccB = ks * 2 + ((lane >> 3) & 1);
#pragma unroll
                for (int nf2 = 0; nf2 < 2; nf2++) {
                    int r = rB0 + nf2 * 16;
                    uint32_t so = (uint32_t)(r * 128 + ((ccB ^ (r & 7)) << 4));
                    ldsm_x4(sBh + so, bH[nf2*2][0], bH[nf2*2][1], bH[nf2*2+1][0], bH[nf2*2+1][1]);
                }
            }
#pragma unroll
            for (int mf = 0; mf < 4; mf++)
#pragma unroll
                for (int nf = 0; nf < 4; nf++) {
                    mma16816h(acc[mf][nf], aH[mf], bH[nf]);
                    mma16816h(acc[mf][nf], aL[mf], bH[nf]);
                }
        }
        __syncthreads();
        if (c + 2 < NC)
            g_load_stage2(sb + (c & 1) * SM_STAGE2, Ah, Al, Bh,
                          mBase, nBase, Kdim, (c + 2) * 64, tid);
        CP_COMMIT();
    }

#pragma unroll
    for (int mf = 0; mf < 4; mf++) {
        int row0 = mBase + wm * 64 + mf * 16 + (lane >> 2);
#pragma unroll
        for (int nf = 0; nf < 4; nf++) {
            int col = nBase + wn * 32 + nf * 8 + (lane & 3) * 2;
            *(float2*)&C[(size_t)row0 * Ntot + col]       = make_float2(acc[mf][nf][0], acc[mf][nf][1]);
            *(float2*)&C[(size_t)(row0 + 8) * Ntot + col] = make_float2(acc[mf][nf][2], acc[mf][nf][3]);
        }
    }
}

// fused QKV projection (2-pass fp16): bx 0..15 -> Q, 16..19 -> K, 20..23 -> V
__global__ __launch_bounds__(256, 2)
void qkv_gemm2(const __half* __restrict__ Ah, const __half* __restrict__ Al,
               const __half* __restrict__ WqF, const __half* __restrict__ WkF,
               const __half* __restrict__ WvF,
               float* __restrict__ Cq, float* __restrict__ Ck, float* __restrict__ Cv)
{
    extern __shared__ char dyns[];
    uint32_t sb = smem_u32(dyns);
    int bx = blockIdx.x, mBase = blockIdx.y * 128;
    if (bx < 16)      gemm2_body(Ah, Al, WqF, Cq, HID,   HID, mBase, bx*128,      sb);
    else if (bx < 20) gemm2_body(Ah, Al, WkF, Ck, KVDIM, HID, mBase, (bx-16)*128, sb);
    else              gemm2_body(Ah, Al, WvF, Cv, KVDIM, HID, mBase, (bx-20)*128, sb);
}

__global__ __launch_bounds__(256, 2)
void wo_gemm2(const __half* __restrict__ Ah, const __half* __restrict__ Al,
              const __half* __restrict__ Bh, float* __restrict__ C)
{
    extern __shared__ char dyns[];
    uint32_t sb = smem_u32(dyns);
    gemm2_body(Ah, Al, Bh, C, HID, HID, blockIdx.y*128, blockIdx.x*128, sb);
}

// ---------------- RoPE + split (float4-vectorized, unchanged) --------------
__device__ __forceinline__ void split_w2(bf16* hp, bf16* lp, float x0, float x1) {
    bf16 h0 = __float2bfloat16(x0);
    bf16 h1 = __float2bfloat16(x1);
    *(__nv_bfloat162*)hp = __nv_bfloat162(h0, h1);
    *(__nv_bfloat162*)lp = __nv_bfloat162(__float2bfloat16(x0 - __bfloat162float(h0)),
                                          __float2bfloat16(x1 - __bfloat162float(h1)));
}

__global__ void rope_split_kernel(const float* __restrict__ Q, const float* __restrict__ K,
                                  const float* __restrict__ V,
                                  bf16* __restrict__ qh, bf16* __restrict__ ql,
                                  bf16* __restrict__ kbh, bf16* __restrict__ kbl,
                                  bf16* __restrict__ knh, bf16* __restrict__ knl,
                                  __half* __restrict__ vh, __half* __restrict__ vl)
{
    const int s = blockIdx.x;
    const int tid = threadIdx.x; // 256
    const bool narrowRow = (s >= CTX);
    const float QS = 1.4426950408889634f * 0.125f;   // log2(e)/sqrt(64)

    __shared__ float cb[32], sb[32], cn[32], sn[32];
    if (tid < 32) {
        double inv = pow(10000.0, -(double)tid / 32.0);
        double ab = (double)s * inv;
        double an = ((double)s * 0.25) * inv;
        cb[tid] = (float)cos(ab); sb[tid] = (float)sin(ab);
        cn[tid] = (float)cos(an); sn[tid] = (float)sin(an);
    }
    __syncthreads();

    {
        int p = tid;
        int h = p >> 3, d4 = (p & 7) * 4;
        size_t base = (size_t)s * HID + h * HD;
        float4 x1 = *(const float4*)&Q[base + d4];
        float4 x2 = *(const float4*)&Q[base + d4 + 32];
        const float* cc = narrowRow ? cn : cb;
        const float* ss = narrowRow ? sn : sb;
        float c0 = cc[d4], c1 = cc[d4+1], c2 = cc[d4+2], c3 = cc[d4+3];
        float s0 = ss[d4], s1 = ss[d4+1], s2 = ss[d4+2], s3 = ss[d4+3];
        split_w2(qh + base + d4,     ql + base + d4,
                 (x1.x*c0 - x2.x*s0)*QS, (x1.y*c1 - x2.y*s1)*QS);
        split_w2(qh + base + d4 + 2, ql + base + d4 + 2,
                 (x1.z*c2 - x2.z*s2)*QS, (x1.w*c3 - x2.w*s3)*QS);
        split_w2(qh + base + d4 + 32, ql + base + d4 + 32,
                 (x2.x*c0 + x1.x*s0)*QS, (x2.y*c1 + x1.y*s1)*QS);
        split_w2(qh + base + d4 + 34, ql + base + d4 + 34,
                 (x2.z*c2 + x1.z*s2)*QS, (x2.w*c3 + x1.w*s3)*QS);
    }
    if (tid < NKV * 8) {
        int p = tid;
        int h = p >> 3, d4 = (p & 7) * 4;
        size_t base = (size_t)s * KVDIM + h * HD;
        float4 x1 = *(const float4*)&K[base + d4];
        float4 x2 = *(const float4*)&K[base + d4 + 32];
        float cb0 = cb[d4], cb1 = cb[d4+1], cb2 = cb[d4+2], cb3 = cb[d4+3];
        float sb0 = sb[d4], sb1 = sb[d4+1], sb2 = sb[d4+2], sb3 = sb[d4+3];
        float cn0 = cn[d4], cn1 = cn[d4+1], cn2 = cn[d4+2], cn3 = cn[d4+3];
        float sn0 = sn[d4], sn1 = sn[d4+1], sn2 = sn[d4+2], sn3 = sn[d4+3];
        split_w2(kbh + base + d4,     kbl + base + d4,
                 x1.x*cb0 - x2.x*sb0, x1.y*cb1 - x2.y*sb1);
        split_w2(kbh + base + d4 + 2, kbl + base + d4 + 2,
                 x1.z*cb2 - x2.z*sb2, x1.w*cb3 - x2.w*sb3);
        split_w2(kbh + base + d4 + 32, kbl + base + d4 + 32,
                 x2.x*cb0 + x1.x*sb0, x2.y*cb1 + x1.y*sb1);
        split_w2(kbh + base + d4 + 34, kbl + base + d4 + 34,
                 x2.z*cb2 + x1.z*sb2, x2.w*cb3 + x1.w*sb3);
        split_w2(knh + base + d4,     knl + base + d4,
                 x1.x*cn0 - x2.x*sn0, x1.y*cn1 - x2.y*sn1);
        split_w2(knh + base + d4 + 2, knl + base + d4 + 2,
                 x1.z*cn2 - x2.z*sn2, x1.w*cn3 - x2.w*sn3);
        split_w2(knh + base + d4 + 32, knl + base + d4 + 32,
                 x2.x*cn0 + x1.x*sn0, x2.y*cn1 + x1.y*sn1);
        split_w2(knh + base + d4 + 34, knl + base + d4 + 34,
                 x2.z*cn2 + x1.z*sn2, x2.w*cn3 + x1.w*sn3);
    }
    if (tid < KVDIM / 4) {
        size_t base = (size_t)s * KVDIM + tid * 4;
        float4 v = *(const float4*)&V[base];
        __half h0 = __float2half_rn(v.x), h1 = __float2half_rn(v.y);
        __half h2 = __float2half_rn(v.z), h3 = __float2half_rn(v.w);
        *(__half2*)(vh + base)     = __half2(h0, h1);
        *(__half2*)(vh + base + 2) = __half2(h2, h3);
        *(__half2*)(vl + base)     = __half2(__float2half_rn(v.x - __half2float(h0)),
                                             __float2half_rn(v.y - __half2float(h1)));
        *(__half2*)(vl + base + 2) = __half2(__float2half_rn(v.z - __half2float(h2)),
                                             __float2half_rn(v.w - __half2float(h3)));
    }
}

// ---------------- Tensor-core flash attention (unchanged from R14) ---------
template<bool DUAL>
__device__ __forceinline__ void fa_load_stage(
    uint32_t sb, int kt, int kvh, int tid,
    const bf16* __restrict__ Kbh, const bf16* __restrict__ Kbl,
    const bf16* __restrict__ Knh, const bf16* __restrict__ Knl,
    const __half* __restrict__ Vh, const __half* __restrict__ Vl)
{
#pragma unroll
    for (int i = 0; i < 4; i++) {
        int u = i * 128 + tid;      // 0..511
        int r = u >> 3, c = u & 7;
        uint32_t so = (uint32_t)(r * 128 + ((c ^ (r & 7)) << 4));
        size_t go = (size_t)(kt * 64 + r) * KVDIM + kvh * 64 + c * 8;
        cp16(sb +         so, Kbh + go);
        cp16(sb + 8192  + so, Kbl + go);
        cp16(sb + 16384 + so, Vh + go);
        cp16(sb + 24576 + so, Vl + go);
        if (DUAL) {
            cp16(sb + 32768 + so, Knh + go);
            cp16(sb + 40960 + so, Knl + go);
        }
    }
}

__device__ __forceinline__ void fa_compute_S(
    float s[8][4], uint32_t sKh, uint32_t sKl,
    const uint32_t qfh[4][4], const uint32_t qfl[4][4], int lane)
{
#pragma unroll
    for (int kk = 0; kk < 4; kk++) {
        uint32_t kh[8][2], kl[8][2];
        int rB0 = (lane & 7) + ((lane >> 4) << 3);
        int ccB = kk * 2 + ((lane >> 3) & 1);
#pragma unroll
        for (int nb = 0; nb < 4; nb++) {
            int r = nb * 16 + rB0;
            uint32_t so = (uint32_t)(r * 128 + ((ccB ^ (r & 7)) << 4));
            ldsm_x4(sKh + so, kh[nb*2][0], kh[nb*2][1], kh[nb*2+1][0], kh[nb*2+1][1]);
            ldsm_x4(sKl + so, kl[nb*2][0], kl[nb*2][1], kl[nb*2+1][0], kl[nb*2+1][1]);
        }
#pragma unroll
        for (int nf = 0; nf < 8; nf++) {
            mma16816(s[nf], qfh[kk], kh[nf]);
            mma16816(s[nf], qfl[kk], kh[nf]);
            mma16816(s[nf], qfh[kk], kl[nf]);
        }
    }
}

__device__ __forceinline__ void fa_load_qfrag(
    uint32_t sQ, const bf16* __restrict__ Qh, const bf16* __restrict__ Ql,
    int qt, int h, int tid, int lane, int w,
    uint32_t qfh[4][4], uint32_t qfl[4][4])
{
    const bf16* gQh = Qh + (size_t)(qt * 64) * HID + h * 64;
    const bf16* gQl = Ql + (size_t)(qt * 64) * HID + h * 64;
#pragma unroll
    for (int i = 0; i < 4; i++) {
        int u = i * 128 + tid;
        int r = u >> 3, c = u & 7;
        uint32_t so = (uint32_t)(r * 128 + ((c ^ (r & 7)) << 4));
        cp16(sQ +        so, gQh + (size_t)r * HID + c * 8);
        cp16(sQ + 8192 + so, gQl + (size_t)r * HID + c * 8);
    }
    (void)qfh; (void)qfl;
}

struct FaState {
    float o[8][4];
    float m0, m1, l0, l1;
};

__device__ __forceinline__ void fa_softmax_pv(
    FaState& st, float s[8][4], uint32_t sb, int lane)
{
    float mr0 = -1e30f, mr1 = -1e30f;
#pragma unroll
    for (int nf = 0; nf < 8; nf++) {
        mr0 = fmaxf(mr0, fmaxf(s[nf][0], s[nf][1]));
        mr1 = fmaxf(mr1, fmaxf(s[nf][2], s[nf][3]));
    }
    mr0 = fmaxf(mr0, __shfl_xor_sync(0xffffffffu, mr0, 1));
    mr0 = fmaxf(mr0, __shfl_xor_sync(0xffffffffu, mr0, 2));
    mr1 = fmaxf(mr1, __shfl_xor_sync(0xffffffffu, mr1, 1));
    mr1 = fmaxf(mr1, __shfl_xor_sync(0xffffffffu, mr1, 2));

    float mn0 = fmaxf(st.m0, mr0), mn1 = fmaxf(st.m1, mr1);
    float sc0 = exp2f(st.m0 - mn0), sc1 = exp2f(st.m1 - mn1);
    st.m0 = mn0; st.m1 = mn1;
    st.l0 *= sc0; st.l1 *= sc1;
#pragma unroll
    for (int nf = 0; nf < 8; nf++) {
        st.o[nf][0] *= sc0; st.o[nf][1] *= sc0;
        st.o[nf][2] *= sc1; st.o[nf][3] *= sc1;
    }

    uint32_t pF[4][4];
    float sum0 = 0.0f, sum1 = 0.0f;
#pragma unroll
    for (int nf = 0; nf < 8; nf++) {
        float p0 = exp2f(s[nf][0] - st.m0), p1 = exp2f(s[nf][1] - st.m0);
        float p2 = exp2f(s[nf][2] - st.m1), p3 = exp2f(s[nf][3] - st.m1);
        sum0 += p0 + p1; sum1 += p2 + p3;
        int kk = nf >> 1;
        int off = (nf & 1) * 2;
        pF[kk][off + 0] = pack_f16x2(p0, p1);
        pF[kk][off + 1] = pack_f16x2(p2, p3);
    }
    sum0 += __shfl_xor_sync(0xffffffffu, sum0, 1);
    sum0 += __shfl_xor_sync(0xffffffffu, sum0, 2);
    sum1 += __shfl_xor_sync(0xffffffffu, sum1, 1);
    sum1 += __shfl_xor_sync(0xffffffffu, sum1, 2);
    st.l0 += sum0; st.l1 += sum1;

    const uint32_t sVh = sb + 16384, sVl = sb + 24576;
#pragma unroll
    for (int kk = 0; kk < 4; kk++) {
        uint32_t vh[8][2], vl[8][2];
        int key0 = kk * 16 + (lane & 7) + ((lane >> 3) & 1) * 8;
#pragma unroll
        for (int nb = 0; nb < 4; nb++) {
            int chunk = nb * 2 + (lane >> 4);
            uint32_t so = (uint32_t)(key0 * 128 + ((chunk ^ (key0 & 7)) << 4));
            ldsm_x4t(sVh + so, vh[nb*2][0], vh[nb*2][1], vh[nb*2+1][0], vh[nb*2+1][1]);
            ldsm_x4t(sVl + so, vl[nb*2][0], vl[nb*2][1], vl[nb*2+1][0], vl[nb*2+1][1]);
        }
#pragma unroll
        for (int nf = 0; nf < 8; nf++) {
            mma16816h(st.o[nf], pF[kk], vh[nf]);
            mma16816h(st.o[nf], pF[kk], vl[nf]);
        }
    }
}

__global__ __launch_bounds__(128, 2)
void flash_all(const bf16* __restrict__ Qh, const bf16* __restrict__ Ql,
               const bf16* __restrict__ Kbh, const bf16* __restrict__ Kbl,
               const bf16* __restrict__ Knh, const bf16* __restrict__ Knl,
               const __half* __restrict__ Vh,  const __half* __restrict__ Vl,
               __half* __restrict__ aHf, __half* __restrict__ aLf,
               float* __restrict__ pO, float* __restrict__ pm,
               float* __restrict__ pl)
{
    extern __shared__ char dyn[];
    const uint32_t sQ = smem_u32(dyn);
    const int tid = threadIdx.x, lane = tid & 31, w = tid >> 5;
    const int h = blockIdx.y, kvh = h >> 2;
    const bool isDual = (blockIdx.x < DSPLIT);

    FaState st;
#pragma unroll
    for (int nf = 0; nf < 8; nf++)
#pragma unroll
        for (int j = 0; j < 4; j++) st.o[nf][j] = 0.0f;
    st.m0 = -1e30f; st.m1 = -1e30f; st.l0 = 0.0f; st.l1 = 0.0f;

    if (isDual) {
        constexpr int STAGE = 49152;
        const int split = blockIdx.x;
        const int qt = S/64 - 1;
        const int kt0 = split * DTILES, kt1 = kt0 + DTILES;

        fa_load_qfrag(sQ, Qh, Ql, qt, h, tid, lane, w, nullptr, nullptr);
        fa_load_stage<true>(sQ + 16384, kt0, kvh, tid, Kbh, Kbl, Knh, Knl, Vh, Vl);
        CP_COMMIT();
        fa_load_stage<true>(sQ + 16384 + STAGE, kt0 + 1, kvh, tid, Kbh, Kbl, Knh, Knl, Vh, Vl);
        CP_COMMIT();
        CP_WAIT1();
        __syncthreads();

        uint32_t qfh[4][4], qfl[4][4];
        {
            int rA = w * 16 + (lane & 15);
#pragma unroll
            for (int kk = 0; kk < 4; kk++) {
                int cc = kk * 2 + (lane >> 4);
                uint32_t so = (uint32_t)(rA * 128 + ((cc ^ (rA & 7)) << 4));
                ldsm_x4(sQ + so,        qfh[kk][0], qfh[kk][1], qfh[kk][2], qfh[kk][3]);
                ldsm_x4(sQ + 8192 + so, qfl[kk][0], qfl[kk][1], qfl[kk][2], qfl[kk][3]);
            }
        }

        const int rl0 = w * 16 + (lane >> 2);
        const int rl1 = rl0 + 8;
        const int rg0 = qt * 64 + rl0, rg1 = qt * 64 + rl1;

        for (int kt = kt0; kt < kt1; kt++) {
            if (kt > kt0) { CP_WAIT1(); __syncthreads(); }
            const uint32_t sb = sQ + 16384 + (kt & 1) * STAGE;

            float s[8][4];
#pragma unroll
            for (int nf = 0; nf < 8; nf++)
#pragma unroll
                for (int j = 0; j < 4; j++) s[nf][j] = 0.0f;
            fa_compute_S(s, sb, sb + 8192, qfh, qfl, lane);

            {
                float sn[8][4];
#pragma unroll
                for (int nf = 0; nf < 8; nf++)
#pragma unroll
                    for (int j = 0; j < 4; j++) sn[nf][j] = 0.0f;
                fa_compute_S(sn, sb + 32768, sb + 40960, qfh, qfl, lane);
                if (rg0 >= CTX) {
#pragma unroll
                    for (int nf = 0; nf < 8; nf++) { s[nf][0] = sn[nf][0]; s[nf][1] = sn[nf][1]; }
                }
                if (rg1 >= CTX) {
#pragma unroll
                    for (int nf = 0; nf < 8; nf++) { s[nf][2] = sn[nf][2]; s[nf][3] = sn[nf][3]; }
                }
            }

            if (kt == qt) {
#pragma unroll
                for (int nf = 0; nf < 8; nf++) {
                    int c0 = kt * 64 + nf * 8 + (lane & 3) * 2;
                    if (c0     > rg0) s[nf][0] = -1e30f;
                    if (c0 + 1 > rg0) s[nf][1] = -1e30f;
                    if (c0     > rg1) s[nf][2] = -1e30f;
                    if (c0 + 1 > rg1) s[nf][3] = -1e30f;
                }
            }

            fa_softmax_pv(st, s, sb, lane);

            __syncthreads();
            if (kt + 2 < kt1)
                fa_load_stage<true>(sQ + 16384 + (kt & 1) * STAGE, kt + 2, kvh, tid,
                                    Kbh, Kbl, Knh, Knl, Vh, Vl);
            CP_COMMIT();
        }

        const int hb = (split * NH + h) * 64;
#pragma unroll
        for (int nf = 0; nf < 8; nf++) {
            int col = nf * 8 + (lane & 3) * 2;
            *(float2*)&pO[(size_t)(hb + rl0) * 64 + col] = make_float2(st.o[nf][0], st.o[nf][1]);
            *(float2*)&pO[(size_t)(hb + rl1) * 64 + col] = make_float2(st.o[nf][2], st.o[nf][3]);
        }
        if ((lane & 3) == 0) {
            pm[hb + rl0] = st.m0; pl[hb + rl0] = st.l0;
            pm[hb + rl1] = st.m1; pl[hb + rl1] = st.l1;
        }
        return;
    }

    {
        constexpr int STAGE = 32768;
        const int qt = (S/64 - 2) - ((int)blockIdx.x - DSPLIT);   // heavy first

        fa_load_qfrag(sQ, Qh, Ql, qt, h, tid, lane, w, nullptr, nullptr);
        fa_load_stage<false>(sQ + 16384, 0, kvh, tid, Kbh, Kbl, nullptr, nullptr, Vh, Vl);
        CP_COMMIT();
        if (qt >= 1)
            fa_load_stage<false>(sQ + 16384 + STAGE, 1, kvh, tid, Kbh, Kbl, nullptr, nullptr, Vh, Vl);
        CP_COMMIT();
        CP_WAIT1();
        __syncthreads();

        uint32_t qfh[4][4], qfl[4][4];
        {
            int rA = w * 16 + (lane & 15);
#pragma unroll
            for (int kk = 0; kk < 4; kk++) {
                int cc = kk * 2 + (lane >> 4);
                uint32_t so = (uint32_t)(rA * 128 + ((cc ^ (rA & 7)) << 4));
                ldsm_x4(sQ + so,        qfh[kk][0], qfh[kk][1], qfh[kk][2], qfh[kk][3]);
                ldsm_x4(sQ + 8192 + so, qfl[kk][0], qfl[kk][1], qfl[kk][2], qfl[kk][3]);
            }
        }

        const int rg0 = qt * 64 + w * 16 + (lane >> 2);
        const int rg1 = rg0 + 8;

        for (int kt = 0; kt <= qt; kt++) {
            if (kt) { CP_WAIT1(); __syncthreads(); }
            const uint32_t sb = sQ + 16384 + (kt & 1) * STAGE;

            float s[8][4];
#pragma unroll
            for (int nf = 0; nf < 8; nf++)
#pragma unroll
                for (int j = 0; j < 4; j++) s[nf][j] = 0.0f;
            fa_compute_S(s, sb, sb + 8192, qfh, qfl, lane);

            if (kt == qt) {
#pragma unroll
                for (int nf = 0; nf < 8; nf++) {
                    int c0 = kt * 64 + nf * 8 + (lane & 3) * 2;
                    if (c0     > rg0) s[nf][0] = -1e30f;
                    if (c0 + 1 > rg0) s[nf][1] = -1e30f;
                    if (c0     > rg1) s[nf][2] = -1e30f;
                    if (c0 + 1 > rg1) s[nf][3] = -1e30f;
                }
            }

            fa_softmax_pv(st, s, sb, lane);

            __syncthreads();
            if (kt + 2 <= qt)
                fa_load_stage<false>(sQ + 16384 + (kt & 1) * STAGE, kt + 2, kvh, tid,
                                     Kbh, Kbl, nullptr, nullptr, Vh, Vl);
            CP_COMMIT();
        }

        float inv0 = 1.0f / st.l0, inv1 = 1.0f / st.l1;
#pragma unroll
        for (int nf = 0; nf < 8; nf++) {
            int col = h * 64 + nf * 8 + (lane & 3) * 2;
            float x0 = st.o[nf][0]*inv0, x1 = st.o[nf][1]*inv0;
            float x2 = st.o[nf][2]*inv1, x3 = st.o[nf][3]*inv1;
            float r0 = __half2float(__float2half_rn(x0));
            float r1 = __half2float(__float2half_rn(x1));
            float r2 = __half2float(__float2half_rn(x2));
            float r3 = __half2float(__float2half_rn(x3));
            *(uint32_t*)&aHf[(size_t)rg0 * HID + col] = pack_f16x2(x0, x1);
            *(uint32_t*)&aLf[(size_t)rg0 * HID + col] = pack_f16x2(x0 - r0, x1 - r1);
            *(uint32_t*)&aHf[(size_t)rg1 * HID + col] = pack_f16x2(x2, x3);
            *(uint32_t*)&aLf[(size_t)rg1 * HID + col] = pack_f16x2(x2 - r2, x3 - r3);
        }
    }
}

// ---- merge dual partials -> fp16 hi/lo attn output (exact reassociation) --
__global__ __launch_bounds__(256)
void dual_merge(const float* __restrict__ pO, const float* __restrict__ pm,
                const float* __restrict__ pl,
                __half* __restrict__ aHf, __half* __restrict__ aLf)
{
    int idx = blockIdx.x * 256 + threadIdx.x;     // 64*32*32 = 65536 dim-pairs
    if (idx >= 64 * NH * 32) return;
    int dp = idx & 31;
    int h  = (idx >> 5) & 31;
    int rl = idx >> 10;

    float m[DSPLIT], l[DSPLIT];
#pragma unroll
    for (int i = 0; i < DSPLIT; i++) {
        m[i] = pm[(i * NH + h) * 64 + rl];
        l[i] = pl[(i * NH + h) * 64 + rl];
    }
    float M = m[0];
#pragma unroll
    for (int i = 1; i < DSPLIT; i++) M = fmaxf(M, m[i]);
    float wgt[DSPLIT], L = 0.0f;
#pragma unroll
    for (int i = 0; i < DSPLIT; i++) { wgt[i] = exp2f(m[i] - M); L += l[i] * wgt[i]; }

    float o0 = 0.0f, o1 = 0.0f;
#pragma unroll
    for (int i = 0; i < DSPLIT; i++) {
        float2 v = *(const float2*)&pO[(size_t)((i * NH + h) * 64 + rl) * 64 + dp * 2];
        o0 += v.x * wgt[i];
        o1 += v.y * wgt[i];
    }
    float inv = 1.0f / L;
    o0 *= inv; o1 *= inv;

    size_t off = (size_t)((S - 64) + rl) * HID + h * 64 + dp * 2;
    float r0 = __half2float(__float2half_rn(o0));
    float r1 = __half2float(__float2half_rn(o1));
    *(uint32_t*)&aHf[off] = pack_f16x2(o0, o1);
    *(uint32_t*)&aLf[off] = pack_f16x2(o0 - r0, o1 - r1);
}

// ---------------- launch ----------------
extern "C" void kernel_launch(void* const* d_in, const int* in_sizes, int n_in,
                              void* d_out, int out_size)
{
    const float* hidden = (const float*)d_in[0];
    const float* Wq = (const float*)d_in[3];
    const float* Wk = (const float*)d_in[4];
    const float* Wv = (const float*)d_in[5];
    const float* Wo = (const float*)d_in[6];
    float* out = (float*)d_out;

    float *qB, *kB, *vB;
    cudaGetSymbolAddress((void**)&qB,  g_Q);
    cudaGetSymbolAddress((void**)&kB,  g_K);
    cudaGetSymbolAddress((void**)&vB,  g_V);

    __half *hHf,*hLf,*WqF,*WkF,*WvF,*WoF,*aHf,*aLf;
    cudaGetSymbolAddress((void**)&hHf, g_hHf); cudaGetSymbolAddress((void**)&hLf, g_hLf);
    cudaGetSymbolAddress((void**)&WqF, g_WqF); cudaGetSymbolAddress((void**)&WkF, g_WkF);
    cudaGetSymbolAddress((void**)&WvF, g_WvF); cudaGetSymbolAddress((void**)&WoF, g_WoF);
    cudaGetSymbolAddress((void**)&aHf, g_aHf); cudaGetSymbolAddress((void**)&aLf, g_aLf);

    bf16 *Qh,*Ql,*bKh,*bKl,*nKh,*nKl;
    __half *Vh,*Vl;
    cudaGetSymbolAddress((void**)&Qh,  g_Qh);  cudaGetSymbolAddress((void**)&Ql,  g_Ql);
    cudaGetSymbolAddress((void**)&bKh, g_bKh); cudaGetSymbolAddress((void**)&bKl, g_bKl);
    cudaGetSymbolAddress((void**)&nKh, g_nKh); cudaGetSymbolAddress((void**)&nKl, g_nKl);
    cudaGetSymbolAddress((void**)&Vh,  g_Vh);  cudaGetSymbolAddress((void**)&Vl,  g_Vl);

    float *pO, *pm, *pl;
    cudaGetSymbolAddress((void**)&pO, g_pO);
    cudaGetSymbolAddress((void**)&pm, g_pm);
    cudaGetSymbolAddress((void**)&pl, g_pl);

    cudaFuncSetAttribute(qkv_gemm2, cudaFuncAttributeMaxDynamicSharedMemorySize, SM_TOTAL2);
    cudaFuncSetAttribute(wo_gemm2,  cudaFuncAttributeMaxDynamicSharedMemorySize, SM_TOTAL2);
    const int FA_SMEM_D = 16384 + 2*49152;   // 114688 (covers both flash paths)
    cudaFuncSetAttribute(flash_all, cudaFuncAttributeMaxDynamicSharedMemorySize, FA_SMEM_D);

    // all 5 input conversions in one launch (hidden fp16 hi/lo, weights fp16 hi)
    const int TOT4 = 1048576*3 + 262144*2;   // float4 units
    split_all_kernel<<<(TOT4/4 + 255)/256, 256>>>(hidden, Wq, Wk, Wv, Wo,
                                                  hHf, hLf, WqF, WkF, WvF, WoF);

    // QKV projections: 2-pass fp16, 2 CTAs/SM
    qkv_gemm2<<<dim3(24, 16), 256, SM_TOTAL2>>>(hHf, hLf, WqF, WkF, WvF, qB, kB, vB);

    rope_split_kernel<<<S, 256>>>(qB, kB, vB, Qh, Ql, bKh, bKl, nKh, nKl, Vh, Vl);

    // single flash launch: 4 dual-split CTAs first, then 31 main tiles
    flash_all<<<dim3(DSPLIT + S/64 - 1, NH), 128, FA_SMEM_D>>>(
        Qh, Ql, bKh, bKl, nKh, nKl, Vh, Vl, aHf, aLf, pO, pm, pl);
    dual_merge<<<(64*NH*32 + 255)/256, 256>>>(pO, pm, pl, aHf, aLf);

    // 2-pass fp16 Wo GEMM into d_out
    wo_gemm2<<<dim3(16, 16), 256, SM_TOTAL2>>>(aHf, aLf, WoF, out);
}